// round 6
// baseline (speedup 1.0000x reference)
#include <cuda_runtime.h>
#include <math.h>
#include <stdint.h>

#define TNUM 4096
#define CH 128
#define NE 16
#define KB 32
#define VSZ 50257
#define NTILES 393   // ceil(50257/128)

// scratch (static device arrays — no allocation)
__device__ float g_x [TNUM*CH];
__device__ float g_q [TNUM*CH];
__device__ float g_rw[TNUM*NE];
__device__ float g_ao[TNUM*CH];
__device__ float g_xf[TNUM*CH];

// ---------------- block reduce over 128 threads ----------------
__device__ __forceinline__ float blockReduce128(float v, float* sred, int tid) {
    #pragma unroll
    for (int o = 16; o; o >>= 1) v += __shfl_down_sync(0xffffffffu, v, o);
    if ((tid & 31) == 0) sred[tid >> 5] = v;
    __syncthreads();
    return sred[0] + sred[1] + sred[2] + sred[3];
}

// ==================== K1: embed + LN1 + routing + q ====================
__global__ __launch_bounds__(128) void k1(const int* __restrict__ ids,
        const float* __restrict__ emb, const float* __restrict__ router,
        const float* __restrict__ Wq, const float* __restrict__ g1,
        const float* __restrict__ b1, float* __restrict__ gate_out)
{
    int t = blockIdx.x, tid = threadIdx.x;
    __shared__ float sx[CH];
    __shared__ float sred[4];
    __shared__ float sgl[NE];

    int id = ids[t];
    float xv = __ldg(&emb[(long long)id * CH + tid]);
    g_x[t*CH + tid] = xv;

    float mu = blockReduce128(xv, sred, tid) * (1.f/CH);
    __syncthreads();
    float d  = xv - mu;
    float var = blockReduce128(d*d, sred, tid) * (1.f/CH);
    float xln = d * rsqrtf(var + 1e-5f) * g1[tid] + b1[tid];
    sx[tid] = xln;
    __syncthreads();

    int e = tid >> 3, l = tid & 7;
    float gl = 0.f;
    #pragma unroll 4
    for (int k = l; k < CH; k += 8) gl += sx[k] * __ldg(&router[e*CH + k]);
    #pragma unroll
    for (int o = 4; o; o >>= 1) gl += __shfl_xor_sync(0xffffffffu, gl, o, 8);
    if (l == 0) sgl[e] = gl;
    __syncthreads();

    if (tid < NE) gate_out[(long long)t*NE + tid] = sgl[tid];

    float mx = -1e30f;
    #pragma unroll
    for (int i = 0; i < NE; i++) mx = fmaxf(mx, sgl[i]);
    float ss = 0.f;
    #pragma unroll
    for (int i = 0; i < NE; i++) ss += __expf(sgl[i] - mx);
    if (tid < NE) g_rw[t*NE + tid] = __expf(sgl[tid] - mx) / ss;

    float acc = 0.f;
    const float4* wr = (const float4*)(Wq + tid*CH);
    const float4* xr = (const float4*)sx;
    #pragma unroll 8
    for (int k = 0; k < 32; k++) {
        float4 w = __ldg(&wr[k]);
        float4 x4 = xr[k];
        acc += w.x*x4.x + w.y*x4.y + w.z*x4.z + w.w*x4.w;
    }
    g_q[t*CH + tid] = acc;
}

// ==================== K2: expert attention ====================
#define TB 32
#define QSTR 132
__global__ __launch_bounds__(256) void k2(const float* __restrict__ kexp,
        const float* __restrict__ vexp, const float* __restrict__ skv,
        const float* __restrict__ svv, const float* __restrict__ kvg)
{
    __shared__ float sQ[TB*QSTR];
    __shared__ float sT[KB*QSTR];
    __shared__ float sS[TB][KB+1];
    __shared__ float sRW[TB*NE];

    int t0 = blockIdx.x * TB;
    int tid = threadIdx.x;
    float g = 1.f / (1.f + __expf(-kvg[0]));

    for (int i = tid; i < TB*CH; i += 256) {
        int tt = i >> 7, cc = i & 127;
        sQ[tt*QSTR + cc] = g_q[(t0+tt)*CH + cc];
    }
    for (int i = tid; i < TB*NE; i += 256) sRW[i] = g_rw[t0*NE + i];

    int t = tid >> 3, kg = tid & 7;
    float sdyn[4] = {0,0,0,0}, sstat[4];

    for (int e = 0; e < NE; e++) {
        __syncthreads();
        for (int i = tid; i < KB*CH; i += 256) {
            int kk = i >> 7, cc = i & 127;
            sT[kk*QSTR + cc] = __ldg(&kexp[e*KB*CH + i]);
        }
        __syncthreads();
        float rwv = sRW[t*NE + e];
        float dj[4] = {0,0,0,0};
        const float4* qp = (const float4*)(sQ + t*QSTR);
        #pragma unroll 4
        for (int c4 = 0; c4 < 32; c4++) {
            float4 qv = qp[c4];
            #pragma unroll
            for (int j = 0; j < 4; j++) {
                int k = kg + 8*j;
                float4 kv = *(const float4*)(sT + k*QSTR + 4*c4);
                dj[j] += qv.x*kv.x + qv.y*kv.y + qv.z*kv.z + qv.w*kv.w;
            }
        }
        #pragma unroll
        for (int j = 0; j < 4; j++) sdyn[j] += rwv * dj[j];
    }
    __syncthreads();
    for (int i = tid; i < KB*CH; i += 256) {
        int kk = i >> 7, cc = i & 127;
        sT[kk*QSTR + cc] = __ldg(&skv[i]);
    }
    __syncthreads();
    {
        float dj[4] = {0,0,0,0};
        const float4* qp = (const float4*)(sQ + t*QSTR);
        #pragma unroll 4
        for (int c4 = 0; c4 < 32; c4++) {
            float4 qv = qp[c4];
            #pragma unroll
            for (int j = 0; j < 4; j++) {
                int k = kg + 8*j;
                float4 kv = *(const float4*)(sT + k*QSTR + 4*c4);
                dj[j] += qv.x*kv.x + qv.y*kv.y + qv.z*kv.z + qv.w*kv.w;
            }
        }
        #pragma unroll
        for (int j = 0; j < 4; j++) sstat[j] = dj[j];
    }
    const float scale = 0.08838834764831845f;
    #pragma unroll
    for (int j = 0; j < 4; j++)
        sS[t][kg + 8*j] = (g*sdyn[j] + (1.f-g)*sstat[j]) * scale;
    __syncthreads();

    if (tid < TB) {
        float mx = -1e30f;
        #pragma unroll
        for (int k = 0; k < KB; k++) mx = fmaxf(mx, sS[tid][k]);
        float ssum = 0.f;
        #pragma unroll
        for (int k = 0; k < KB; k++) { float ev = __expf(sS[tid][k] - mx); sS[tid][k] = ev; ssum += ev; }
        float inv = 1.f / ssum;
        #pragma unroll
        for (int k = 0; k < KB; k++) sS[tid][k] *= inv;
    }

    float acc[16];
    #pragma unroll
    for (int i = 0; i < 16; i++) acc[i] = 0.f;

    for (int e = 0; e < NE; e++) {
        __syncthreads();
        for (int i = tid; i < KB*CH; i += 256) {
            int kk = i >> 7, cc = i & 127;
            sT[kk*QSTR + cc] = __ldg(&vexp[e*KB*CH + i]);
        }
        __syncthreads();
        float we = g * sRW[t*NE + e];
        #pragma unroll 4
        for (int k = 0; k < KB; k++) {
            float w = we * sS[t][k];
            #pragma unroll
            for (int j = 0; j < 4; j++) {
                float4 vv = *(const float4*)(sT + k*QSTR + 4*(kg + 8*j));
                acc[j*4+0] += w*vv.x; acc[j*4+1] += w*vv.y;
                acc[j*4+2] += w*vv.z; acc[j*4+3] += w*vv.w;
            }
        }
    }
    __syncthreads();
    for (int i = tid; i < KB*CH; i += 256) {
        int kk = i >> 7, cc = i & 127;
        sT[kk*QSTR + cc] = __ldg(&svv[i]);
    }
    __syncthreads();
    {
        float we = 1.f - g;
        #pragma unroll 4
        for (int k = 0; k < KB; k++) {
            float w = we * sS[t][k];
            #pragma unroll
            for (int j = 0; j < 4; j++) {
                float4 vv = *(const float4*)(sT + k*QSTR + 4*(kg + 8*j));
                acc[j*4+0] += w*vv.x; acc[j*4+1] += w*vv.y;
                acc[j*4+2] += w*vv.z; acc[j*4+3] += w*vv.w;
            }
        }
    }
    #pragma unroll
    for (int j = 0; j < 4; j++) {
        float4 o;
        o.x = acc[j*4+0]; o.y = acc[j*4+1]; o.z = acc[j*4+2]; o.w = acc[j*4+3];
        *(float4*)&g_ao[(t0+t)*CH + 4*(kg + 8*j)] = o;
    }
}

// ==================== K3: Wo + residual + LN2 + MLP + residual ====================
__global__ __launch_bounds__(128) void k3(const float* __restrict__ Wo,
        const float* __restrict__ Wm, const float* __restrict__ bm,
        const float* __restrict__ g2, const float* __restrict__ b2)
{
    int t = blockIdx.x, tid = threadIdx.x;
    __shared__ float sa[CH];
    __shared__ float sred[4];

    sa[tid] = g_ao[t*CH + tid];
    __syncthreads();

    float o = 0.f;
    {
        const float4* wr = (const float4*)(Wo + tid*CH);
        const float4* ar = (const float4*)sa;
        #pragma unroll 8
        for (int k = 0; k < 32; k++) {
            float4 w = __ldg(&wr[k]);
            float4 a4 = ar[k];
            o += w.x*a4.x + w.y*a4.y + w.z*a4.z + w.w*a4.w;
        }
    }
    float x2 = g_x[t*CH + tid] + o;

    __syncthreads();
    float mu = blockReduce128(x2, sred, tid) * (1.f/CH);
    __syncthreads();
    float d = x2 - mu;
    float var = blockReduce128(d*d, sred, tid) * (1.f/CH);
    float xln = d * rsqrtf(var + 1e-5f) * g2[tid] + b2[tid];
    __syncthreads();
    sa[tid] = xln;
    __syncthreads();

    float m = __ldg(&bm[tid]);
    {
        const float4* wr = (const float4*)(Wm + tid*CH);
        const float4* ar = (const float4*)sa;
        #pragma unroll 8
        for (int k = 0; k < 32; k++) {
            float4 w = __ldg(&wr[k]);
            float4 a4 = ar[k];
            m += w.x*a4.x + w.y*a4.y + w.z*a4.z + w.w*a4.w;
        }
    }
    g_xf[t*CH + tid] = x2 + m;
}

// ==================== K4: LM head GEMM ====================
// D[4096,50257] = Xf[4096,128] @ Wlm[50257,128]^T  (both K-major)

#if defined(__CUDA_ARCH__) && (__CUDA_ARCH__ == 1030) && defined(__CUDA_ARCH_FEAT_SM103_ALL)
#define HAS_TCGEN05 1
#else
#define HAS_TCGEN05 0
#endif

__device__ __forceinline__ uint32_t s2u(const void* p) {
    uint32_t a;
    asm("{ .reg .u64 t; cvta.to.shared.u64 t, %1; cvt.u32.u64 %0, t; }" : "=r"(a) : "l"(p));
    return a;
}

#define SMA 0
#define SMB0 65536
#define SMB1 131072
#define SCR  196608
#define K4_SMEM 229376   // 64K A + 2x64K B + 32K transpose scratch

#if HAS_TCGEN05

__device__ __forceinline__ uint32_t f2tf(float f) {
    uint32_t r; asm("cvt.rna.tf32.f32 %0, %1;" : "=r"(r) : "f"(f)); return r;
}
__device__ __forceinline__ bool elect1() {
    uint32_t p;
    asm volatile("{ .reg .pred p; elect.sync _|p, 0xFFFFFFFF; selp.b32 %0, 1, 0, p; }" : "=r"(p));
    return p != 0;
}
__device__ __forceinline__ void mbar_init(uint32_t a, uint32_t cnt) {
    asm volatile("mbarrier.init.shared.b64 [%0], %1;" :: "r"(a), "r"(cnt) : "memory");
}
__device__ __forceinline__ void mbar_wait(uint32_t a, uint32_t ph) {
    asm volatile(
        "{\n\t.reg .pred P;\n"
        "W_%=:\n\t"
        "mbarrier.try_wait.parity.acquire.cta.shared::cta.b64 P, [%0], %1, 0x989680;\n\t"
        "@P bra D_%=;\n\t"
        "bra W_%=;\n"
        "D_%=:\n\t}"
        :: "r"(a), "r"(ph) : "memory");
}
__device__ __forceinline__ void sts128(uint32_t a, uint32_t r0, uint32_t r1, uint32_t r2, uint32_t r3) {
    asm volatile("st.shared.v4.b32 [%0], {%1, %2, %3, %4};" :: "r"(a), "r"(r0), "r"(r1), "r"(r2), "r"(r3) : "memory");
}
__device__ __forceinline__ void mma_tf32(uint32_t d, uint64_t ad, uint64_t bd, uint32_t idesc, bool accum) {
    uint32_t en = accum ? 1u : 0u;
    asm volatile(
        "{\n\t.reg .pred p;\n\t"
        "setp.ne.u32 p, %5, 0;\n\t"
        "tcgen05.mma.cta_group::1.kind::tf32 [%0], %1, %2, %3, {%4, %4, %4, %4}, p;\n\t}"
        :: "r"(d), "l"(ad), "l"(bd), "r"(idesc), "r"(0u), "r"(en) : "memory");
}
__device__ __forceinline__ void mma_commit(uint32_t mbar) {
    asm volatile("tcgen05.commit.cta_group::1.mbarrier::arrive::one.shared::cluster.b64 [%0];" :: "r"(mbar) : "memory");
}
// SW128 K-major smem descriptor: layout=2, version=1, SBO=64, LBO=1
__device__ __forceinline__ uint64_t mk_desc(uint32_t addr) {
    const uint64_t base = (uint64_t(2) << 61) | (uint64_t(1) << 46) | (uint64_t(64) << 32) | (uint64_t(1) << 16);
    return base | ((uint64_t)(addr >> 4) & 0x3FFF);
}

#define LDTM32(r, a) \
    asm volatile( \
        "tcgen05.ld.sync.aligned.32x32b.x32.b32 " \
        "{%0, %1, %2, %3, %4, %5, %6, %7, " \
        " %8, %9, %10, %11, %12, %13, %14, %15, " \
        " %16, %17, %18, %19, %20, %21, %22, %23, " \
        " %24, %25, %26, %27, %28, %29, %30, %31}, [%32];" \
        : "=r"((r)[0]),  "=r"((r)[1]),  "=r"((r)[2]),  "=r"((r)[3]), \
          "=r"((r)[4]),  "=r"((r)[5]),  "=r"((r)[6]),  "=r"((r)[7]), \
          "=r"((r)[8]),  "=r"((r)[9]),  "=r"((r)[10]), "=r"((r)[11]), \
          "=r"((r)[12]), "=r"((r)[13]), "=r"((r)[14]), "=r"((r)[15]), \
          "=r"((r)[16]), "=r"((r)[17]), "=r"((r)[18]), "=r"((r)[19]), \
          "=r"((r)[20]), "=r"((r)[21]), "=r"((r)[22]), "=r"((r)[23]), \
          "=r"((r)[24]), "=r"((r)[25]), "=r"((r)[26]), "=r"((r)[27]), \
          "=r"((r)[28]), "=r"((r)[29]), "=r"((r)[30]), "=r"((r)[31]) \
        : "r"(a))

// idesc: dtype=F32(1<<4), atype=TF32(2<<7), btype=TF32(2<<10), N=128(16<<17), M=128(8<<24)
#define K4_IDESC ((1u<<4) | (2u<<7) | (2u<<10) | (16u<<17) | (8u<<24))

__device__ __forceinline__ void k4_load_tile(const float* __restrict__ src, uint32_t sdst,
                                             int row0, int rowmax, int tid)
{
    // 128 rows x 128 cols f32 -> 4 K-chunks of [128 x 32] SW128-swizzled tf32
    #pragma unroll
    for (int it = 0; it < 16; it++) {
        int f = tid + it * 256;          // float4 index, 0..4095
        int r = f >> 5, q = f & 31;
        int kc = q >> 3, c4 = q & 7;
        float4 v = make_float4(0.f, 0.f, 0.f, 0.f);
        if (row0 + r < rowmax)
            v = *(const float4*)&src[(size_t)(row0 + r) * CH + q * 4];
        uint32_t off = (uint32_t)(kc * 16384 + r * 128 + c4 * 16);
        off = off ^ ((off >> 3) & 0x70);
        sts128(sdst + off, f2tf(v.x), f2tf(v.y), f2tf(v.z), f2tf(v.w));
    }
}

// Epilogue v3: two 64-col rounds through a dedicated 32KB float4-swizzled
// scratch. Both smem phases are vectorized (.128) and conflict-free at the
// 4-phase floor; STGs are 256B-contiguous per half-warp.
__device__ __forceinline__ void k4_epilogue(uint32_t dt, float* __restrict__ scr,
                                            int m0, int n0,
                                            float* __restrict__ out, int tid)
{
    int wid = tid >> 5, lid = tid & 31;
    int row  = (wid & 3) * 32 + lid;   // TMEM lane -> D row
    int half = wid >> 2;               // 32-col half within each 64-col round
    uint32_t scr_u = s2u(scr);

    #pragma unroll
    for (int rr = 0; rr < 2; rr++) {
        uint32_t r[32];
        LDTM32(r, dt + rr * 64 + half * 32);
        asm volatile("tcgen05.wait::ld.sync.aligned;" ::: "memory");
        asm volatile("tcgen05.fence::before_thread_sync;" ::: "memory");
        #pragma unroll
        for (int gq = 0; gq < 8; gq++) {
            int cgl = half * 8 + gq;             // col-group 0..15 within round
            int sg  = cgl ^ (row & 15);
            sts128(scr_u + (uint32_t)(row * 64 + sg * 4) * 4,
                   r[4*gq], r[4*gq+1], r[4*gq+2], r[4*gq+3]);
        }
        __syncthreads();

        int cg = tid & 15;
        int nb = n0 + rr * 64 + 4 * cg;
        #pragma unroll
        for (int itr = 0; itr < 8; itr++) {
            int r2  = (tid >> 4) + 16 * itr;
            int sg2 = cg ^ (r2 & 15);
            float4 v = *(const float4*)&scr[r2 * 64 + sg2 * 4];
            float* orow = out + (size_t)(m0 + r2) * VSZ;
            if (nb + 3 < VSZ) {
                orow[nb]   = v.x; orow[nb+1] = v.y;
                orow[nb+2] = v.z; orow[nb+3] = v.w;
            } else {
                if (nb     < VSZ) orow[nb]   = v.x;
                if (nb + 1 < VSZ) orow[nb+1] = v.y;
                if (nb + 2 < VSZ) orow[nb+2] = v.z;
                if (nb + 3 < VSZ) orow[nb+3] = v.w;
            }
        }
        __syncthreads();
    }
}
#endif  // HAS_TCGEN05

__global__ void __launch_bounds__(256, 1) k4mma(const float* __restrict__ Wlm,
                                                float* __restrict__ out)
{
    extern __shared__ __align__(1024) char smem[];
    int tid = threadIdx.x;
    int m0 = blockIdx.x * 128;
    int g  = blockIdx.y;              // N-group 0..3, tiles jt = g, g+4, ...
    int nt = (NTILES - 1 - g) / 4 + 1;

#if HAS_TCGEN05
    __shared__ __align__(16) unsigned long long s_mbar[2];
    __shared__ uint32_t s_tmem;

    int wid = tid >> 5;
    uint32_t sb = s2u(smem);
    float* scr = (float*)(smem + SCR);
    uint32_t mbD0 = s2u(&s_mbar[0]);
    uint32_t mbD1 = s2u(&s_mbar[1]);

    if (wid == 0) {
        asm volatile("tcgen05.alloc.cta_group::1.sync.aligned.shared::cta.b32 [%0], %1;"
                     :: "r"(s2u(&s_tmem)), "r"(256u) : "memory");
        asm volatile("tcgen05.relinquish_alloc_permit.cta_group::1.sync.aligned;");
    }
    if (tid == 0) { mbar_init(mbD0, 1); mbar_init(mbD1, 1); }
    __syncthreads();
    uint32_t tmem;
    asm volatile("ld.shared.b32 %0, [%1];" : "=r"(tmem) : "r"(s2u(&s_tmem)));

    // prologue: A tile (once) + B(0)
    k4_load_tile(g_xf, sb + SMA, m0, TNUM, tid);
    k4_load_tile(Wlm, sb + SMB0, g * 128, VSZ, tid);
    asm volatile("fence.proxy.async.shared::cta;" ::: "memory");
    __syncthreads();
    uint64_t adesc = mk_desc(sb + SMA);

    int phD0 = 0, phD1 = 0;

    for (int i = 0; i < nt; i++) {
        int b = i & 1, pb = b ^ 1;

        // 1. issue MMA(i) on buffer b (already resident + synced)
        if (wid == 0 && elect1()) {
            uint64_t bdesc = mk_desc(sb + (b ? SMB1 : SMB0));
            uint32_t dreg = tmem + (uint32_t)(b * 128);
            #pragma unroll
            for (int s = 0; s < 16; s++) {
                uint64_t koff = (uint64_t)((s >> 2) * 1024 + (s & 3) * 2);
                mma_tf32(dreg, adesc + koff, bdesc + koff, K4_IDESC, s > 0);
            }
            mma_commit(b ? mbD1 : mbD0);
        }

        // 2. wait MMA(i-1) done -> TMEM pb readable, buffer pb free
        if (i >= 1) {
            if (pb) { mbar_wait(mbD1, phD1); phD1 ^= 1; }
            else    { mbar_wait(mbD0, phD0); phD0 ^= 1; }
        }

        // 3. load B(i+1) into freed buffer pb (overlaps MMA(i))
        if (i + 1 < nt) {
            k4_load_tile(Wlm, sb + (pb ? SMB1 : SMB0), (g + 4 * (i + 1)) * 128, VSZ, tid);
            asm volatile("fence.proxy.async.shared::cta;" ::: "memory");
        }

        // 4. epilogue(i-1) (overlaps MMA(i)); its syncthreads also orders the
        //    B(i+1) STS before MMA(i+1)
        if (i >= 1) {
            k4_epilogue(tmem + pb * 128, scr, m0, (g + 4 * (i - 1)) * 128, out, tid);
        } else {
            __syncthreads();
        }
    }

    // final tile epilogue
    {
        int b = (nt - 1) & 1;
        if (b) { mbar_wait(mbD1, phD1); phD1 ^= 1; }
        else   { mbar_wait(mbD0, phD0); phD0 ^= 1; }
        k4_epilogue(tmem + b * 128, scr, m0, (g + 4 * (nt - 1)) * 128, out, tid);
    }

    __syncthreads();
    if (wid == 0) {
        asm volatile("tcgen05.dealloc.cta_group::1.sync.aligned.b32 %0, %1;"
                     :: "r"(tmem), "r"(256u));
    }
#else
    // -------- fallback: plain fp32 smem GEMM (baseline sm_103 target) --------
    float* sA = (float*)(smem + SMA);     // [128][128]
    float* sB = (float*)(smem + SMB0);    // [128][128]

    for (int i = tid; i < 128 * 32; i += 256) {
        int r = i >> 5, q = i & 31;
        *(float4*)&sA[r * 128 + q * 4] = *(const float4*)&g_xf[(size_t)(m0 + r) * CH + q * 4];
    }

    int tx = tid & 15, ty = tid >> 4;

    for (int t = 0; t < nt; t++) {
        int n0 = (g + 4 * t) * 128;
        __syncthreads();
        for (int i = tid; i < 128 * 32; i += 256) {
            int r = i >> 5, q = i & 31;
            float4 v = make_float4(0.f, 0.f, 0.f, 0.f);
            if (n0 + r < VSZ)
                v = *(const float4*)&Wlm[(size_t)(n0 + r) * CH + q * 4];
            *(float4*)&sB[r * 128 + q * 4] = v;
        }
        __syncthreads();

        float acc[8][8];
        #pragma unroll
        for (int i = 0; i < 8; i++)
            #pragma unroll
            for (int j = 0; j < 8; j++) acc[i][j] = 0.f;

        for (int k = 0; k < 128; k++) {
            float a[8], b[8];
            #pragma unroll
            for (int i = 0; i < 8; i++) a[i] = sA[(ty * 8 + i) * 128 + k];
            #pragma unroll
            for (int j = 0; j < 8; j++) b[j] = sB[(tx * 8 + j) * 128 + k];
            #pragma unroll
            for (int i = 0; i < 8; i++)
                #pragma unroll
                for (int j = 0; j < 8; j++) acc[i][j] += a[i] * b[j];
        }

        #pragma unroll
        for (int i = 0; i < 8; i++) {
            float* row = out + (size_t)(m0 + ty * 8 + i) * VSZ;
            #pragma unroll
            for (int j = 0; j < 8; j++) {
                int n = n0 + tx * 8 + j;
                if (n < VSZ) row[n] = acc[i][j];
            }
        }
    }
#endif
}

// ==================== launch ====================
extern "C" void kernel_launch(void* const* d_in, const int* in_sizes, int n_in,
                              void* d_out, int out_size)
{
    const int*   ids    = (const int*)  d_in[0];
    const float* emb    = (const float*)d_in[1];
    const float* router = (const float*)d_in[2];
    const float* kexp   = (const float*)d_in[3];
    const float* vexp   = (const float*)d_in[4];
    const float* skv    = (const float*)d_in[5];
    const float* svv    = (const float*)d_in[6];
    const float* kvg    = (const float*)d_in[7];
    const float* Wq     = (const float*)d_in[8];
    const float* Wo     = (const float*)d_in[9];
    const float* Wm     = (const float*)d_in[10];
    const float* bm     = (const float*)d_in[11];
    const float* g1     = (const float*)d_in[12];
    const float* b1     = (const float*)d_in[13];
    const float* g2     = (const float*)d_in[14];
    const float* b2     = (const float*)d_in[15];
    const float* Wlm    = (const float*)d_in[16];

    float* out = (float*)d_out;
    float* gate_out = out + ((size_t)out_size - (size_t)TNUM * NE);

    cudaFuncSetAttribute(k4mma, cudaFuncAttributeMaxDynamicSharedMemorySize, K4_SMEM);

    k1<<<TNUM, 128>>>(ids, emb, router, Wq, g1, b1, gate_out);
    k2<<<TNUM/TB, 256>>>(kexp, vexp, skv, svv, kvg);
    k3<<<TNUM, 128>>>(Wo, Wm, bm, g2, b2);
    dim3 g4(TNUM/128, 4);
    k4mma<<<g4, 256, K4_SMEM>>>(Wlm, out);
}

// round 7
// speedup vs baseline: 1.0440x; 1.0440x over previous
#include <cuda_runtime.h>
#include <math.h>
#include <stdint.h>

#define TNUM 4096
#define CH 128
#define NE 16
#define KB 32
#define VSZ 50257
#define NTILES 393   // ceil(50257/128)

// scratch (static device arrays — no allocation)
__device__ float g_x [TNUM*CH];
__device__ float g_q [TNUM*CH];
__device__ float g_rw[TNUM*NE];
__device__ float g_ao[TNUM*CH];
__device__ float g_xf[TNUM*CH];

// ---------------- block reduce over 128 threads ----------------
__device__ __forceinline__ float blockReduce128(float v, float* sred, int tid) {
    #pragma unroll
    for (int o = 16; o; o >>= 1) v += __shfl_down_sync(0xffffffffu, v, o);
    if ((tid & 31) == 0) sred[tid >> 5] = v;
    __syncthreads();
    return sred[0] + sred[1] + sred[2] + sred[3];
}

// ==================== K1: embed + LN1 + routing + q ====================
__global__ __launch_bounds__(128) void k1(const int* __restrict__ ids,
        const float* __restrict__ emb, const float* __restrict__ router,
        const float* __restrict__ Wq, const float* __restrict__ g1,
        const float* __restrict__ b1, float* __restrict__ gate_out)
{
    int t = blockIdx.x, tid = threadIdx.x;
    __shared__ float sx[CH];
    __shared__ float sred[4];
    __shared__ float sgl[NE];

    int id = ids[t];
    float xv = __ldg(&emb[(long long)id * CH + tid]);
    g_x[t*CH + tid] = xv;

    float mu = blockReduce128(xv, sred, tid) * (1.f/CH);
    __syncthreads();
    float d  = xv - mu;
    float var = blockReduce128(d*d, sred, tid) * (1.f/CH);
    float xln = d * rsqrtf(var + 1e-5f) * g1[tid] + b1[tid];
    sx[tid] = xln;
    __syncthreads();

    int e = tid >> 3, l = tid & 7;
    float gl = 0.f;
    #pragma unroll 4
    for (int k = l; k < CH; k += 8) gl += sx[k] * __ldg(&router[e*CH + k]);
    #pragma unroll
    for (int o = 4; o; o >>= 1) gl += __shfl_xor_sync(0xffffffffu, gl, o, 8);
    if (l == 0) sgl[e] = gl;
    __syncthreads();

    if (tid < NE) gate_out[(long long)t*NE + tid] = sgl[tid];

    float mx = -1e30f;
    #pragma unroll
    for (int i = 0; i < NE; i++) mx = fmaxf(mx, sgl[i]);
    float ss = 0.f;
    #pragma unroll
    for (int i = 0; i < NE; i++) ss += __expf(sgl[i] - mx);
    if (tid < NE) g_rw[t*NE + tid] = __expf(sgl[tid] - mx) / ss;

    float acc = 0.f;
    const float4* wr = (const float4*)(Wq + tid*CH);
    const float4* xr = (const float4*)sx;
    #pragma unroll 8
    for (int k = 0; k < 32; k++) {
        float4 w = __ldg(&wr[k]);
        float4 x4 = xr[k];
        acc += w.x*x4.x + w.y*x4.y + w.z*x4.z + w.w*x4.w;
    }
    g_q[t*CH + tid] = acc;
}

// ==================== K2: expert attention ====================
#define TB 32
#define QSTR 132
__global__ __launch_bounds__(256) void k2(const float* __restrict__ kexp,
        const float* __restrict__ vexp, const float* __restrict__ skv,
        const float* __restrict__ svv, const float* __restrict__ kvg)
{
    __shared__ float sQ[TB*QSTR];
    __shared__ float sT[KB*QSTR];
    __shared__ float sS[TB][KB+1];
    __shared__ float sRW[TB*NE];

    int t0 = blockIdx.x * TB;
    int tid = threadIdx.x;
    float g = 1.f / (1.f + __expf(-kvg[0]));

    for (int i = tid; i < TB*CH; i += 256) {
        int tt = i >> 7, cc = i & 127;
        sQ[tt*QSTR + cc] = g_q[(t0+tt)*CH + cc];
    }
    for (int i = tid; i < TB*NE; i += 256) sRW[i] = g_rw[t0*NE + i];

    int t = tid >> 3, kg = tid & 7;
    float sdyn[4] = {0,0,0,0}, sstat[4];

    for (int e = 0; e < NE; e++) {
        __syncthreads();
        for (int i = tid; i < KB*CH; i += 256) {
            int kk = i >> 7, cc = i & 127;
            sT[kk*QSTR + cc] = __ldg(&kexp[e*KB*CH + i]);
        }
        __syncthreads();
        float rwv = sRW[t*NE + e];
        float dj[4] = {0,0,0,0};
        const float4* qp = (const float4*)(sQ + t*QSTR);
        #pragma unroll 4
        for (int c4 = 0; c4 < 32; c4++) {
            float4 qv = qp[c4];
            #pragma unroll
            for (int j = 0; j < 4; j++) {
                int k = kg + 8*j;
                float4 kv = *(const float4*)(sT + k*QSTR + 4*c4);
                dj[j] += qv.x*kv.x + qv.y*kv.y + qv.z*kv.z + qv.w*kv.w;
            }
        }
        #pragma unroll
        for (int j = 0; j < 4; j++) sdyn[j] += rwv * dj[j];
    }
    __syncthreads();
    for (int i = tid; i < KB*CH; i += 256) {
        int kk = i >> 7, cc = i & 127;
        sT[kk*QSTR + cc] = __ldg(&skv[i]);
    }
    __syncthreads();
    {
        float dj[4] = {0,0,0,0};
        const float4* qp = (const float4*)(sQ + t*QSTR);
        #pragma unroll 4
        for (int c4 = 0; c4 < 32; c4++) {
            float4 qv = qp[c4];
            #pragma unroll
            for (int j = 0; j < 4; j++) {
                int k = kg + 8*j;
                float4 kv = *(const float4*)(sT + k*QSTR + 4*c4);
                dj[j] += qv.x*kv.x + qv.y*kv.y + qv.z*kv.z + qv.w*kv.w;
            }
        }
        #pragma unroll
        for (int j = 0; j < 4; j++) sstat[j] = dj[j];
    }
    const float scale = 0.08838834764831845f;
    #pragma unroll
    for (int j = 0; j < 4; j++)
        sS[t][kg + 8*j] = (g*sdyn[j] + (1.f-g)*sstat[j]) * scale;
    __syncthreads();

    if (tid < TB) {
        float mx = -1e30f;
        #pragma unroll
        for (int k = 0; k < KB; k++) mx = fmaxf(mx, sS[tid][k]);
        float ssum = 0.f;
        #pragma unroll
        for (int k = 0; k < KB; k++) { float ev = __expf(sS[tid][k] - mx); sS[tid][k] = ev; ssum += ev; }
        float inv = 1.f / ssum;
        #pragma unroll
        for (int k = 0; k < KB; k++) sS[tid][k] *= inv;
    }

    float acc[16];
    #pragma unroll
    for (int i = 0; i < 16; i++) acc[i] = 0.f;

    for (int e = 0; e < NE; e++) {
        __syncthreads();
        for (int i = tid; i < KB*CH; i += 256) {
            int kk = i >> 7, cc = i & 127;
            sT[kk*QSTR + cc] = __ldg(&vexp[e*KB*CH + i]);
        }
        __syncthreads();
        float we = g * sRW[t*NE + e];
        #pragma unroll 4
        for (int k = 0; k < KB; k++) {
            float w = we * sS[t][k];
            #pragma unroll
            for (int j = 0; j < 4; j++) {
                float4 vv = *(const float4*)(sT + k*QSTR + 4*(kg + 8*j));
                acc[j*4+0] += w*vv.x; acc[j*4+1] += w*vv.y;
                acc[j*4+2] += w*vv.z; acc[j*4+3] += w*vv.w;
            }
        }
    }
    __syncthreads();
    for (int i = tid; i < KB*CH; i += 256) {
        int kk = i >> 7, cc = i & 127;
        sT[kk*QSTR + cc] = __ldg(&svv[i]);
    }
    __syncthreads();
    {
        float we = 1.f - g;
        #pragma unroll 4
        for (int k = 0; k < KB; k++) {
            float w = we * sS[t][k];
            #pragma unroll
            for (int j = 0; j < 4; j++) {
                float4 vv = *(const float4*)(sT + k*QSTR + 4*(kg + 8*j));
                acc[j*4+0] += w*vv.x; acc[j*4+1] += w*vv.y;
                acc[j*4+2] += w*vv.z; acc[j*4+3] += w*vv.w;
            }
        }
    }
    #pragma unroll
    for (int j = 0; j < 4; j++) {
        float4 o;
        o.x = acc[j*4+0]; o.y = acc[j*4+1]; o.z = acc[j*4+2]; o.w = acc[j*4+3];
        *(float4*)&g_ao[(t0+t)*CH + 4*(kg + 8*j)] = o;
    }
}

// ==================== K3: Wo + residual + LN2 + MLP + residual ====================
__global__ __launch_bounds__(128) void k3(const float* __restrict__ Wo,
        const float* __restrict__ Wm, const float* __restrict__ bm,
        const float* __restrict__ g2, const float* __restrict__ b2)
{
    int t = blockIdx.x, tid = threadIdx.x;
    __shared__ float sa[CH];
    __shared__ float sred[4];

    sa[tid] = g_ao[t*CH + tid];
    __syncthreads();

    float o = 0.f;
    {
        const float4* wr = (const float4*)(Wo + tid*CH);
        const float4* ar = (const float4*)sa;
        #pragma unroll 8
        for (int k = 0; k < 32; k++) {
            float4 w = __ldg(&wr[k]);
            float4 a4 = ar[k];
            o += w.x*a4.x + w.y*a4.y + w.z*a4.z + w.w*a4.w;
        }
    }
    float x2 = g_x[t*CH + tid] + o;

    __syncthreads();
    float mu = blockReduce128(x2, sred, tid) * (1.f/CH);
    __syncthreads();
    float d = x2 - mu;
    float var = blockReduce128(d*d, sred, tid) * (1.f/CH);
    float xln = d * rsqrtf(var + 1e-5f) * g2[tid] + b2[tid];
    __syncthreads();
    sa[tid] = xln;
    __syncthreads();

    float m = __ldg(&bm[tid]);
    {
        const float4* wr = (const float4*)(Wm + tid*CH);
        const float4* ar = (const float4*)sa;
        #pragma unroll 8
        for (int k = 0; k < 32; k++) {
            float4 w = __ldg(&wr[k]);
            float4 a4 = ar[k];
            m += w.x*a4.x + w.y*a4.y + w.z*a4.z + w.w*a4.w;
        }
    }
    g_xf[t*CH + tid] = x2 + m;
}

// ==================== K4: LM head GEMM ====================
// D[4096,50257] = Xf[4096,128] @ Wlm[50257,128]^T  (both K-major)

#if defined(__CUDA_ARCH__) && (__CUDA_ARCH__ == 1030) && defined(__CUDA_ARCH_FEAT_SM103_ALL)
#define HAS_TCGEN05 1
#else
#define HAS_TCGEN05 0
#endif

__device__ __forceinline__ uint32_t s2u(const void* p) {
    uint32_t a;
    asm("{ .reg .u64 t; cvta.to.shared.u64 t, %1; cvt.u32.u64 %0, t; }" : "=r"(a) : "l"(p));
    return a;
}

#define SMA 0
#define SMB 65536
#define SCR 131072
#define K4_SMEM 196608   // 64K A + 64K B + 64K epilogue scratch

#if HAS_TCGEN05

__device__ __forceinline__ uint32_t f2tf(float f) {
    uint32_t r; asm("cvt.rna.tf32.f32 %0, %1;" : "=r"(r) : "f"(f)); return r;
}
__device__ __forceinline__ bool elect1() {
    uint32_t p;
    asm volatile("{ .reg .pred p; elect.sync _|p, 0xFFFFFFFF; selp.b32 %0, 1, 0, p; }" : "=r"(p));
    return p != 0;
}
__device__ __forceinline__ void mbar_init(uint32_t a, uint32_t cnt) {
    asm volatile("mbarrier.init.shared.b64 [%0], %1;" :: "r"(a), "r"(cnt) : "memory");
}
__device__ __forceinline__ void mbar_wait(uint32_t a, uint32_t ph) {
    asm volatile(
        "{\n\t.reg .pred P;\n"
        "W_%=:\n\t"
        "mbarrier.try_wait.parity.acquire.cta.shared::cta.b64 P, [%0], %1, 0x989680;\n\t"
        "@P bra D_%=;\n\t"
        "bra W_%=;\n"
        "D_%=:\n\t}"
        :: "r"(a), "r"(ph) : "memory");
}
__device__ __forceinline__ void sts128(uint32_t a, uint32_t r0, uint32_t r1, uint32_t r2, uint32_t r3) {
    asm volatile("st.shared.v4.b32 [%0], {%1, %2, %3, %4};" :: "r"(a), "r"(r0), "r"(r1), "r"(r2), "r"(r3) : "memory");
}
__device__ __forceinline__ void mma_tf32(uint32_t d, uint64_t ad, uint64_t bd, uint32_t idesc, bool accum) {
    uint32_t en = accum ? 1u : 0u;
    asm volatile(
        "{\n\t.reg .pred p;\n\t"
        "setp.ne.u32 p, %5, 0;\n\t"
        "tcgen05.mma.cta_group::1.kind::tf32 [%0], %1, %2, %3, {%4, %4, %4, %4}, p;\n\t}"
        :: "r"(d), "l"(ad), "l"(bd), "r"(idesc), "r"(0u), "r"(en) : "memory");
}
__device__ __forceinline__ void mma_commit(uint32_t mbar) {
    asm volatile("tcgen05.commit.cta_group::1.mbarrier::arrive::one.shared::cluster.b64 [%0];" :: "r"(mbar) : "memory");
}
// SW128 K-major smem descriptor: layout=2, version=1, SBO=64, LBO=1
__device__ __forceinline__ uint64_t mk_desc(uint32_t addr) {
    const uint64_t base = (uint64_t(2) << 61) | (uint64_t(1) << 46) | (uint64_t(64) << 32) | (uint64_t(1) << 16);
    return base | ((uint64_t)(addr >> 4) & 0x3FFF);
}

#define LDTM32(r, a) \
    asm volatile( \
        "tcgen05.ld.sync.aligned.32x32b.x32.b32 " \
        "{%0, %1, %2, %3, %4, %5, %6, %7, " \
        " %8, %9, %10, %11, %12, %13, %14, %15, " \
        " %16, %17, %18, %19, %20, %21, %22, %23, " \
        " %24, %25, %26, %27, %28, %29, %30, %31}, [%32];" \
        : "=r"((r)[0]),  "=r"((r)[1]),  "=r"((r)[2]),  "=r"((r)[3]), \
          "=r"((r)[4]),  "=r"((r)[5]),  "=r"((r)[6]),  "=r"((r)[7]), \
          "=r"((r)[8]),  "=r"((r)[9]),  "=r"((r)[10]), "=r"((r)[11]), \
          "=r"((r)[12]), "=r"((r)[13]), "=r"((r)[14]), "=r"((r)[15]), \
          "=r"((r)[16]), "=r"((r)[17]), "=r"((r)[18]), "=r"((r)[19]), \
          "=r"((r)[20]), "=r"((r)[21]), "=r"((r)[22]), "=r"((r)[23]), \
          "=r"((r)[24]), "=r"((r)[25]), "=r"((r)[26]), "=r"((r)[27]), \
          "=r"((r)[28]), "=r"((r)[29]), "=r"((r)[30]), "=r"((r)[31]) \
        : "r"(a))

// idesc: dtype=F32(1<<4), atype=TF32(2<<7), btype=TF32(2<<10), N=128(16<<17), M=128(8<<24)
#define K4_IDESC ((1u<<4) | (2u<<7) | (2u<<10) | (16u<<17) | (8u<<24))

__device__ __forceinline__ void k4_load_tile(const float* __restrict__ src, uint32_t sdst,
                                             int row0, int rowmax, int tid)
{
    // 128 rows x 128 cols f32 -> 4 K-chunks of [128 x 32] SW128-swizzled tf32
    #pragma unroll
    for (int it = 0; it < 16; it++) {
        int f = tid + it * 256;          // float4 index, 0..4095
        int r = f >> 5, q = f & 31;
        int kc = q >> 3, c4 = q & 7;
        float4 v = make_float4(0.f, 0.f, 0.f, 0.f);
        if (row0 + r < rowmax)
            v = *(const float4*)&src[(size_t)(row0 + r) * CH + q * 4];
        uint32_t off = (uint32_t)(kc * 16384 + r * 128 + c4 * 16);
        off = off ^ ((off >> 3) & 0x70);
        sts128(sdst + off, f2tf(v.x), f2tf(v.y), f2tf(v.z), f2tf(v.w));
    }
}

// Epilogue v4: both LDTM rounds -> 64KB scratch (two 32KB halves, no mid-sync),
// one sync, then per-row ALIGNED float4 STG (c0 = (-m) mod 4 alignment fixup).
__device__ __forceinline__ void k4_epilogue(uint32_t dt, float* __restrict__ scr,
                                            int m0, int n0,
                                            float* __restrict__ out, int tid)
{
    int wid = tid >> 5, lid = tid & 31;
    int row  = (wid & 3) * 32 + lid;   // TMEM lane -> D row
    int half = wid >> 2;               // 32-col half within each 64-col round
    uint32_t scr_u = s2u(scr);

    // phase 1: TMEM -> scratch (round rr into scratch half rr; no sync between)
    #pragma unroll
    for (int rr = 0; rr < 2; rr++) {
        uint32_t r[32];
        LDTM32(r, dt + rr * 64 + half * 32);
        asm volatile("tcgen05.wait::ld.sync.aligned;" ::: "memory");
        #pragma unroll
        for (int gq = 0; gq < 8; gq++) {
            int cgl = half * 8 + gq;             // col-group 0..15 within round
            int sg  = cgl ^ (row & 15);
            sts128(scr_u + (uint32_t)(rr * 8192 + row * 64 + sg * 4) * 4,
                   r[4*gq], r[4*gq+1], r[4*gq+2], r[4*gq+3]);
        }
    }
    __syncthreads();

    // phase 2: scratch -> gmem, one full 128-col row per warp-step
    if (n0 + 128 <= VSZ) {
        #pragma unroll 4
        for (int itr = 0; itr < 16; itr++) {
            int r2 = wid * 16 + itr;
            int m  = m0 + r2;
            int c0 = (4 - (m & 3)) & 3;    // (m*VSZ + n0 + c0) % 4 == 0
            int sw = r2 & 15;
            float* orow = out + (size_t)m * VSZ + n0;
            int j = c0 + 4 * lid;
            if (j + 3 < 128) {
                float4 v;
                float* vp = &v.x;
                #pragma unroll
                for (int k = 0; k < 4; k++) {
                    int col = j + k;
                    int hh = col >> 6, jj = col & 63;
                    int sg2 = (jj >> 2) ^ sw;
                    vp[k] = scr[hh * 8192 + r2 * 64 + sg2 * 4 + (jj & 3)];
                }
                *(float4*)(orow + j) = v;   // provably 16B-aligned
            }
            if (c0 && lid < 4) {            // 4 leftover columns, scalar
                int col = (lid < c0) ? lid : (c0 + 124 + (lid - c0));
                int hh = col >> 6, jj = col & 63;
                int sg2 = (jj >> 2) ^ sw;
                orow[col] = scr[hh * 8192 + r2 * 64 + sg2 * 4 + (jj & 3)];
            }
        }
    } else {
        // vocab edge tile: scalar bounds-checked
        for (int itr = 0; itr < 16; itr++) {
            int r2 = wid * 16 + itr;
            int sw = r2 & 15;
            float* orow = out + (size_t)(m0 + r2) * VSZ;
            #pragma unroll
            for (int k = 0; k < 4; k++) {
                int col = lid + 32 * k;
                if (n0 + col < VSZ) {
                    int hh = col >> 6, jj = col & 63;
                    int sg2 = (jj >> 2) ^ sw;
                    orow[n0 + col] = scr[hh * 8192 + r2 * 64 + sg2 * 4 + (jj & 3)];
                }
            }
        }
    }
}
#endif  // HAS_TCGEN05

__global__ void __launch_bounds__(256, 1) k4mma(const float* __restrict__ Wlm,
                                                float* __restrict__ out)
{
    extern __shared__ __align__(1024) char smem[];
    int tid = threadIdx.x;
    int m0 = blockIdx.x * 128;
    int g  = blockIdx.y;              // N-group 0..3, tiles jt = g, g+4, ...
    int nt = (NTILES - 1 - g) / 4 + 1;

#if HAS_TCGEN05
    __shared__ __align__(16) unsigned long long s_mbar[2];
    __shared__ uint32_t s_tmem;

    int wid = tid >> 5;
    uint32_t sb = s2u(smem);
    float* scr = (float*)(smem + SCR);
    uint32_t mb[2] = { s2u(&s_mbar[0]), s2u(&s_mbar[1]) };

    if (wid == 0) {
        asm volatile("tcgen05.alloc.cta_group::1.sync.aligned.shared::cta.b32 [%0], %1;"
                     :: "r"(s2u(&s_tmem)), "r"(256u) : "memory");
        asm volatile("tcgen05.relinquish_alloc_permit.cta_group::1.sync.aligned;");
    }
    if (tid == 0) { mbar_init(mb[0], 1); mbar_init(mb[1], 1); }
    __syncthreads();
    uint32_t tmem;
    asm volatile("ld.shared.b32 %0, [%1];" : "=r"(tmem) : "r"(s2u(&s_tmem)));

    // prologue: A tile (once) + B(0)
    k4_load_tile(g_xf, sb + SMA, m0, TNUM, tid);
    k4_load_tile(Wlm, sb + SMB, g * 128, VSZ, tid);
    asm volatile("fence.proxy.async.shared::cta;" ::: "memory");
    __syncthreads();

    uint64_t adesc = mk_desc(sb + SMA);
    uint64_t bdesc = mk_desc(sb + SMB);
    int ph[2] = {0, 0};

    for (int i = 0; i < nt; i++) {
        int b = i & 1;

        // 1. issue MMA(i) from the (resident, synced) B buffer into TMEM[b]
        if (wid == 0 && elect1()) {
            uint32_t dreg = tmem + (uint32_t)(b * 128);
            #pragma unroll
            for (int s = 0; s < 16; s++) {
                uint64_t koff = (uint64_t)((s >> 2) * 1024 + (s & 3) * 2);
                mma_tf32(dreg, adesc + koff, bdesc + koff, K4_IDESC, s > 0);
            }
            mma_commit(mb[b]);
        }

        // 2. epilogue(i-1) overlaps MMA(i)  (TMEM[b^1], done since last iter)
        if (i >= 1)
            k4_epilogue(tmem + (b ^ 1) * 128, scr, m0, (g + 4 * (i - 1)) * 128, out, tid);

        // 3. wait MMA(i) -> B buffer free, TMEM[b] valid for next-iter epilogue
        mbar_wait(mb[b], ph[b]); ph[b] ^= 1;
        asm volatile("tcgen05.fence::after_thread_sync;" ::: "memory");

        // 4. refill B with tile i+1
        if (i + 1 < nt) {
            k4_load_tile(Wlm, sb + SMB, (g + 4 * (i + 1)) * 128, VSZ, tid);
            asm volatile("fence.proxy.async.shared::cta;" ::: "memory");
        }
        __syncthreads();
    }

    // final tile epilogue
    k4_epilogue(tmem + ((nt - 1) & 1) * 128, scr, m0, (g + 4 * (nt - 1)) * 128, out, tid);

    __syncthreads();
    if (wid == 0) {
        asm volatile("tcgen05.dealloc.cta_group::1.sync.aligned.b32 %0, %1;"
                     :: "r"(tmem), "r"(256u));
    }
#else
    // -------- fallback: plain fp32 smem GEMM (baseline sm_103 target) --------
    float* sA = (float*)(smem + SMA);     // [128][128]
    float* sB = (float*)(smem + SMB);     // [128][128]

    for (int i = tid; i < 128 * 32; i += 256) {
        int r = i >> 5, q = i & 31;
        *(float4*)&sA[r * 128 + q * 4] = *(const float4*)&g_xf[(size_t)(m0 + r) * CH + q * 4];
    }

    int tx = tid & 15, ty = tid >> 4;

    for (int t = 0; t < nt; t++) {
        int n0 = (g + 4 * t) * 128;
        __syncthreads();
        for (int i = tid; i < 128 * 32; i += 256) {
            int r = i >> 5, q = i & 31;
            float4 v = make_float4(0.f, 0.f, 0.f, 0.f);
            if (n0 + r < VSZ)
                v = *(const float4*)&Wlm[(size_t)(n0 + r) * CH + q * 4];
            *(float4*)&sB[r * 128 + q * 4] = v;
        }
        __syncthreads();

        float acc[8][8];
        #pragma unroll
        for (int i = 0; i < 8; i++)
            #pragma unroll
            for (int j = 0; j < 8; j++) acc[i][j] = 0.f;

        for (int k = 0; k < 128; k++) {
            float a[8], b[8];
            #pragma unroll
            for (int i = 0; i < 8; i++) a[i] = sA[(ty * 8 + i) * 128 + k];
            #pragma unroll
            for (int j = 0; j < 8; j++) b[j] = sB[(tx * 8 + j) * 128 + k];
            #pragma unroll
            for (int i = 0; i < 8; i++)
                #pragma unroll
                for (int j = 0; j < 8; j++) acc[i][j] += a[i] * b[j];
        }

        #pragma unroll
        for (int i = 0; i < 8; i++) {
            float* row = out + (size_t)(m0 + ty * 8 + i) * VSZ;
            #pragma unroll
            for (int j = 0; j < 8; j++) {
                int n = n0 + tx * 8 + j;
                if (n < VSZ) row[n] = acc[i][j];
            }
        }
    }
#endif
}

// ==================== launch ====================
extern "C" void kernel_launch(void* const* d_in, const int* in_sizes, int n_in,
                              void* d_out, int out_size)
{
    const int*   ids    = (const int*)  d_in[0];
    const float* emb    = (const float*)d_in[1];
    const float* router = (const float*)d_in[2];
    const float* kexp   = (const float*)d_in[3];
    const float* vexp   = (const float*)d_in[4];
    const float* skv    = (const float*)d_in[5];
    const float* svv    = (const float*)d_in[6];
    const float* kvg    = (const float*)d_in[7];
    const float* Wq     = (const float*)d_in[8];
    const float* Wo     = (const float*)d_in[9];
    const float* Wm     = (const float*)d_in[10];
    const float* bm     = (const float*)d_in[11];
    const float* g1     = (const float*)d_in[12];
    const float* b1     = (const float*)d_in[13];
    const float* g2     = (const float*)d_in[14];
    const float* b2     = (const float*)d_in[15];
    const float* Wlm    = (const float*)d_in[16];

    float* out = (float*)d_out;
    float* gate_out = out + ((size_t)out_size - (size_t)TNUM * NE);

    cudaFuncSetAttribute(k4mma, cudaFuncAttributeMaxDynamicSharedMemorySize, K4_SMEM);

    k1<<<TNUM, 128>>>(ids, emb, router, Wq, g1, b1, gate_out);
    k2<<<TNUM/TB, 256>>>(kexp, vexp, skv, svv, kvg);
    k3<<<TNUM, 128>>>(Wo, Wm, bm, g2, b2);
    dim3 g4(TNUM/128, 4);
    k4mma<<<g4, 256, K4_SMEM>>>(Wlm, out);
}

// round 8
// speedup vs baseline: 1.0550x; 1.0105x over previous
#include <cuda_runtime.h>
#include <math.h>
#include <stdint.h>

#define TNUM 4096
#define CH 128
#define NE 16
#define KB 32
#define VSZ 50257
#define NTILES 393   // ceil(50257/128)

// scratch (static device arrays — no allocation)
__device__ float g_x [TNUM*CH];
__device__ float g_q [TNUM*CH];
__device__ float g_rw[TNUM*NE];
__device__ float g_ao[TNUM*CH];
__device__ float g_xf[TNUM*CH];

// ---------------- block reduce over 128 threads ----------------
__device__ __forceinline__ float blockReduce128(float v, float* sred, int tid) {
    #pragma unroll
    for (int o = 16; o; o >>= 1) v += __shfl_down_sync(0xffffffffu, v, o);
    if ((tid & 31) == 0) sred[tid >> 5] = v;
    __syncthreads();
    return sred[0] + sred[1] + sred[2] + sred[3];
}

// ==================== K1: embed + LN1 + routing + q ====================
__global__ __launch_bounds__(128) void k1(const int* __restrict__ ids,
        const float* __restrict__ emb, const float* __restrict__ router,
        const float* __restrict__ Wq, const float* __restrict__ g1,
        const float* __restrict__ b1, float* __restrict__ gate_out)
{
    int t = blockIdx.x, tid = threadIdx.x;
    __shared__ float sx[CH];
    __shared__ float sred[4];
    __shared__ float sgl[NE];

    int id = ids[t];
    float xv = __ldg(&emb[(long long)id * CH + tid]);
    g_x[t*CH + tid] = xv;

    float mu = blockReduce128(xv, sred, tid) * (1.f/CH);
    __syncthreads();
    float d  = xv - mu;
    float var = blockReduce128(d*d, sred, tid) * (1.f/CH);
    float xln = d * rsqrtf(var + 1e-5f) * g1[tid] + b1[tid];
    sx[tid] = xln;
    __syncthreads();

    int e = tid >> 3, l = tid & 7;
    float gl = 0.f;
    #pragma unroll 4
    for (int k = l; k < CH; k += 8) gl += sx[k] * __ldg(&router[e*CH + k]);
    #pragma unroll
    for (int o = 4; o; o >>= 1) gl += __shfl_xor_sync(0xffffffffu, gl, o, 8);
    if (l == 0) sgl[e] = gl;
    __syncthreads();

    if (tid < NE) gate_out[(long long)t*NE + tid] = sgl[tid];

    float mx = -1e30f;
    #pragma unroll
    for (int i = 0; i < NE; i++) mx = fmaxf(mx, sgl[i]);
    float ss = 0.f;
    #pragma unroll
    for (int i = 0; i < NE; i++) ss += __expf(sgl[i] - mx);
    if (tid < NE) g_rw[t*NE + tid] = __expf(sgl[tid] - mx) / ss;

    float acc = 0.f;
    const float4* wr = (const float4*)(Wq + tid*CH);
    const float4* xr = (const float4*)sx;
    #pragma unroll 8
    for (int k = 0; k < 32; k++) {
        float4 w = __ldg(&wr[k]);
        float4 x4 = xr[k];
        acc += w.x*x4.x + w.y*x4.y + w.z*x4.z + w.w*x4.w;
    }
    g_q[t*CH + tid] = acc;
}

// ==================== K2: expert attention ====================
#define TB 32
#define QSTR 132
__global__ __launch_bounds__(256) void k2(const float* __restrict__ kexp,
        const float* __restrict__ vexp, const float* __restrict__ skv,
        const float* __restrict__ svv, const float* __restrict__ kvg)
{
    __shared__ float sQ[TB*QSTR];
    __shared__ float sT[KB*QSTR];
    __shared__ float sS[TB][KB+1];
    __shared__ float sRW[TB*NE];

    int t0 = blockIdx.x * TB;
    int tid = threadIdx.x;
    float g = 1.f / (1.f + __expf(-kvg[0]));

    for (int i = tid; i < TB*CH; i += 256) {
        int tt = i >> 7, cc = i & 127;
        sQ[tt*QSTR + cc] = g_q[(t0+tt)*CH + cc];
    }
    for (int i = tid; i < TB*NE; i += 256) sRW[i] = g_rw[t0*NE + i];

    int t = tid >> 3, kg = tid & 7;
    float sdyn[4] = {0,0,0,0}, sstat[4];

    for (int e = 0; e < NE; e++) {
        __syncthreads();
        for (int i = tid; i < KB*CH; i += 256) {
            int kk = i >> 7, cc = i & 127;
            sT[kk*QSTR + cc] = __ldg(&kexp[e*KB*CH + i]);
        }
        __syncthreads();
        float rwv = sRW[t*NE + e];
        float dj[4] = {0,0,0,0};
        const float4* qp = (const float4*)(sQ + t*QSTR);
        #pragma unroll 4
        for (int c4 = 0; c4 < 32; c4++) {
            float4 qv = qp[c4];
            #pragma unroll
            for (int j = 0; j < 4; j++) {
                int k = kg + 8*j;
                float4 kv = *(const float4*)(sT + k*QSTR + 4*c4);
                dj[j] += qv.x*kv.x + qv.y*kv.y + qv.z*kv.z + qv.w*kv.w;
            }
        }
        #pragma unroll
        for (int j = 0; j < 4; j++) sdyn[j] += rwv * dj[j];
    }
    __syncthreads();
    for (int i = tid; i < KB*CH; i += 256) {
        int kk = i >> 7, cc = i & 127;
        sT[kk*QSTR + cc] = __ldg(&skv[i]);
    }
    __syncthreads();
    {
        float dj[4] = {0,0,0,0};
        const float4* qp = (const float4*)(sQ + t*QSTR);
        #pragma unroll 4
        for (int c4 = 0; c4 < 32; c4++) {
            float4 qv = qp[c4];
            #pragma unroll
            for (int j = 0; j < 4; j++) {
                int k = kg + 8*j;
                float4 kv = *(const float4*)(sT + k*QSTR + 4*c4);
                dj[j] += qv.x*kv.x + qv.y*kv.y + qv.z*kv.z + qv.w*kv.w;
            }
        }
        #pragma unroll
        for (int j = 0; j < 4; j++) sstat[j] = dj[j];
    }
    const float scale = 0.08838834764831845f;
    #pragma unroll
    for (int j = 0; j < 4; j++)
        sS[t][kg + 8*j] = (g*sdyn[j] + (1.f-g)*sstat[j]) * scale;
    __syncthreads();

    if (tid < TB) {
        float mx = -1e30f;
        #pragma unroll
        for (int k = 0; k < KB; k++) mx = fmaxf(mx, sS[tid][k]);
        float ssum = 0.f;
        #pragma unroll
        for (int k = 0; k < KB; k++) { float ev = __expf(sS[tid][k] - mx); sS[tid][k] = ev; ssum += ev; }
        float inv = 1.f / ssum;
        #pragma unroll
        for (int k = 0; k < KB; k++) sS[tid][k] *= inv;
    }

    float acc[16];
    #pragma unroll
    for (int i = 0; i < 16; i++) acc[i] = 0.f;

    for (int e = 0; e < NE; e++) {
        __syncthreads();
        for (int i = tid; i < KB*CH; i += 256) {
            int kk = i >> 7, cc = i & 127;
            sT[kk*QSTR + cc] = __ldg(&vexp[e*KB*CH + i]);
        }
        __syncthreads();
        float we = g * sRW[t*NE + e];
        #pragma unroll 4
        for (int k = 0; k < KB; k++) {
            float w = we * sS[t][k];
            #pragma unroll
            for (int j = 0; j < 4; j++) {
                float4 vv = *(const float4*)(sT + k*QSTR + 4*(kg + 8*j));
                acc[j*4+0] += w*vv.x; acc[j*4+1] += w*vv.y;
                acc[j*4+2] += w*vv.z; acc[j*4+3] += w*vv.w;
            }
        }
    }
    __syncthreads();
    for (int i = tid; i < KB*CH; i += 256) {
        int kk = i >> 7, cc = i & 127;
        sT[kk*QSTR + cc] = __ldg(&svv[i]);
    }
    __syncthreads();
    {
        float we = 1.f - g;
        #pragma unroll 4
        for (int k = 0; k < KB; k++) {
            float w = we * sS[t][k];
            #pragma unroll
            for (int j = 0; j < 4; j++) {
                float4 vv = *(const float4*)(sT + k*QSTR + 4*(kg + 8*j));
                acc[j*4+0] += w*vv.x; acc[j*4+1] += w*vv.y;
                acc[j*4+2] += w*vv.z; acc[j*4+3] += w*vv.w;
            }
        }
    }
    #pragma unroll
    for (int j = 0; j < 4; j++) {
        float4 o;
        o.x = acc[j*4+0]; o.y = acc[j*4+1]; o.z = acc[j*4+2]; o.w = acc[j*4+3];
        *(float4*)&g_ao[(t0+t)*CH + 4*(kg + 8*j)] = o;
    }
}

// ==================== K3: Wo + residual + LN2 + MLP + residual ====================
__global__ __launch_bounds__(128) void k3(const float* __restrict__ Wo,
        const float* __restrict__ Wm, const float* __restrict__ bm,
        const float* __restrict__ g2, const float* __restrict__ b2)
{
    int t = blockIdx.x, tid = threadIdx.x;
    __shared__ float sa[CH];
    __shared__ float sred[4];

    sa[tid] = g_ao[t*CH + tid];
    __syncthreads();

    float o = 0.f;
    {
        const float4* wr = (const float4*)(Wo + tid*CH);
        const float4* ar = (const float4*)sa;
        #pragma unroll 8
        for (int k = 0; k < 32; k++) {
            float4 w = __ldg(&wr[k]);
            float4 a4 = ar[k];
            o += w.x*a4.x + w.y*a4.y + w.z*a4.z + w.w*a4.w;
        }
    }
    float x2 = g_x[t*CH + tid] + o;

    __syncthreads();
    float mu = blockReduce128(x2, sred, tid) * (1.f/CH);
    __syncthreads();
    float d = x2 - mu;
    float var = blockReduce128(d*d, sred, tid) * (1.f/CH);
    float xln = d * rsqrtf(var + 1e-5f) * g2[tid] + b2[tid];
    __syncthreads();
    sa[tid] = xln;
    __syncthreads();

    float m = __ldg(&bm[tid]);
    {
        const float4* wr = (const float4*)(Wm + tid*CH);
        const float4* ar = (const float4*)sa;
        #pragma unroll 8
        for (int k = 0; k < 32; k++) {
            float4 w = __ldg(&wr[k]);
            float4 a4 = ar[k];
            m += w.x*a4.x + w.y*a4.y + w.z*a4.z + w.w*a4.w;
        }
    }
    g_xf[t*CH + tid] = x2 + m;
}

// ==================== K4: LM head GEMM ====================
// D[4096,50257] = Xf[4096,128] @ Wlm[50257,128]^T  (both K-major)
// 512 threads/CTA (16 warps) to hide the LDG/TMEM/smem latency chains.

#if defined(__CUDA_ARCH__) && (__CUDA_ARCH__ == 1030) && defined(__CUDA_ARCH_FEAT_SM103_ALL)
#define HAS_TCGEN05 1
#else
#define HAS_TCGEN05 0
#endif

__device__ __forceinline__ uint32_t s2u(const void* p) {
    uint32_t a;
    asm("{ .reg .u64 t; cvta.to.shared.u64 t, %1; cvt.u32.u64 %0, t; }" : "=r"(a) : "l"(p));
    return a;
}

#define K4T 512
#define SMA 0
#define SMB 65536
#define SCR 131072
#define K4_SMEM 196608   // 64K A + 64K B + 64K epilogue scratch

#if HAS_TCGEN05

__device__ __forceinline__ uint32_t f2tf(float f) {
    uint32_t r; asm("cvt.rna.tf32.f32 %0, %1;" : "=r"(r) : "f"(f)); return r;
}
__device__ __forceinline__ bool elect1() {
    uint32_t p;
    asm volatile("{ .reg .pred p; elect.sync _|p, 0xFFFFFFFF; selp.b32 %0, 1, 0, p; }" : "=r"(p));
    return p != 0;
}
__device__ __forceinline__ void mbar_init(uint32_t a, uint32_t cnt) {
    asm volatile("mbarrier.init.shared.b64 [%0], %1;" :: "r"(a), "r"(cnt) : "memory");
}
__device__ __forceinline__ void mbar_wait(uint32_t a, uint32_t ph) {
    asm volatile(
        "{\n\t.reg .pred P;\n"
        "W_%=:\n\t"
        "mbarrier.try_wait.parity.acquire.cta.shared::cta.b64 P, [%0], %1, 0x989680;\n\t"
        "@P bra D_%=;\n\t"
        "bra W_%=;\n"
        "D_%=:\n\t}"
        :: "r"(a), "r"(ph) : "memory");
}
__device__ __forceinline__ void sts128(uint32_t a, uint32_t r0, uint32_t r1, uint32_t r2, uint32_t r3) {
    asm volatile("st.shared.v4.b32 [%0], {%1, %2, %3, %4};" :: "r"(a), "r"(r0), "r"(r1), "r"(r2), "r"(r3) : "memory");
}
__device__ __forceinline__ void mma_tf32(uint32_t d, uint64_t ad, uint64_t bd, uint32_t idesc, bool accum) {
    uint32_t en = accum ? 1u : 0u;
    asm volatile(
        "{\n\t.reg .pred p;\n\t"
        "setp.ne.u32 p, %5, 0;\n\t"
        "tcgen05.mma.cta_group::1.kind::tf32 [%0], %1, %2, %3, {%4, %4, %4, %4}, p;\n\t}"
        :: "r"(d), "l"(ad), "l"(bd), "r"(idesc), "r"(0u), "r"(en) : "memory");
}
__device__ __forceinline__ void mma_commit(uint32_t mbar) {
    asm volatile("tcgen05.commit.cta_group::1.mbarrier::arrive::one.shared::cluster.b64 [%0];" :: "r"(mbar) : "memory");
}
// SW128 K-major smem descriptor: layout=2, version=1, SBO=64, LBO=1
__device__ __forceinline__ uint64_t mk_desc(uint32_t addr) {
    const uint64_t base = (uint64_t(2) << 61) | (uint64_t(1) << 46) | (uint64_t(64) << 32) | (uint64_t(1) << 16);
    return base | ((uint64_t)(addr >> 4) & 0x3FFF);
}

#define LDTM32(r, a) \
    asm volatile( \
        "tcgen05.ld.sync.aligned.32x32b.x32.b32 " \
        "{%0, %1, %2, %3, %4, %5, %6, %7, " \
        " %8, %9, %10, %11, %12, %13, %14, %15, " \
        " %16, %17, %18, %19, %20, %21, %22, %23, " \
        " %24, %25, %26, %27, %28, %29, %30, %31}, [%32];" \
        : "=r"((r)[0]),  "=r"((r)[1]),  "=r"((r)[2]),  "=r"((r)[3]), \
          "=r"((r)[4]),  "=r"((r)[5]),  "=r"((r)[6]),  "=r"((r)[7]), \
          "=r"((r)[8]),  "=r"((r)[9]),  "=r"((r)[10]), "=r"((r)[11]), \
          "=r"((r)[12]), "=r"((r)[13]), "=r"((r)[14]), "=r"((r)[15]), \
          "=r"((r)[16]), "=r"((r)[17]), "=r"((r)[18]), "=r"((r)[19]), \
          "=r"((r)[20]), "=r"((r)[21]), "=r"((r)[22]), "=r"((r)[23]), \
          "=r"((r)[24]), "=r"((r)[25]), "=r"((r)[26]), "=r"((r)[27]), \
          "=r"((r)[28]), "=r"((r)[29]), "=r"((r)[30]), "=r"((r)[31]) \
        : "r"(a))

// idesc: dtype=F32(1<<4), atype=TF32(2<<7), btype=TF32(2<<10), N=128(16<<17), M=128(8<<24)
#define K4_IDESC ((1u<<4) | (2u<<7) | (2u<<10) | (16u<<17) | (8u<<24))

__device__ __forceinline__ void k4_load_tile(const float* __restrict__ src, uint32_t sdst,
                                             int row0, int rowmax, int tid)
{
    // 128 rows x 128 cols f32 -> 4 K-chunks of [128 x 32] SW128-swizzled tf32
    #pragma unroll
    for (int it = 0; it < 8; it++) {
        int f = tid + it * K4T;          // float4 index, 0..4095
        int r = f >> 5, q = f & 31;
        int kc = q >> 3, c4 = q & 7;
        float4 v = make_float4(0.f, 0.f, 0.f, 0.f);
        if (row0 + r < rowmax)
            v = *(const float4*)&src[(size_t)(row0 + r) * CH + q * 4];
        uint32_t off = (uint32_t)(kc * 16384 + r * 128 + c4 * 16);
        off = off ^ ((off >> 3) & 0x70);
        sts128(sdst + off, f2tf(v.x), f2tf(v.y), f2tf(v.z), f2tf(v.w));
    }
}

// Epilogue v5 (16 warps): single LDTM round — warp group (wid>>2) covers one
// 32-col slab for its subpartition rows — into a 64KB [128x128] scratch with
// float4-group XOR swizzle; then each warp streams 8 rows out with aligned
// float4 STG (c0 = (-m) mod 4 fixup).
__device__ __forceinline__ void k4_epilogue(uint32_t dt, float* __restrict__ scr,
                                            int m0, int n0,
                                            float* __restrict__ out, int tid)
{
    int wid = tid >> 5, lid = tid & 31;
    int row = (wid & 3) * 32 + lid;    // TMEM lane -> D row
    int cb  = (wid >> 2) * 32;         // 32-col slab for this warp group
    uint32_t scr_u = s2u(scr);

    // phase 1: TMEM -> scratch
    {
        uint32_t r[32];
        LDTM32(r, dt + cb);
        asm volatile("tcgen05.wait::ld.sync.aligned;" ::: "memory");
        #pragma unroll
        for (int gq = 0; gq < 8; gq++) {
            int cg = (cb >> 2) + gq;             // float4 col-group 0..31
            int sg = cg ^ (row & 31);
            sts128(scr_u + (uint32_t)(row * 128 + sg * 4) * 4,
                   r[4*gq], r[4*gq+1], r[4*gq+2], r[4*gq+3]);
        }
    }
    __syncthreads();

    // phase 2: scratch -> gmem, warp w -> rows w*8..w*8+7
    if (n0 + 128 <= VSZ) {
        #pragma unroll
        for (int itr = 0; itr < 8; itr++) {
            int r2 = wid * 8 + itr;
            int m  = m0 + r2;
            int c0 = (4 - (m & 3)) & 3;    // (m*VSZ + n0 + c0) % 4 == 0
            int sw = r2 & 31;
            float* orow = out + (size_t)m * VSZ + n0;
            int j = c0 + 4 * lid;
            if (j + 3 < 128) {
                float4 v;
                float* vp = &v.x;
                #pragma unroll
                for (int k = 0; k < 4; k++) {
                    int col = j + k;
                    int sg2 = (col >> 2) ^ sw;
                    vp[k] = scr[r2 * 128 + sg2 * 4 + (col & 3)];
                }
                *(float4*)(orow + j) = v;   // provably 16B-aligned
            }
            if (c0 && lid < 4) {            // 4 leftover columns, scalar
                int col = (lid < c0) ? lid : (c0 + 124 + (lid - c0));
                int sg2 = (col >> 2) ^ sw;
                orow[col] = scr[r2 * 128 + sg2 * 4 + (col & 3)];
            }
        }
    } else {
        // vocab edge tile: scalar bounds-checked
        for (int itr = 0; itr < 8; itr++) {
            int r2 = wid * 8 + itr;
            int sw = r2 & 31;
            float* orow = out + (size_t)(m0 + r2) * VSZ;
            #pragma unroll
            for (int k = 0; k < 4; k++) {
                int col = lid + 32 * k;
                if (n0 + col < VSZ) {
                    int sg2 = (col >> 2) ^ sw;
                    orow[n0 + col] = scr[r2 * 128 + sg2 * 4 + (col & 3)];
                }
            }
        }
    }
}
#endif  // HAS_TCGEN05

__global__ void __launch_bounds__(K4T, 1) k4mma(const float* __restrict__ Wlm,
                                                float* __restrict__ out)
{
    extern __shared__ __align__(1024) char smem[];
    int tid = threadIdx.x;
    int m0 = blockIdx.x * 128;
    int g  = blockIdx.y;              // N-group 0..3, tiles jt = g, g+4, ...
    int nt = (NTILES - 1 - g) / 4 + 1;

#if HAS_TCGEN05
    __shared__ __align__(16) unsigned long long s_mbar[2];
    __shared__ uint32_t s_tmem;

    int wid = tid >> 5;
    uint32_t sb = s2u(smem);
    float* scr = (float*)(smem + SCR);
    uint32_t mb[2] = { s2u(&s_mbar[0]), s2u(&s_mbar[1]) };

    if (wid == 0) {
        asm volatile("tcgen05.alloc.cta_group::1.sync.aligned.shared::cta.b32 [%0], %1;"
                     :: "r"(s2u(&s_tmem)), "r"(256u) : "memory");
        asm volatile("tcgen05.relinquish_alloc_permit.cta_group::1.sync.aligned;");
    }
    if (tid == 0) { mbar_init(mb[0], 1); mbar_init(mb[1], 1); }
    __syncthreads();
    uint32_t tmem;
    asm volatile("ld.shared.b32 %0, [%1];" : "=r"(tmem) : "r"(s2u(&s_tmem)));

    // prologue: A tile (once) + B(0)
    k4_load_tile(g_xf, sb + SMA, m0, TNUM, tid);
    k4_load_tile(Wlm, sb + SMB, g * 128, VSZ, tid);
    asm volatile("fence.proxy.async.shared::cta;" ::: "memory");
    __syncthreads();

    uint64_t adesc = mk_desc(sb + SMA);
    uint64_t bdesc = mk_desc(sb + SMB);
    int ph[2] = {0, 0};

    for (int i = 0; i < nt; i++) {
        int b = i & 1;

        // 1. issue MMA(i) from the (resident, synced) B buffer into TMEM[b]
        if (wid == 0 && elect1()) {
            uint32_t dreg = tmem + (uint32_t)(b * 128);
            #pragma unroll
            for (int s = 0; s < 16; s++) {
                uint64_t koff = (uint64_t)((s >> 2) * 1024 + (s & 3) * 2);
                mma_tf32(dreg, adesc + koff, bdesc + koff, K4_IDESC, s > 0);
            }
            mma_commit(mb[b]);
        }

        // 2. epilogue(i-1) overlaps MMA(i)  (TMEM[b^1], done since last iter)
        if (i >= 1)
            k4_epilogue(tmem + (b ^ 1) * 128, scr, m0, (g + 4 * (i - 1)) * 128, out, tid);

        // 3. wait MMA(i) -> B buffer free, TMEM[b] valid for next-iter epilogue
        mbar_wait(mb[b], ph[b]); ph[b] ^= 1;
        asm volatile("tcgen05.fence::after_thread_sync;" ::: "memory");

        // 4. refill B with tile i+1
        if (i + 1 < nt) {
            k4_load_tile(Wlm, sb + SMB, (g + 4 * (i + 1)) * 128, VSZ, tid);
            asm volatile("fence.proxy.async.shared::cta;" ::: "memory");
        }
        __syncthreads();
    }

    // final tile epilogue
    k4_epilogue(tmem + ((nt - 1) & 1) * 128, scr, m0, (g + 4 * (nt - 1)) * 128, out, tid);

    __syncthreads();
    if (wid == 0) {
        asm volatile("tcgen05.dealloc.cta_group::1.sync.aligned.b32 %0, %1;"
                     :: "r"(tmem), "r"(256u));
    }
#else
    // -------- fallback: plain fp32 smem GEMM (baseline sm_103 target) --------
    float* sA = (float*)(smem + SMA);     // [128][128]
    float* sB = (float*)(smem + SMB);     // [128][128]

    for (int i = tid; i < 128 * 32; i += K4T) {
        int r = i >> 5, q = i & 31;
        *(float4*)&sA[r * 128 + q * 4] = *(const float4*)&g_xf[(size_t)(m0 + r) * CH + q * 4];
    }

    int tx = tid & 31, ty = tid >> 5;   // 32 x 16 threads, 8x4 outputs each

    for (int t = 0; t < nt; t++) {
        int n0 = (g + 4 * t) * 128;
        __syncthreads();
        for (int i = tid; i < 128 * 32; i += K4T) {
            int r = i >> 5, q = i & 31;
            float4 v = make_float4(0.f, 0.f, 0.f, 0.f);
            if (n0 + r < VSZ)
                v = *(const float4*)&Wlm[(size_t)(n0 + r) * CH + q * 4];
            *(float4*)&sB[r * 128 + q * 4] = v;
        }
        __syncthreads();

        float acc[8][4];
        #pragma unroll
        for (int i = 0; i < 8; i++)
            #pragma unroll
            for (int j = 0; j < 4; j++) acc[i][j] = 0.f;

        for (int k = 0; k < 128; k++) {
            float a[8], b[4];
            #pragma unroll
            for (int i = 0; i < 8; i++) a[i] = sA[(ty * 8 + i) * 128 + k];
            #pragma unroll
            for (int j = 0; j < 4; j++) b[j] = sB[(tx * 4 + j) * 128 + k];
            #pragma unroll
            for (int i = 0; i < 8; i++)
                #pragma unroll
                for (int j = 0; j < 4; j++) acc[i][j] += a[i] * b[j];
        }

        #pragma unroll
        for (int i = 0; i < 8; i++) {
            float* row = out + (size_t)(m0 + ty * 8 + i) * VSZ;
            #pragma unroll
            for (int j = 0; j < 4; j++) {
                int n = n0 + tx * 4 + j;
                if (n < VSZ) row[n] = acc[i][j];
            }
        }
    }
#endif
}

// ==================== launch ====================
extern "C" void kernel_launch(void* const* d_in, const int* in_sizes, int n_in,
                              void* d_out, int out_size)
{
    const int*   ids    = (const int*)  d_in[0];
    const float* emb    = (const float*)d_in[1];
    const float* router = (const float*)d_in[2];
    const float* kexp   = (const float*)d_in[3];
    const float* vexp   = (const float*)d_in[4];
    const float* skv    = (const float*)d_in[5];
    const float* svv    = (const float*)d_in[6];
    const float* kvg    = (const float*)d_in[7];
    const float* Wq     = (const float*)d_in[8];
    const float* Wo     = (const float*)d_in[9];
    const float* Wm     = (const float*)d_in[10];
    const float* bm     = (const float*)d_in[11];
    const float* g1     = (const float*)d_in[12];
    const float* b1     = (const float*)d_in[13];
    const float* g2     = (const float*)d_in[14];
    const float* b2     = (const float*)d_in[15];
    const float* Wlm    = (const float*)d_in[16];

    float* out = (float*)d_out;
    float* gate_out = out + ((size_t)out_size - (size_t)TNUM * NE);

    cudaFuncSetAttribute(k4mma, cudaFuncAttributeMaxDynamicSharedMemorySize, K4_SMEM);

    k1<<<TNUM, 128>>>(ids, emb, router, Wq, g1, b1, gate_out);
    k2<<<TNUM/TB, 256>>>(kexp, vexp, skv, svv, kvg);
    k3<<<TNUM, 128>>>(Wo, Wm, bm, g2, b2);
    dim3 g4(TNUM/128, 4);
    k4mma<<<g4, K4T, K4_SMEM>>>(Wlm, out);
}

// round 9
// speedup vs baseline: 1.1045x; 1.0470x over previous
#include <cuda_runtime.h>
#include <math.h>
#include <stdint.h>

#define TNUM 4096
#define CH 128
#define NE 16
#define KB 32
#define VSZ 50257
#define NTILES 393   // ceil(50257/128)

// scratch (static device arrays — no allocation)
__device__ float g_x [TNUM*CH];
__device__ float g_q [TNUM*CH];
__device__ float g_rw[TNUM*NE];
__device__ float g_ao[TNUM*CH];
__device__ float g_xf[TNUM*CH];

// ---------------- block reduce over 128 threads ----------------
__device__ __forceinline__ float blockReduce128(float v, float* sred, int tid) {
    #pragma unroll
    for (int o = 16; o; o >>= 1) v += __shfl_down_sync(0xffffffffu, v, o);
    if ((tid & 31) == 0) sred[tid >> 5] = v;
    __syncthreads();
    return sred[0] + sred[1] + sred[2] + sred[3];
}

// ==================== K1: embed + LN1 + routing + q ====================
__global__ __launch_bounds__(128) void k1(const int* __restrict__ ids,
        const float* __restrict__ emb, const float* __restrict__ router,
        const float* __restrict__ Wq, const float* __restrict__ g1,
        const float* __restrict__ b1, float* __restrict__ gate_out)
{
    int t = blockIdx.x, tid = threadIdx.x;
    __shared__ float sx[CH];
    __shared__ float sred[4];
    __shared__ float sgl[NE];

    int id = ids[t];
    float xv = __ldg(&emb[(long long)id * CH + tid]);
    g_x[t*CH + tid] = xv;

    float mu = blockReduce128(xv, sred, tid) * (1.f/CH);
    __syncthreads();
    float d  = xv - mu;
    float var = blockReduce128(d*d, sred, tid) * (1.f/CH);
    float xln = d * rsqrtf(var + 1e-5f) * g1[tid] + b1[tid];
    sx[tid] = xln;
    __syncthreads();

    int e = tid >> 3, l = tid & 7;
    float gl = 0.f;
    #pragma unroll 4
    for (int k = l; k < CH; k += 8) gl += sx[k] * __ldg(&router[e*CH + k]);
    #pragma unroll
    for (int o = 4; o; o >>= 1) gl += __shfl_xor_sync(0xffffffffu, gl, o, 8);
    if (l == 0) sgl[e] = gl;
    __syncthreads();

    if (tid < NE) gate_out[(long long)t*NE + tid] = sgl[tid];

    float mx = -1e30f;
    #pragma unroll
    for (int i = 0; i < NE; i++) mx = fmaxf(mx, sgl[i]);
    float ss = 0.f;
    #pragma unroll
    for (int i = 0; i < NE; i++) ss += __expf(sgl[i] - mx);
    if (tid < NE) g_rw[t*NE + tid] = __expf(sgl[tid] - mx) / ss;

    float acc = 0.f;
    const float4* wr = (const float4*)(Wq + tid*CH);
    const float4* xr = (const float4*)sx;
    #pragma unroll 8
    for (int k = 0; k < 32; k++) {
        float4 w = __ldg(&wr[k]);
        float4 x4 = xr[k];
        acc += w.x*x4.x + w.y*x4.y + w.z*x4.z + w.w*x4.w;
    }
    g_q[t*CH + tid] = acc;
}

// ==================== K2: expert attention ====================
#define TB 32
#define QSTR 132
__global__ __launch_bounds__(256) void k2(const float* __restrict__ kexp,
        const float* __restrict__ vexp, const float* __restrict__ skv,
        const float* __restrict__ svv, const float* __restrict__ kvg)
{
    __shared__ float sQ[TB*QSTR];
    __shared__ float sT[KB*QSTR];
    __shared__ float sS[TB][KB+1];
    __shared__ float sRW[TB*NE];

    int t0 = blockIdx.x * TB;
    int tid = threadIdx.x;
    float g = 1.f / (1.f + __expf(-kvg[0]));

    for (int i = tid; i < TB*CH; i += 256) {
        int tt = i >> 7, cc = i & 127;
        sQ[tt*QSTR + cc] = g_q[(t0+tt)*CH + cc];
    }
    for (int i = tid; i < TB*NE; i += 256) sRW[i] = g_rw[t0*NE + i];

    int t = tid >> 3, kg = tid & 7;
    float sdyn[4] = {0,0,0,0}, sstat[4];

    for (int e = 0; e < NE; e++) {
        __syncthreads();
        for (int i = tid; i < KB*CH; i += 256) {
            int kk = i >> 7, cc = i & 127;
            sT[kk*QSTR + cc] = __ldg(&kexp[e*KB*CH + i]);
        }
        __syncthreads();
        float rwv = sRW[t*NE + e];
        float dj[4] = {0,0,0,0};
        const float4* qp = (const float4*)(sQ + t*QSTR);
        #pragma unroll 4
        for (int c4 = 0; c4 < 32; c4++) {
            float4 qv = qp[c4];
            #pragma unroll
            for (int j = 0; j < 4; j++) {
                int k = kg + 8*j;
                float4 kv = *(const float4*)(sT + k*QSTR + 4*c4);
                dj[j] += qv.x*kv.x + qv.y*kv.y + qv.z*kv.z + qv.w*kv.w;
            }
        }
        #pragma unroll
        for (int j = 0; j < 4; j++) sdyn[j] += rwv * dj[j];
    }
    __syncthreads();
    for (int i = tid; i < KB*CH; i += 256) {
        int kk = i >> 7, cc = i & 127;
        sT[kk*QSTR + cc] = __ldg(&skv[i]);
    }
    __syncthreads();
    {
        float dj[4] = {0,0,0,0};
        const float4* qp = (const float4*)(sQ + t*QSTR);
        #pragma unroll 4
        for (int c4 = 0; c4 < 32; c4++) {
            float4 qv = qp[c4];
            #pragma unroll
            for (int j = 0; j < 4; j++) {
                int k = kg + 8*j;
                float4 kv = *(const float4*)(sT + k*QSTR + 4*c4);
                dj[j] += qv.x*kv.x + qv.y*kv.y + qv.z*kv.z + qv.w*kv.w;
            }
        }
        #pragma unroll
        for (int j = 0; j < 4; j++) sstat[j] = dj[j];
    }
    const float scale = 0.08838834764831845f;
    #pragma unroll
    for (int j = 0; j < 4; j++)
        sS[t][kg + 8*j] = (g*sdyn[j] + (1.f-g)*sstat[j]) * scale;
    __syncthreads();

    if (tid < TB) {
        float mx = -1e30f;
        #pragma unroll
        for (int k = 0; k < KB; k++) mx = fmaxf(mx, sS[tid][k]);
        float ssum = 0.f;
        #pragma unroll
        for (int k = 0; k < KB; k++) { float ev = __expf(sS[tid][k] - mx); sS[tid][k] = ev; ssum += ev; }
        float inv = 1.f / ssum;
        #pragma unroll
        for (int k = 0; k < KB; k++) sS[tid][k] *= inv;
    }

    float acc[16];
    #pragma unroll
    for (int i = 0; i < 16; i++) acc[i] = 0.f;

    for (int e = 0; e < NE; e++) {
        __syncthreads();
        for (int i = tid; i < KB*CH; i += 256) {
            int kk = i >> 7, cc = i & 127;
            sT[kk*QSTR + cc] = __ldg(&vexp[e*KB*CH + i]);
        }
        __syncthreads();
        float we = g * sRW[t*NE + e];
        #pragma unroll 4
        for (int k = 0; k < KB; k++) {
            float w = we * sS[t][k];
            #pragma unroll
            for (int j = 0; j < 4; j++) {
                float4 vv = *(const float4*)(sT + k*QSTR + 4*(kg + 8*j));
                acc[j*4+0] += w*vv.x; acc[j*4+1] += w*vv.y;
                acc[j*4+2] += w*vv.z; acc[j*4+3] += w*vv.w;
            }
        }
    }
    __syncthreads();
    for (int i = tid; i < KB*CH; i += 256) {
        int kk = i >> 7, cc = i & 127;
        sT[kk*QSTR + cc] = __ldg(&svv[i]);
    }
    __syncthreads();
    {
        float we = 1.f - g;
        #pragma unroll 4
        for (int k = 0; k < KB; k++) {
            float w = we * sS[t][k];
            #pragma unroll
            for (int j = 0; j < 4; j++) {
                float4 vv = *(const float4*)(sT + k*QSTR + 4*(kg + 8*j));
                acc[j*4+0] += w*vv.x; acc[j*4+1] += w*vv.y;
                acc[j*4+2] += w*vv.z; acc[j*4+3] += w*vv.w;
            }
        }
    }
    #pragma unroll
    for (int j = 0; j < 4; j++) {
        float4 o;
        o.x = acc[j*4+0]; o.y = acc[j*4+1]; o.z = acc[j*4+2]; o.w = acc[j*4+3];
        *(float4*)&g_ao[(t0+t)*CH + 4*(kg + 8*j)] = o;
    }
}

// ==================== K3: Wo + residual + LN2 + MLP + residual ====================
__global__ __launch_bounds__(128) void k3(const float* __restrict__ Wo,
        const float* __restrict__ Wm, const float* __restrict__ bm,
        const float* __restrict__ g2, const float* __restrict__ b2)
{
    int t = blockIdx.x, tid = threadIdx.x;
    __shared__ float sa[CH];
    __shared__ float sred[4];

    sa[tid] = g_ao[t*CH + tid];
    __syncthreads();

    float o = 0.f;
    {
        const float4* wr = (const float4*)(Wo + tid*CH);
        const float4* ar = (const float4*)sa;
        #pragma unroll 8
        for (int k = 0; k < 32; k++) {
            float4 w = __ldg(&wr[k]);
            float4 a4 = ar[k];
            o += w.x*a4.x + w.y*a4.y + w.z*a4.z + w.w*a4.w;
        }
    }
    float x2 = g_x[t*CH + tid] + o;

    __syncthreads();
    float mu = blockReduce128(x2, sred, tid) * (1.f/CH);
    __syncthreads();
    float d = x2 - mu;
    float var = blockReduce128(d*d, sred, tid) * (1.f/CH);
    float xln = d * rsqrtf(var + 1e-5f) * g2[tid] + b2[tid];
    __syncthreads();
    sa[tid] = xln;
    __syncthreads();

    float m = __ldg(&bm[tid]);
    {
        const float4* wr = (const float4*)(Wm + tid*CH);
        const float4* ar = (const float4*)sa;
        #pragma unroll 8
        for (int k = 0; k < 32; k++) {
            float4 w = __ldg(&wr[k]);
            float4 a4 = ar[k];
            m += w.x*a4.x + w.y*a4.y + w.z*a4.z + w.w*a4.w;
        }
    }
    g_xf[t*CH + tid] = x2 + m;
}

// ==================== K4: LM head GEMM (warp-specialized) ====================
// D[4096,50257] = Xf[4096,128] @ Wlm[50257,128]^T  (both K-major)
// 512 threads: warps 0-7 = MMA issue + epilogue; warps 8-15 = B producer.
// A lives in TMEM (TS-mode MMA) -> smem holds two B buffers + epilogue scratch.

#if defined(__CUDA_ARCH__) && (__CUDA_ARCH__ == 1030) && defined(__CUDA_ARCH_FEAT_SM103_ALL)
#define HAS_TCGEN05 1
#else
#define HAS_TCGEN05 0
#endif

__device__ __forceinline__ uint32_t s2u(const void* p) {
    uint32_t a;
    asm("{ .reg .u64 t; cvta.to.shared.u64 t, %1; cvt.u32.u64 %0, t; }" : "=r"(a) : "l"(p));
    return a;
}

#define K4T 512
#define SMB0 0
#define SMB1 65536
#define SCR  131072
#define K4_SMEM 196608   // 2x64K B buffers + 64K epilogue scratch

// TMEM layout (512 cols): D0 @0, D1 @128, A @256 (128 cols, 1 tf32/col)
#define TM_D0 0
#define TM_D1 128
#define TM_A  256

#if HAS_TCGEN05

__device__ __forceinline__ uint32_t f2tf(float f) {
    uint32_t r; asm("cvt.rna.tf32.f32 %0, %1;" : "=r"(r) : "f"(f)); return r;
}
__device__ __forceinline__ bool elect1() {
    uint32_t p;
    asm volatile("{ .reg .pred p; elect.sync _|p, 0xFFFFFFFF; selp.b32 %0, 1, 0, p; }" : "=r"(p));
    return p != 0;
}
__device__ __forceinline__ void mbar_init(uint32_t a, uint32_t cnt) {
    asm volatile("mbarrier.init.shared.b64 [%0], %1;" :: "r"(a), "r"(cnt) : "memory");
}
__device__ __forceinline__ void mbar_wait(uint32_t a, uint32_t ph) {
    asm volatile(
        "{\n\t.reg .pred P;\n"
        "W_%=:\n\t"
        "mbarrier.try_wait.parity.acquire.cta.shared::cta.b64 P, [%0], %1, 0x989680;\n\t"
        "@P bra D_%=;\n\t"
        "bra W_%=;\n"
        "D_%=:\n\t}"
        :: "r"(a), "r"(ph) : "memory");
}
__device__ __forceinline__ void sts128(uint32_t a, uint32_t r0, uint32_t r1, uint32_t r2, uint32_t r3) {
    asm volatile("st.shared.v4.b32 [%0], {%1, %2, %3, %4};" :: "r"(a), "r"(r0), "r"(r1), "r"(r2), "r"(r3) : "memory");
}
// TS-mode tf32 MMA: A in TMEM, B via smem descriptor
__device__ __forceinline__ void mma_tf32_ts(uint32_t d, uint32_t a, uint64_t bd, uint32_t idesc, bool accum) {
    uint32_t en = accum ? 1u : 0u;
    asm volatile(
        "{\n\t.reg .pred p;\n\t"
        "setp.ne.u32 p, %5, 0;\n\t"
        "tcgen05.mma.cta_group::1.kind::tf32 [%0], [%1], %2, %3, {%4, %4, %4, %4}, p;\n\t}"
        :: "r"(d), "r"(a), "l"(bd), "r"(idesc), "r"(0u), "r"(en) : "memory");
}
__device__ __forceinline__ void mma_commit(uint32_t mbar) {
    asm volatile("tcgen05.commit.cta_group::1.mbarrier::arrive::one.shared::cluster.b64 [%0];" :: "r"(mbar) : "memory");
}
// SW128 K-major smem descriptor: layout=2, version=1, SBO=64, LBO=1
__device__ __forceinline__ uint64_t mk_desc(uint32_t addr) {
    const uint64_t base = (uint64_t(2) << 61) | (uint64_t(1) << 46) | (uint64_t(64) << 32) | (uint64_t(1) << 16);
    return base | ((uint64_t)(addr >> 4) & 0x3FFF);
}

#define LDTM32(r, a) \
    asm volatile( \
        "tcgen05.ld.sync.aligned.32x32b.x32.b32 " \
        "{%0, %1, %2, %3, %4, %5, %6, %7, " \
        " %8, %9, %10, %11, %12, %13, %14, %15, " \
        " %16, %17, %18, %19, %20, %21, %22, %23, " \
        " %24, %25, %26, %27, %28, %29, %30, %31}, [%32];" \
        : "=r"((r)[0]),  "=r"((r)[1]),  "=r"((r)[2]),  "=r"((r)[3]), \
          "=r"((r)[4]),  "=r"((r)[5]),  "=r"((r)[6]),  "=r"((r)[7]), \
          "=r"((r)[8]),  "=r"((r)[9]),  "=r"((r)[10]), "=r"((r)[11]), \
          "=r"((r)[12]), "=r"((r)[13]), "=r"((r)[14]), "=r"((r)[15]), \
          "=r"((r)[16]), "=r"((r)[17]), "=r"((r)[18]), "=r"((r)[19]), \
          "=r"((r)[20]), "=r"((r)[21]), "=r"((r)[22]), "=r"((r)[23]), \
          "=r"((r)[24]), "=r"((r)[25]), "=r"((r)[26]), "=r"((r)[27]), \
          "=r"((r)[28]), "=r"((r)[29]), "=r"((r)[30]), "=r"((r)[31]) \
        : "r"(a))

#define STTM32(a, r) \
    asm volatile( \
        "tcgen05.st.sync.aligned.32x32b.x32.b32 [%0], " \
        "{%1, %2, %3, %4, %5, %6, %7, %8, " \
        " %9, %10, %11, %12, %13, %14, %15, %16, " \
        " %17, %18, %19, %20, %21, %22, %23, %24, " \
        " %25, %26, %27, %28, %29, %30, %31, %32};" \
        :: "r"(a), \
           "r"((r)[0]),  "r"((r)[1]),  "r"((r)[2]),  "r"((r)[3]), \
           "r"((r)[4]),  "r"((r)[5]),  "r"((r)[6]),  "r"((r)[7]), \
           "r"((r)[8]),  "r"((r)[9]),  "r"((r)[10]), "r"((r)[11]), \
           "r"((r)[12]), "r"((r)[13]), "r"((r)[14]), "r"((r)[15]), \
           "r"((r)[16]), "r"((r)[17]), "r"((r)[18]), "r"((r)[19]), \
           "r"((r)[20]), "r"((r)[21]), "r"((r)[22]), "r"((r)[23]), \
           "r"((r)[24]), "r"((r)[25]), "r"((r)[26]), "r"((r)[27]), \
           "r"((r)[28]), "r"((r)[29]), "r"((r)[30]), "r"((r)[31]) \
        : "memory")

// idesc: dtype=F32(1<<4), atype=TF32(2<<7), btype=TF32(2<<10), N=128(16<<17), M=128(8<<24)
#define K4_IDESC ((1u<<4) | (2u<<7) | (2u<<10) | (16u<<17) | (8u<<24))

// producer half (256 threads): fp32 rows -> SW128-swizzled tf32 tile
__device__ __forceinline__ void k4_load_tile_p(const float* __restrict__ src, uint32_t sdst,
                                               int row0, int rowmax, int ltid)
{
    #pragma unroll
    for (int it = 0; it < 16; it++) {
        int f = ltid + it * 256;         // float4 index, 0..4095
        int r = f >> 5, q = f & 31;
        int kc = q >> 3, c4 = q & 7;
        float4 v = make_float4(0.f, 0.f, 0.f, 0.f);
        if (row0 + r < rowmax)
            v = *(const float4*)&src[(size_t)(row0 + r) * CH + q * 4];
        uint32_t off = (uint32_t)(kc * 16384 + r * 128 + c4 * 16);
        off = off ^ ((off >> 3) & 0x70);
        sts128(sdst + off, f2tf(v.x), f2tf(v.y), f2tf(v.z), f2tf(v.w));
    }
}

// epilogue (warps 0-7): LDTM D -> 64KB swizzled scratch -> aligned float4 STG
__device__ __forceinline__ void k4_epilogue(uint32_t dt, float* __restrict__ scr,
                                            int m0, int n0,
                                            float* __restrict__ out, int tid)
{
    int w = tid >> 5, lid = tid & 31;    // w in 0..7
    int row = (w & 3) * 32 + lid;        // TMEM lane -> D row
    int cb  = (w >> 2) * 64;             // 64-col slab per warp quad
    uint32_t scr_u = s2u(scr);

    // phase 1: TMEM -> scratch (two x32 LDTM per warp)
    #pragma unroll
    for (int h = 0; h < 2; h++) {
        uint32_t r[32];
        LDTM32(r, dt + cb + h * 32);
        asm volatile("tcgen05.wait::ld.sync.aligned;" ::: "memory");
        #pragma unroll
        for (int gq = 0; gq < 8; gq++) {
            int cg = ((cb + h * 32) >> 2) + gq;   // float4 col-group 0..31
            int sg = cg ^ (row & 31);
            sts128(scr_u + (uint32_t)(row * 128 + sg * 4) * 4,
                   r[4*gq], r[4*gq+1], r[4*gq+2], r[4*gq+3]);
        }
    }
    asm volatile("bar.sync 1, 256;" ::: "memory");   // epi group only

    // phase 2: scratch -> gmem, warp w -> rows w*16..w*16+15
    if (n0 + 128 <= VSZ) {
        #pragma unroll 4
        for (int itr = 0; itr < 16; itr++) {
            int r2 = w * 16 + itr;
            int m  = m0 + r2;
            int c0 = (4 - (m & 3)) & 3;    // (m*VSZ + n0 + c0) % 4 == 0
            int sw = r2 & 31;
            float* orow = out + (size_t)m * VSZ + n0;
            int j = c0 + 4 * lid;
            if (j + 3 < 128) {
                float4 v;
                float* vp = &v.x;
                #pragma unroll
                for (int k = 0; k < 4; k++) {
                    int col = j + k;
                    int sg2 = (col >> 2) ^ sw;
                    vp[k] = scr[r2 * 128 + sg2 * 4 + (col & 3)];
                }
                *(float4*)(orow + j) = v;   // provably 16B-aligned
            }
            if (c0 && lid < 4) {            // 4 leftover columns, scalar
                int col = (lid < c0) ? lid : (c0 + 124 + (lid - c0));
                int sg2 = (col >> 2) ^ sw;
                orow[col] = scr[r2 * 128 + sg2 * 4 + (col & 3)];
            }
        }
    } else {
        for (int itr = 0; itr < 16; itr++) {
            int r2 = w * 16 + itr;
            int sw = r2 & 31;
            float* orow = out + (size_t)(m0 + r2) * VSZ;
            #pragma unroll
            for (int k = 0; k < 4; k++) {
                int col = lid + 32 * k;
                if (n0 + col < VSZ) {
                    int sg2 = (col >> 2) ^ sw;
                    orow[n0 + col] = scr[r2 * 128 + sg2 * 4 + (col & 3)];
                }
            }
        }
    }
}
#endif  // HAS_TCGEN05

__global__ void __launch_bounds__(K4T, 1) k4mma(const float* __restrict__ Wlm,
                                                float* __restrict__ out)
{
    extern __shared__ __align__(1024) char smem[];
    int tid = threadIdx.x;
    int m0 = blockIdx.x * 128;
    int g  = blockIdx.y;              // N-group 0..3, tiles jt = g, g+4, ...
    int nt = (NTILES - 1 - g) / 4 + 1;

#if HAS_TCGEN05
    __shared__ __align__(16) unsigned long long s_mbar[2];
    __shared__ uint32_t s_tmem;

    int wid = tid >> 5;
    uint32_t sb = s2u(smem);
    float* scr = (float*)(smem + SCR);
    uint32_t mb[2] = { s2u(&s_mbar[0]), s2u(&s_mbar[1]) };

    if (wid == 0) {
        asm volatile("tcgen05.alloc.cta_group::1.sync.aligned.shared::cta.b32 [%0], %1;"
                     :: "r"(s2u(&s_tmem)), "r"(512u) : "memory");
        asm volatile("tcgen05.relinquish_alloc_permit.cta_group::1.sync.aligned;");
    }
    if (tid == 0) { mbar_init(mb[0], 1); mbar_init(mb[1], 1); }
    __syncthreads();
    uint32_t tmem;
    asm volatile("ld.shared.b32 %0, [%1];" : "=r"(tmem) : "r"(s2u(&s_tmem)));

    // prologue: A -> TMEM (warps 0-3, one row per thread), B(0) -> smem (producers)
    if (tid < 128) {
        uint32_t warp_off = (uint32_t)(tid >> 5) << 21;
        const float* arow = &g_xf[(size_t)(m0 + tid) * CH];
        #pragma unroll
        for (int q = 0; q < 4; q++) {
            uint32_t ar[32];
            #pragma unroll
            for (int j = 0; j < 32; j++) ar[j] = f2tf(arow[q * 32 + j]);
            STTM32(tmem + TM_A + q * 32 + warp_off, ar);
        }
        asm volatile("tcgen05.wait::st.sync.aligned;" ::: "memory");
        asm volatile("tcgen05.fence::before_thread_sync;" ::: "memory");
    }
    if (wid >= 8) {
        k4_load_tile_p(Wlm, sb + SMB0, g * 128, VSZ, tid - 256);
        asm volatile("fence.proxy.async.shared::cta;" ::: "memory");
    }

    uint64_t bdesc[2] = { mk_desc(sb + SMB0), mk_desc(sb + SMB1) };
    int ph[2] = {0, 0};

    for (int i = 0; i < nt; i++) {
        int b = i & 1, pb = b ^ 1;

        __syncthreads();   // B(i) resident; epilogue(i-2) LDTMs retired; A ready

        // MMA(i): TS-mode, A in TMEM, into D[b]
        if (wid == 0 && elect1()) {
            asm volatile("tcgen05.fence::after_thread_sync;" ::: "memory");
            uint32_t dreg = tmem + (uint32_t)(b ? TM_D1 : TM_D0);
            #pragma unroll
            for (int s = 0; s < 16; s++) {
                uint64_t koff = (uint64_t)((s >> 2) * 1024 + (s & 3) * 2);
                mma_tf32_ts(dreg, tmem + TM_A + s * 8, bdesc[b] + koff, K4_IDESC, s > 0);
            }
            mma_commit(mb[b]);
        }

        if (i >= 1) {
            // both groups need MMA(i-1) done: epi reads D[pb], producers reuse B[pb]
            mbar_wait(mb[pb], ph[pb]); ph[pb] ^= 1;
            if (wid < 8) {
                asm volatile("tcgen05.fence::after_thread_sync;" ::: "memory");
                k4_epilogue(tmem + (pb ? TM_D1 : TM_D0), scr, m0,
                            (g + 4 * (i - 1)) * 128, out, tid);
            } else if (i + 1 < nt) {
                k4_load_tile_p(Wlm, sb + (pb ? SMB1 : SMB0),
                               (g + 4 * (i + 1)) * 128, VSZ, tid - 256);
                asm volatile("fence.proxy.async.shared::cta;" ::: "memory");
            }
        } else {
            if (wid >= 8 && nt > 1) {
                k4_load_tile_p(Wlm, sb + SMB1, (g + 4) * 128, VSZ, tid - 256);
                asm volatile("fence.proxy.async.shared::cta;" ::: "memory");
            }
        }
    }

    // final tile epilogue
    {
        int b = (nt - 1) & 1;
        mbar_wait(mb[b], ph[b]);
        if (wid < 8) {
            asm volatile("tcgen05.fence::after_thread_sync;" ::: "memory");
            k4_epilogue(tmem + (b ? TM_D1 : TM_D0), scr, m0,
                        (g + 4 * (nt - 1)) * 128, out, tid);
        }
    }

    __syncthreads();
    if (wid == 0) {
        asm volatile("tcgen05.dealloc.cta_group::1.sync.aligned.b32 %0, %1;"
                     :: "r"(tmem), "r"(512u));
    }
#else
    // -------- fallback: plain fp32 smem GEMM (baseline sm_103 target) --------
    float* sA = (float*)(smem + SCR);     // [128][128]
    float* sB = (float*)(smem + SMB0);    // [128][128]

    for (int i = tid; i < 128 * 32; i += K4T) {
        int r = i >> 5, q = i & 31;
        *(float4*)&sA[r * 128 + q * 4] = *(const float4*)&g_xf[(size_t)(m0 + r) * CH + q * 4];
    }

    int tx = tid & 31, ty = tid >> 5;   // 32 x 16 threads, 8x4 outputs each

    for (int t = 0; t < nt; t++) {
        int n0 = (g + 4 * t) * 128;
        __syncthreads();
        for (int i = tid; i < 128 * 32; i += K4T) {
            int r = i >> 5, q = i & 31;
            float4 v = make_float4(0.f, 0.f, 0.f, 0.f);
            if (n0 + r < VSZ)
                v = *(const float4*)&Wlm[(size_t)(n0 + r) * CH + q * 4];
            *(float4*)&sB[r * 128 + q * 4] = v;
        }
        __syncthreads();

        float acc[8][4];
        #pragma unroll
        for (int i = 0; i < 8; i++)
            #pragma unroll
            for (int j = 0; j < 4; j++) acc[i][j] = 0.f;

        for (int k = 0; k < 128; k++) {
            float a[8], b[4];
            #pragma unroll
            for (int i = 0; i < 8; i++) a[i] = sA[(ty * 8 + i) * 128 + k];
            #pragma unroll
            for (int j = 0; j < 4; j++) b[j] = sB[(tx * 4 + j) * 128 + k];
            #pragma unroll
            for (int i = 0; i < 8; i++)
                #pragma unroll
                for (int j = 0; j < 4; j++) acc[i][j] += a[i] * b[j];
        }

        #pragma unroll
        for (int i = 0; i < 8; i++) {
            float* row = out + (size_t)(m0 + ty * 8 + i) * VSZ;
            #pragma unroll
            for (int j = 0; j < 4; j++) {
                int n = n0 + tx * 4 + j;
                if (n < VSZ) row[n] = acc[i][j];
            }
        }
    }
#endif
}

// ==================== launch ====================
extern "C" void kernel_launch(void* const* d_in, const int* in_sizes, int n_in,
                              void* d_out, int out_size)
{
    const int*   ids    = (const int*)  d_in[0];
    const float* emb    = (const float*)d_in[1];
    const float* router = (const float*)d_in[2];
    const float* kexp   = (const float*)d_in[3];
    const float* vexp   = (const float*)d_in[4];
    const float* skv    = (const float*)d_in[5];
    const float* svv    = (const float*)d_in[6];
    const float* kvg    = (const float*)d_in[7];
    const float* Wq     = (const float*)d_in[8];
    const float* Wo     = (const float*)d_in[9];
    const float* Wm     = (const float*)d_in[10];
    const float* bm     = (const float*)d_in[11];
    const float* g1     = (const float*)d_in[12];
    const float* b1     = (const float*)d_in[13];
    const float* g2     = (const float*)d_in[14];
    const float* b2     = (const float*)d_in[15];
    const float* Wlm    = (const float*)d_in[16];

    float* out = (float*)d_out;
    float* gate_out = out + ((size_t)out_size - (size_t)TNUM * NE);

    cudaFuncSetAttribute(k4mma, cudaFuncAttributeMaxDynamicSharedMemorySize, K4_SMEM);

    k1<<<TNUM, 128>>>(ids, emb, router, Wq, g1, b1, gate_out);
    k2<<<TNUM/TB, 256>>>(kexp, vexp, skv, svv, kvg);
    k3<<<TNUM, 128>>>(Wo, Wm, bm, g2, b2);
    dim3 g4(TNUM/128, 4);
    k4mma<<<g4, K4T, K4_SMEM>>>(Wlm, out);
}

// round 10
// speedup vs baseline: 1.1765x; 1.0652x over previous
#include <cuda_runtime.h>
#include <math.h>
#include <stdint.h>

#define TNUM 4096
#define CH 128
#define NE 16
#define KB 32
#define VSZ 50257
#define NTILES 393   // ceil(50257/128)

// scratch (static device arrays — no allocation)
__device__ float g_x [TNUM*CH];
__device__ float g_q [TNUM*CH];
__device__ float g_rw[TNUM*NE];
__device__ float g_ao[TNUM*CH];
__device__ float g_xf[TNUM*CH];
__device__ float g_wtf[VSZ*CH];   // Wlm pre-rounded to tf32 (RNA), 25.7MB

__device__ __forceinline__ uint32_t f2tf(float f) {
    uint32_t r; asm("cvt.rna.tf32.f32 %0, %1;" : "=r"(r) : "f"(f)); return r;
}

// ==================== K0: Wlm -> tf32-rounded copy ====================
__global__ __launch_bounds__(512) void k0(const float* __restrict__ Wlm)
{
    int i = blockIdx.x * 512 + threadIdx.x;          // float4 index
    const int n4 = (VSZ * CH) / 4;                   // 1,608,224
    if (i < n4) {
        float4 v = *(const float4*)&Wlm[(size_t)i * 4];
        uint4 o;
        o.x = f2tf(v.x); o.y = f2tf(v.y); o.z = f2tf(v.z); o.w = f2tf(v.w);
        *(uint4*)&g_wtf[(size_t)i * 4] = o;
    }
}

// ---------------- block reduce over 128 threads ----------------
__device__ __forceinline__ float blockReduce128(float v, float* sred, int tid) {
    #pragma unroll
    for (int o = 16; o; o >>= 1) v += __shfl_down_sync(0xffffffffu, v, o);
    if ((tid & 31) == 0) sred[tid >> 5] = v;
    __syncthreads();
    return sred[0] + sred[1] + sred[2] + sred[3];
}

// ==================== K1: embed + LN1 + routing + q ====================
__global__ __launch_bounds__(128) void k1(const int* __restrict__ ids,
        const float* __restrict__ emb, const float* __restrict__ router,
        const float* __restrict__ Wq, const float* __restrict__ g1,
        const float* __restrict__ b1, float* __restrict__ gate_out)
{
    int t = blockIdx.x, tid = threadIdx.x;
    __shared__ float sx[CH];
    __shared__ float sred[4];
    __shared__ float sgl[NE];

    int id = ids[t];
    float xv = __ldg(&emb[(long long)id * CH + tid]);
    g_x[t*CH + tid] = xv;

    float mu = blockReduce128(xv, sred, tid) * (1.f/CH);
    __syncthreads();
    float d  = xv - mu;
    float var = blockReduce128(d*d, sred, tid) * (1.f/CH);
    float xln = d * rsqrtf(var + 1e-5f) * g1[tid] + b1[tid];
    sx[tid] = xln;
    __syncthreads();

    int e = tid >> 3, l = tid & 7;
    float gl = 0.f;
    #pragma unroll 4
    for (int k = l; k < CH; k += 8) gl += sx[k] * __ldg(&router[e*CH + k]);
    #pragma unroll
    for (int o = 4; o; o >>= 1) gl += __shfl_xor_sync(0xffffffffu, gl, o, 8);
    if (l == 0) sgl[e] = gl;
    __syncthreads();

    if (tid < NE) gate_out[(long long)t*NE + tid] = sgl[tid];

    float mx = -1e30f;
    #pragma unroll
    for (int i = 0; i < NE; i++) mx = fmaxf(mx, sgl[i]);
    float ss = 0.f;
    #pragma unroll
    for (int i = 0; i < NE; i++) ss += __expf(sgl[i] - mx);
    if (tid < NE) g_rw[t*NE + tid] = __expf(sgl[tid] - mx) / ss;

    float acc = 0.f;
    const float4* wr = (const float4*)(Wq + tid*CH);
    const float4* xr = (const float4*)sx;
    #pragma unroll 8
    for (int k = 0; k < 32; k++) {
        float4 w = __ldg(&wr[k]);
        float4 x4 = xr[k];
        acc += w.x*x4.x + w.y*x4.y + w.z*x4.z + w.w*x4.w;
    }
    g_q[t*CH + tid] = acc;
}

// ==================== K2: expert attention ====================
#define TB 32
#define QSTR 132
__global__ __launch_bounds__(256) void k2(const float* __restrict__ kexp,
        const float* __restrict__ vexp, const float* __restrict__ skv,
        const float* __restrict__ svv, const float* __restrict__ kvg)
{
    __shared__ float sQ[TB*QSTR];
    __shared__ float sT[KB*QSTR];
    __shared__ float sS[TB][KB+1];
    __shared__ float sRW[TB*NE];

    int t0 = blockIdx.x * TB;
    int tid = threadIdx.x;
    float g = 1.f / (1.f + __expf(-kvg[0]));

    for (int i = tid; i < TB*CH; i += 256) {
        int tt = i >> 7, cc = i & 127;
        sQ[tt*QSTR + cc] = g_q[(t0+tt)*CH + cc];
    }
    for (int i = tid; i < TB*NE; i += 256) sRW[i] = g_rw[t0*NE + i];

    int t = tid >> 3, kg = tid & 7;
    float sdyn[4] = {0,0,0,0}, sstat[4];

    for (int e = 0; e < NE; e++) {
        __syncthreads();
        for (int i = tid; i < KB*CH; i += 256) {
            int kk = i >> 7, cc = i & 127;
            sT[kk*QSTR + cc] = __ldg(&kexp[e*KB*CH + i]);
        }
        __syncthreads();
        float rwv = sRW[t*NE + e];
        float dj[4] = {0,0,0,0};
        const float4* qp = (const float4*)(sQ + t*QSTR);
        #pragma unroll 4
        for (int c4 = 0; c4 < 32; c4++) {
            float4 qv = qp[c4];
            #pragma unroll
            for (int j = 0; j < 4; j++) {
                int k = kg + 8*j;
                float4 kv = *(const float4*)(sT + k*QSTR + 4*c4);
                dj[j] += qv.x*kv.x + qv.y*kv.y + qv.z*kv.z + qv.w*kv.w;
            }
        }
        #pragma unroll
        for (int j = 0; j < 4; j++) sdyn[j] += rwv * dj[j];
    }
    __syncthreads();
    for (int i = tid; i < KB*CH; i += 256) {
        int kk = i >> 7, cc = i & 127;
        sT[kk*QSTR + cc] = __ldg(&skv[i]);
    }
    __syncthreads();
    {
        float dj[4] = {0,0,0,0};
        const float4* qp = (const float4*)(sQ + t*QSTR);
        #pragma unroll 4
        for (int c4 = 0; c4 < 32; c4++) {
            float4 qv = qp[c4];
            #pragma unroll
            for (int j = 0; j < 4; j++) {
                int k = kg + 8*j;
                float4 kv = *(const float4*)(sT + k*QSTR + 4*c4);
                dj[j] += qv.x*kv.x + qv.y*kv.y + qv.z*kv.z + qv.w*kv.w;
            }
        }
        #pragma unroll
        for (int j = 0; j < 4; j++) sstat[j] = dj[j];
    }
    const float scale = 0.08838834764831845f;
    #pragma unroll
    for (int j = 0; j < 4; j++)
        sS[t][kg + 8*j] = (g*sdyn[j] + (1.f-g)*sstat[j]) * scale;
    __syncthreads();

    if (tid < TB) {
        float mx = -1e30f;
        #pragma unroll
        for (int k = 0; k < KB; k++) mx = fmaxf(mx, sS[tid][k]);
        float ssum = 0.f;
        #pragma unroll
        for (int k = 0; k < KB; k++) { float ev = __expf(sS[tid][k] - mx); sS[tid][k] = ev; ssum += ev; }
        float inv = 1.f / ssum;
        #pragma unroll
        for (int k = 0; k < KB; k++) sS[tid][k] *= inv;
    }

    float acc[16];
    #pragma unroll
    for (int i = 0; i < 16; i++) acc[i] = 0.f;

    for (int e = 0; e < NE; e++) {
        __syncthreads();
        for (int i = tid; i < KB*CH; i += 256) {
            int kk = i >> 7, cc = i & 127;
            sT[kk*QSTR + cc] = __ldg(&vexp[e*KB*CH + i]);
        }
        __syncthreads();
        float we = g * sRW[t*NE + e];
        #pragma unroll 4
        for (int k = 0; k < KB; k++) {
            float w = we * sS[t][k];
            #pragma unroll
            for (int j = 0; j < 4; j++) {
                float4 vv = *(const float4*)(sT + k*QSTR + 4*(kg + 8*j));
                acc[j*4+0] += w*vv.x; acc[j*4+1] += w*vv.y;
                acc[j*4+2] += w*vv.z; acc[j*4+3] += w*vv.w;
            }
        }
    }
    __syncthreads();
    for (int i = tid; i < KB*CH; i += 256) {
        int kk = i >> 7, cc = i & 127;
        sT[kk*QSTR + cc] = __ldg(&svv[i]);
    }
    __syncthreads();
    {
        float we = 1.f - g;
        #pragma unroll 4
        for (int k = 0; k < KB; k++) {
            float w = we * sS[t][k];
            #pragma unroll
            for (int j = 0; j < 4; j++) {
                float4 vv = *(const float4*)(sT + k*QSTR + 4*(kg + 8*j));
                acc[j*4+0] += w*vv.x; acc[j*4+1] += w*vv.y;
                acc[j*4+2] += w*vv.z; acc[j*4+3] += w*vv.w;
            }
        }
    }
    #pragma unroll
    for (int j = 0; j < 4; j++) {
        float4 o;
        o.x = acc[j*4+0]; o.y = acc[j*4+1]; o.z = acc[j*4+2]; o.w = acc[j*4+3];
        *(float4*)&g_ao[(t0+t)*CH + 4*(kg + 8*j)] = o;
    }
}

// ==================== K3: Wo + residual + LN2 + MLP + residual ====================
__global__ __launch_bounds__(128) void k3(const float* __restrict__ Wo,
        const float* __restrict__ Wm, const float* __restrict__ bm,
        const float* __restrict__ g2, const float* __restrict__ b2)
{
    int t = blockIdx.x, tid = threadIdx.x;
    __shared__ float sa[CH];
    __shared__ float sred[4];

    sa[tid] = g_ao[t*CH + tid];
    __syncthreads();

    float o = 0.f;
    {
        const float4* wr = (const float4*)(Wo + tid*CH);
        const float4* ar = (const float4*)sa;
        #pragma unroll 8
        for (int k = 0; k < 32; k++) {
            float4 w = __ldg(&wr[k]);
            float4 a4 = ar[k];
            o += w.x*a4.x + w.y*a4.y + w.z*a4.z + w.w*a4.w;
        }
    }
    float x2 = g_x[t*CH + tid] + o;

    __syncthreads();
    float mu = blockReduce128(x2, sred, tid) * (1.f/CH);
    __syncthreads();
    float d = x2 - mu;
    float var = blockReduce128(d*d, sred, tid) * (1.f/CH);
    float xln = d * rsqrtf(var + 1e-5f) * g2[tid] + b2[tid];
    __syncthreads();
    sa[tid] = xln;
    __syncthreads();

    float m = __ldg(&bm[tid]);
    {
        const float4* wr = (const float4*)(Wm + tid*CH);
        const float4* ar = (const float4*)sa;
        #pragma unroll 8
        for (int k = 0; k < 32; k++) {
            float4 w = __ldg(&wr[k]);
            float4 a4 = ar[k];
            m += w.x*a4.x + w.y*a4.y + w.z*a4.z + w.w*a4.w;
        }
    }
    g_xf[t*CH + tid] = x2 + m;
}

// ==================== K4: LM head GEMM (cp.async B, TS-mode MMA) ====================
// D[4096,50257] = Xf[4096,128] @ Wlm_tf[50257,128]^T
// 512 threads, no producer split: B tiles arrive via cp.async (LDGSTS) from
// the pre-rounded g_wtf; all 16 warps run the epilogue while cp.async streams.

#if defined(__CUDA_ARCH__) && (__CUDA_ARCH__ == 1030) && defined(__CUDA_ARCH_FEAT_SM103_ALL)
#define HAS_TCGEN05 1
#else
#define HAS_TCGEN05 0
#endif

__device__ __forceinline__ uint32_t s2u(const void* p) {
    uint32_t a;
    asm("{ .reg .u64 t; cvta.to.shared.u64 t, %1; cvt.u32.u64 %0, t; }" : "=r"(a) : "l"(p));
    return a;
}

#define K4T 512
#define SMB0 0
#define SMB1 65536
#define SCR  131072
#define K4_SMEM 196608   // 2x64K B buffers + 64K epilogue scratch

// TMEM layout (512 cols): D0 @0, D1 @128, A @256 (128 cols)
#define TM_D0 0
#define TM_D1 128
#define TM_A  256

#if HAS_TCGEN05

__device__ __forceinline__ bool elect1() {
    uint32_t p;
    asm volatile("{ .reg .pred p; elect.sync _|p, 0xFFFFFFFF; selp.b32 %0, 1, 0, p; }" : "=r"(p));
    return p != 0;
}
__device__ __forceinline__ void mbar_init(uint32_t a, uint32_t cnt) {
    asm volatile("mbarrier.init.shared.b64 [%0], %1;" :: "r"(a), "r"(cnt) : "memory");
}
__device__ __forceinline__ void mbar_wait(uint32_t a, uint32_t ph) {
    asm volatile(
        "{\n\t.reg .pred P;\n"
        "W_%=:\n\t"
        "mbarrier.try_wait.parity.acquire.cta.shared::cta.b64 P, [%0], %1, 0x989680;\n\t"
        "@P bra D_%=;\n\t"
        "bra W_%=;\n"
        "D_%=:\n\t}"
        :: "r"(a), "r"(ph) : "memory");
}
__device__ __forceinline__ void sts128(uint32_t a, uint32_t r0, uint32_t r1, uint32_t r2, uint32_t r3) {
    asm volatile("st.shared.v4.b32 [%0], {%1, %2, %3, %4};" :: "r"(a), "r"(r0), "r"(r1), "r"(r2), "r"(r3) : "memory");
}
// TS-mode tf32 MMA: A in TMEM, B via smem descriptor
__device__ __forceinline__ void mma_tf32_ts(uint32_t d, uint32_t a, uint64_t bd, uint32_t idesc, bool accum) {
    uint32_t en = accum ? 1u : 0u;
    asm volatile(
        "{\n\t.reg .pred p;\n\t"
        "setp.ne.u32 p, %5, 0;\n\t"
        "tcgen05.mma.cta_group::1.kind::tf32 [%0], [%1], %2, %3, {%4, %4, %4, %4}, p;\n\t}"
        :: "r"(d), "r"(a), "l"(bd), "r"(idesc), "r"(0u), "r"(en) : "memory");
}
__device__ __forceinline__ void mma_commit(uint32_t mbar) {
    asm volatile("tcgen05.commit.cta_group::1.mbarrier::arrive::one.shared::cluster.b64 [%0];" :: "r"(mbar) : "memory");
}
// SW128 K-major smem descriptor: layout=2, version=1, SBO=64, LBO=1
__device__ __forceinline__ uint64_t mk_desc(uint32_t addr) {
    const uint64_t base = (uint64_t(2) << 61) | (uint64_t(1) << 46) | (uint64_t(64) << 32) | (uint64_t(1) << 16);
    return base | ((uint64_t)(addr >> 4) & 0x3FFF);
}

#define LDTM32(r, a) \
    asm volatile( \
        "tcgen05.ld.sync.aligned.32x32b.x32.b32 " \
        "{%0, %1, %2, %3, %4, %5, %6, %7, " \
        " %8, %9, %10, %11, %12, %13, %14, %15, " \
        " %16, %17, %18, %19, %20, %21, %22, %23, " \
        " %24, %25, %26, %27, %28, %29, %30, %31}, [%32];" \
        : "=r"((r)[0]),  "=r"((r)[1]),  "=r"((r)[2]),  "=r"((r)[3]), \
          "=r"((r)[4]),  "=r"((r)[5]),  "=r"((r)[6]),  "=r"((r)[7]), \
          "=r"((r)[8]),  "=r"((r)[9]),  "=r"((r)[10]), "=r"((r)[11]), \
          "=r"((r)[12]), "=r"((r)[13]), "=r"((r)[14]), "=r"((r)[15]), \
          "=r"((r)[16]), "=r"((r)[17]), "=r"((r)[18]), "=r"((r)[19]), \
          "=r"((r)[20]), "=r"((r)[21]), "=r"((r)[22]), "=r"((r)[23]), \
          "=r"((r)[24]), "=r"((r)[25]), "=r"((r)[26]), "=r"((r)[27]), \
          "=r"((r)[28]), "=r"((r)[29]), "=r"((r)[30]), "=r"((r)[31]) \
        : "r"(a))

#define STTM32(a, r) \
    asm volatile( \
        "tcgen05.st.sync.aligned.32x32b.x32.b32 [%0], " \
        "{%1, %2, %3, %4, %5, %6, %7, %8, " \
        " %9, %10, %11, %12, %13, %14, %15, %16, " \
        " %17, %18, %19, %20, %21, %22, %23, %24, " \
        " %25, %26, %27, %28, %29, %30, %31, %32};" \
        :: "r"(a), \
           "r"((r)[0]),  "r"((r)[1]),  "r"((r)[2]),  "r"((r)[3]), \
           "r"((r)[4]),  "r"((r)[5]),  "r"((r)[6]),  "r"((r)[7]), \
           "r"((r)[8]),  "r"((r)[9]),  "r"((r)[10]), "r"((r)[11]), \
           "r"((r)[12]), "r"((r)[13]), "r"((r)[14]), "r"((r)[15]), \
           "r"((r)[16]), "r"((r)[17]), "r"((r)[18]), "r"((r)[19]), \
           "r"((r)[20]), "r"((r)[21]), "r"((r)[22]), "r"((r)[23]), \
           "r"((r)[24]), "r"((r)[25]), "r"((r)[26]), "r"((r)[27]), \
           "r"((r)[28]), "r"((r)[29]), "r"((r)[30]), "r"((r)[31]) \
        : "memory")

// idesc: dtype=F32(1<<4), atype=TF32(2<<7), btype=TF32(2<<10), N=128(16<<17), M=128(8<<24)
#define K4_IDESC ((1u<<4) | (2u<<7) | (2u<<10) | (16u<<17) | (8u<<24))

// B tile load via cp.async: g_wtf rows -> SW128-swizzled smem, zero-fill OOB.
__device__ __forceinline__ void k4_load_tile_ca(uint32_t sdst, int row0, int tid)
{
    #pragma unroll
    for (int it = 0; it < 8; it++) {
        int f = tid + it * K4T;          // float4 index, 0..4095
        int r = f >> 5, q = f & 31;
        int kc = q >> 3, c4 = q & 7;
        uint32_t off = (uint32_t)(kc * 16384 + r * 128 + c4 * 16);
        off = off ^ ((off >> 3) & 0x70);
        int row = row0 + r;
        int ok = (row < VSZ);
        const float* gsrc = &g_wtf[(size_t)(ok ? row : 0) * CH + q * 4];
        int sz = ok ? 16 : 0;
        asm volatile("cp.async.cg.shared.global [%0], [%1], 16, %2;"
                     :: "r"(sdst + off), "l"(gsrc), "r"(sz) : "memory");
    }
}

// Epilogue (all 16 warps): LDTM D -> 64KB swizzled scratch -> aligned float4 STG
__device__ __forceinline__ void k4_epilogue(uint32_t dt, float* __restrict__ scr,
                                            int m0, int n0,
                                            float* __restrict__ out, int tid)
{
    int w = tid >> 5, lid = tid & 31;    // w in 0..15
    int row = (w & 3) * 32 + lid;        // TMEM lane -> D row (subpartition = w&3)
    int cb  = (w >> 2) * 32;             // 32-col slab per warp quad
    uint32_t scr_u = s2u(scr);

    // phase 1: TMEM -> scratch (one x32 LDTM per warp)
    {
        uint32_t r[32];
        LDTM32(r, dt + cb);
        asm volatile("tcgen05.wait::ld.sync.aligned;" ::: "memory");
        #pragma unroll
        for (int gq = 0; gq < 8; gq++) {
            int cg = (cb >> 2) + gq;             // float4 col-group 0..31
            int sg = cg ^ (row & 31);
            sts128(scr_u + (uint32_t)(row * 128 + sg * 4) * 4,
                   r[4*gq], r[4*gq+1], r[4*gq+2], r[4*gq+3]);
        }
    }
    __syncthreads();

    // phase 2: scratch -> gmem, warp w -> rows w*8..w*8+7
    if (n0 + 128 <= VSZ) {
        #pragma unroll
        for (int itr = 0; itr < 8; itr++) {
            int r2 = w * 8 + itr;
            int m  = m0 + r2;
            int c0 = (4 - (m & 3)) & 3;    // (m*VSZ + n0 + c0) % 4 == 0
            int sw = r2 & 31;
            float* orow = out + (size_t)m * VSZ + n0;
            int j = c0 + 4 * lid;
            if (j + 3 < 128) {
                float4 v;
                float* vp = &v.x;
                #pragma unroll
                for (int k = 0; k < 4; k++) {
                    int col = j + k;
                    int sg2 = (col >> 2) ^ sw;
                    vp[k] = scr[r2 * 128 + sg2 * 4 + (col & 3)];
                }
                *(float4*)(orow + j) = v;   // provably 16B-aligned
            }
            if (c0 && lid < 4) {            // 4 leftover columns, scalar
                int col = (lid < c0) ? lid : (c0 + 124 + (lid - c0));
                int sg2 = (col >> 2) ^ sw;
                orow[col] = scr[r2 * 128 + sg2 * 4 + (col & 3)];
            }
        }
    } else {
        for (int itr = 0; itr < 8; itr++) {
            int r2 = w * 8 + itr;
            int sw = r2 & 31;
            float* orow = out + (size_t)(m0 + r2) * VSZ;
            #pragma unroll
            for (int k = 0; k < 4; k++) {
                int col = lid + 32 * k;
                if (n0 + col < VSZ) {
                    int sg2 = (col >> 2) ^ sw;
                    orow[n0 + col] = scr[r2 * 128 + sg2 * 4 + (col & 3)];
                }
            }
        }
    }
}
#endif  // HAS_TCGEN05

__global__ void __launch_bounds__(K4T, 1) k4mma(const float* __restrict__ Wlm,
                                                float* __restrict__ out)
{
    extern __shared__ __align__(1024) char smem[];
    int tid = threadIdx.x;
    int m0 = blockIdx.x * 128;
    int g  = blockIdx.y;              // N-group 0..3, tiles jt = g, g+4, ...
    int nt = (NTILES - 1 - g) / 4 + 1;

#if HAS_TCGEN05
    __shared__ __align__(16) unsigned long long s_mbar[2];
    __shared__ uint32_t s_tmem;

    int wid = tid >> 5;
    uint32_t sb = s2u(smem);
    float* scr = (float*)(smem + SCR);
    uint32_t mb[2] = { s2u(&s_mbar[0]), s2u(&s_mbar[1]) };

    if (wid == 0) {
        asm volatile("tcgen05.alloc.cta_group::1.sync.aligned.shared::cta.b32 [%0], %1;"
                     :: "r"(s2u(&s_tmem)), "r"(512u) : "memory");
        asm volatile("tcgen05.relinquish_alloc_permit.cta_group::1.sync.aligned;");
    }
    if (tid == 0) { mbar_init(mb[0], 1); mbar_init(mb[1], 1); }
    __syncthreads();
    uint32_t tmem;
    asm volatile("ld.shared.b32 %0, [%1];" : "=r"(tmem) : "r"(s2u(&s_tmem)));

    // prologue: B(0) via cp.async (starts streaming immediately), A -> TMEM
    k4_load_tile_ca(sb + SMB0, g * 128, tid);
    asm volatile("cp.async.commit_group;" ::: "memory");

    if (tid < 128) {
        uint32_t warp_off = (uint32_t)(tid >> 5) << 21;
        const float* arow = &g_xf[(size_t)(m0 + tid) * CH];
        #pragma unroll
        for (int q = 0; q < 4; q++) {
            uint32_t ar[32];
            #pragma unroll
            for (int j = 0; j < 32; j++) ar[j] = f2tf(arow[q * 32 + j]);
            STTM32(tmem + TM_A + q * 32 + warp_off, ar);
        }
        asm volatile("tcgen05.wait::st.sync.aligned;" ::: "memory");
        asm volatile("tcgen05.fence::before_thread_sync;" ::: "memory");
    }

    uint64_t bdesc[2] = { mk_desc(sb + SMB0), mk_desc(sb + SMB1) };
    int ph[2] = {0, 0};

    for (int i = 0; i < nt; i++) {
        int b = i & 1, pb = b ^ 1;

        // B(i) landed + A ready + previous epilogue's scratch reads done
        asm volatile("cp.async.wait_group 0;" ::: "memory");
        asm volatile("fence.proxy.async.shared::cta;" ::: "memory");
        __syncthreads();

        // MMA(i): TS-mode, A in TMEM, into D[b]
        if (wid == 0 && elect1()) {
            asm volatile("tcgen05.fence::after_thread_sync;" ::: "memory");
            uint32_t dreg = tmem + (uint32_t)(b ? TM_D1 : TM_D0);
            #pragma unroll
            for (int s = 0; s < 16; s++) {
                uint64_t koff = (uint64_t)((s >> 2) * 1024 + (s & 3) * 2);
                mma_tf32_ts(dreg, tmem + TM_A + s * 8, bdesc[b] + koff, K4_IDESC, s > 0);
            }
            mma_commit(mb[b]);
        }

        if (i >= 1) {
            // MMA(i-1) done: D[pb] readable, buf pb free for B(i+1)
            mbar_wait(mb[pb], ph[pb]); ph[pb] ^= 1;
            if (i + 1 < nt) {
                k4_load_tile_ca(sb + (pb ? SMB1 : SMB0), (g + 4 * (i + 1)) * 128, tid);
                asm volatile("cp.async.commit_group;" ::: "memory");
            }
            asm volatile("tcgen05.fence::after_thread_sync;" ::: "memory");
            k4_epilogue(tmem + (pb ? TM_D1 : TM_D0), scr, m0,
                        (g + 4 * (i - 1)) * 128, out, tid);
        } else if (nt > 1) {
            k4_load_tile_ca(sb + SMB1, (g + 4) * 128, tid);
            asm volatile("cp.async.commit_group;" ::: "memory");
        }
    }

    // final tile epilogue
    {
        int b = (nt - 1) & 1;
        mbar_wait(mb[b], ph[b]);
        asm volatile("tcgen05.fence::after_thread_sync;" ::: "memory");
        __syncthreads();   // scratch from previous epilogue fully consumed
        k4_epilogue(tmem + (b ? TM_D1 : TM_D0), scr, m0,
                    (g + 4 * (nt - 1)) * 128, out, tid);
    }

    __syncthreads();
    if (wid == 0) {
        asm volatile("tcgen05.dealloc.cta_group::1.sync.aligned.b32 %0, %1;"
                     :: "r"(tmem), "r"(512u));
    }
#else
    // -------- fallback: plain fp32 smem GEMM (baseline sm_103 target) --------
    float* sA = (float*)(smem + SCR);     // [128][128]
    float* sB = (float*)(smem + SMB0);    // [128][128]

    for (int i = tid; i < 128 * 32; i += K4T) {
        int r = i >> 5, q = i & 31;
        *(float4*)&sA[r * 128 + q * 4] = *(const float4*)&g_xf[(size_t)(m0 + r) * CH + q * 4];
    }

    int tx = tid & 31, ty = tid >> 5;   // 32 x 16 threads, 8x4 outputs each

    for (int t = 0; t < nt; t++) {
        int n0 = (g + 4 * t) * 128;
        __syncthreads();
        for (int i = tid; i < 128 * 32; i += K4T) {
            int r = i >> 5, q = i & 31;
            float4 v = make_float4(0.f, 0.f, 0.f, 0.f);
            if (n0 + r < VSZ)
                v = *(const float4*)&Wlm[(size_t)(n0 + r) * CH + q * 4];
            *(float4*)&sB[r * 128 + q * 4] = v;
        }
        __syncthreads();

        float acc[8][4];
        #pragma unroll
        for (int i = 0; i < 8; i++)
            #pragma unroll
            for (int j = 0; j < 4; j++) acc[i][j] = 0.f;

        for (int k = 0; k < 128; k++) {
            float a[8], b[4];
            #pragma unroll
            for (int i = 0; i < 8; i++) a[i] = sA[(ty * 8 + i) * 128 + k];
            #pragma unroll
            for (int j = 0; j < 4; j++) b[j] = sB[(tx * 4 + j) * 128 + k];
            #pragma unroll
            for (int i = 0; i < 8; i++)
                #pragma unroll
                for (int j = 0; j < 4; j++) acc[i][j] += a[i] * b[j];
        }

        #pragma unroll
        for (int i = 0; i < 8; i++) {
            float* row = out + (size_t)(m0 + ty * 8 + i) * VSZ;
            #pragma unroll
            for (int j = 0; j < 4; j++) {
                int n = n0 + tx * 4 + j;
                if (n < VSZ) row[n] = acc[i][j];
            }
        }
    }
#endif
}

// ==================== launch ====================
extern "C" void kernel_launch(void* const* d_in, const int* in_sizes, int n_in,
                              void* d_out, int out_size)
{
    const int*   ids    = (const int*)  d_in[0];
    const float* emb    = (const float*)d_in[1];
    const float* router = (const float*)d_in[2];
    const float* kexp   = (const float*)d_in[3];
    const float* vexp   = (const float*)d_in[4];
    const float* skv    = (const float*)d_in[5];
    const float* svv    = (const float*)d_in[6];
    const float* kvg    = (const float*)d_in[7];
    const float* Wq     = (const float*)d_in[8];
    const float* Wo     = (const float*)d_in[9];
    const float* Wm     = (const float*)d_in[10];
    const float* bm     = (const float*)d_in[11];
    const float* g1     = (const float*)d_in[12];
    const float* b1     = (const float*)d_in[13];
    const float* g2     = (const float*)d_in[14];
    const float* b2     = (const float*)d_in[15];
    const float* Wlm    = (const float*)d_in[16];

    float* out = (float*)d_out;
    float* gate_out = out + ((size_t)out_size - (size_t)TNUM * NE);

    cudaFuncSetAttribute(k4mma, cudaFuncAttributeMaxDynamicSharedMemorySize, K4_SMEM);

    k0<<<((VSZ*CH/4) + 511) / 512, 512>>>(Wlm);
    k1<<<TNUM, 128>>>(ids, emb, router, Wq, g1, b1, gate_out);
    k2<<<TNUM/TB, 256>>>(kexp, vexp, skv, svv, kvg);
    k3<<<TNUM, 128>>>(Wo, Wm, bm, g2, b2);
    dim3 g4(TNUM/128, 4);
    k4mma<<<g4, K4T, K4_SMEM>>>(Wlm, out);
}

// round 11
// speedup vs baseline: 1.4773x; 1.2557x over previous
#include <cuda_runtime.h>
#include <math.h>
#include <stdint.h>

#define TNUM 4096
#define CH 128
#define NE 16
#define KB 32
#define VSZ 50257
#define NTILES 393   // ceil(50257/128)

// scratch (static device arrays — no allocation)
__device__ float g_x [TNUM*CH];
__device__ float g_q [TNUM*CH];
__device__ float g_rw[TNUM*NE];
__device__ float g_ao[TNUM*CH];
__device__ float g_xf[TNUM*CH];
__device__ float g_wtf[VSZ*CH];   // Wlm pre-rounded to tf32 (RNA), 25.7MB

__device__ __forceinline__ uint32_t f2tf(float f) {
    uint32_t r; asm("cvt.rna.tf32.f32 %0, %1;" : "=r"(r) : "f"(f)); return r;
}

// ==================== K0: Wlm -> tf32-rounded copy ====================
__global__ __launch_bounds__(512) void k0(const float* __restrict__ Wlm)
{
    int i = blockIdx.x * 512 + threadIdx.x;          // float4 index
    const int n4 = (VSZ * CH) / 4;                   // 1,608,224
    if (i < n4) {
        float4 v = *(const float4*)&Wlm[(size_t)i * 4];
        uint4 o;
        o.x = f2tf(v.x); o.y = f2tf(v.y); o.z = f2tf(v.z); o.w = f2tf(v.w);
        *(uint4*)&g_wtf[(size_t)i * 4] = o;
    }
}

// ==================== K1: embed + LN1 + routing + q (token-tiled) ====================
// 32 tokens/block, 256 threads. Weight chunks staged in smem; 4t x 4d register tiles.
#define TB1 32
__global__ __launch_bounds__(256) void k1(const int* __restrict__ ids,
        const float* __restrict__ emb, const float* __restrict__ router,
        const float* __restrict__ Wq, const float* __restrict__ g1,
        const float* __restrict__ b1, float* __restrict__ gate_out)
{
    __shared__ float sXL[TB1*132];   // LN'd activations, stride 132
    __shared__ float sW [32*132];    // weight / router chunk
    __shared__ float sGL[TB1][17];

    int t0 = blockIdx.x * TB1;
    int tid = threadIdx.x;
    int wid = tid >> 5, lid = tid & 31;

    // gather + LN: warp wid handles tokens wid*4 .. wid*4+3 (lane = 4 channels)
    #pragma unroll
    for (int i = 0; i < 4; i++) {
        int t = wid * 4 + i;
        int id = ids[t0 + t];
        float4 v = __ldg((const float4*)&emb[(size_t)id * CH + lid * 4]);
        *(float4*)&g_x[(size_t)(t0 + t) * CH + lid * 4] = v;
        float s = v.x + v.y + v.z + v.w;
        #pragma unroll
        for (int o = 16; o; o >>= 1) s += __shfl_xor_sync(0xffffffffu, s, o);
        float mu = s * (1.f/128.f);
        float4 d; d.x = v.x - mu; d.y = v.y - mu; d.z = v.z - mu; d.w = v.w - mu;
        float q2 = d.x*d.x + d.y*d.y + d.z*d.z + d.w*d.w;
        #pragma unroll
        for (int o = 16; o; o >>= 1) q2 += __shfl_xor_sync(0xffffffffu, q2, o);
        float inv = rsqrtf(q2 * (1.f/128.f) + 1e-5f);
        float4 g4 = __ldg((const float4*)&g1[lid * 4]);
        float4 b4 = __ldg((const float4*)&b1[lid * 4]);
        float4 o4;
        o4.x = d.x * inv * g4.x + b4.x;
        o4.y = d.y * inv * g4.y + b4.y;
        o4.z = d.z * inv * g4.z + b4.z;
        o4.w = d.w * inv * g4.w + b4.w;
        *(float4*)&sXL[t * 132 + lid * 4] = o4;
    }
    // stage router rows 0..15
    for (int i = tid; i < 16 * 32; i += 256) {
        int e = i >> 5, c4 = i & 31;
        *(float4*)&sW[e * 132 + c4 * 4] = __ldg((const float4*)&router[(size_t)e * CH + c4 * 4]);
    }
    __syncthreads();

    // gate logits: thread -> (token t, expert pair eg)
    {
        int t = tid >> 3, eg = tid & 7;
        float a0 = 0.f, a1 = 0.f;
        #pragma unroll 8
        for (int c4 = 0; c4 < 32; c4++) {
            float4 xv = *(float4*)&sXL[t * 132 + c4 * 4];
            float4 r0 = *(float4*)&sW[(2*eg)   * 132 + c4 * 4];
            float4 r1 = *(float4*)&sW[(2*eg+1) * 132 + c4 * 4];
            a0 += xv.x*r0.x + xv.y*r0.y + xv.z*r0.z + xv.w*r0.w;
            a1 += xv.x*r1.x + xv.y*r1.y + xv.z*r1.z + xv.w*r1.w;
        }
        sGL[t][2*eg] = a0; sGL[t][2*eg+1] = a1;
    }
    __syncthreads();

    for (int i = tid; i < TB1 * NE; i += 256)
        gate_out[(size_t)t0 * NE + i] = sGL[i >> 4][i & 15];
    if (tid < TB1) {
        float mx = -1e30f;
        #pragma unroll
        for (int e = 0; e < NE; e++) mx = fmaxf(mx, sGL[tid][e]);
        float ss = 0.f;
        #pragma unroll
        for (int e = 0; e < NE; e++) ss += __expf(sGL[tid][e] - mx);
        float inv = 1.f / ss;
        #pragma unroll
        for (int e = 0; e < NE; e++)
            g_rw[(size_t)(t0 + tid) * NE + e] = __expf(sGL[tid][e] - mx) * inv;
    }
    __syncthreads();

    // q GEMM: q[t][d] = dot(xln[t], Wq[d]); 4 chunks of 32 dims
    int td = tid & 31, tt = tid >> 5;
    #pragma unroll
    for (int dc = 0; dc < 4; dc++) {
        for (int i = tid; i < 32 * 32; i += 256) {
            int r = i >> 5, c4 = i & 31;
            *(float4*)&sW[r * 132 + c4 * 4] =
                __ldg((const float4*)&Wq[(size_t)(dc * 32 + r) * CH + c4 * 4]);
        }
        __syncthreads();
        float acc[4] = {0.f, 0.f, 0.f, 0.f};
        #pragma unroll 4
        for (int c4 = 0; c4 < 32; c4++) {
            float4 wv = *(float4*)&sW[td * 132 + c4 * 4];
            #pragma unroll
            for (int i = 0; i < 4; i++) {
                float4 xv = *(float4*)&sXL[(tt * 4 + i) * 132 + c4 * 4];
                acc[i] += xv.x*wv.x + xv.y*wv.y + xv.z*wv.z + xv.w*wv.w;
            }
        }
        #pragma unroll
        for (int i = 0; i < 4; i++)
            g_q[(size_t)(t0 + tt * 4 + i) * CH + dc * 32 + td] = acc[i];
        __syncthreads();
    }
}

// ==================== K2: expert attention ====================
#define TB 32
#define QSTR 132
__global__ __launch_bounds__(256) void k2(const float* __restrict__ kexp,
        const float* __restrict__ vexp, const float* __restrict__ skv,
        const float* __restrict__ svv, const float* __restrict__ kvg)
{
    __shared__ float sQ[TB*QSTR];
    __shared__ float sT[KB*QSTR];
    __shared__ float sS[TB][KB+1];
    __shared__ float sRW[TB*NE];

    int t0 = blockIdx.x * TB;
    int tid = threadIdx.x;
    float g = 1.f / (1.f + __expf(-kvg[0]));

    for (int i = tid; i < TB*CH; i += 256) {
        int tt = i >> 7, cc = i & 127;
        sQ[tt*QSTR + cc] = g_q[(t0+tt)*CH + cc];
    }
    for (int i = tid; i < TB*NE; i += 256) sRW[i] = g_rw[t0*NE + i];

    int t = tid >> 3, kg = tid & 7;
    float sdyn[4] = {0,0,0,0}, sstat[4];

    for (int e = 0; e < NE; e++) {
        __syncthreads();
        for (int i = tid; i < KB*CH; i += 256) {
            int kk = i >> 7, cc = i & 127;
            sT[kk*QSTR + cc] = __ldg(&kexp[e*KB*CH + i]);
        }
        __syncthreads();
        float rwv = sRW[t*NE + e];
        float dj[4] = {0,0,0,0};
        const float4* qp = (const float4*)(sQ + t*QSTR);
        #pragma unroll 4
        for (int c4 = 0; c4 < 32; c4++) {
            float4 qv = qp[c4];
            #pragma unroll
            for (int j = 0; j < 4; j++) {
                int k = kg + 8*j;
                float4 kv = *(const float4*)(sT + k*QSTR + 4*c4);
                dj[j] += qv.x*kv.x + qv.y*kv.y + qv.z*kv.z + qv.w*kv.w;
            }
        }
        #pragma unroll
        for (int j = 0; j < 4; j++) sdyn[j] += rwv * dj[j];
    }
    __syncthreads();
    for (int i = tid; i < KB*CH; i += 256) {
        int kk = i >> 7, cc = i & 127;
        sT[kk*QSTR + cc] = __ldg(&skv[i]);
    }
    __syncthreads();
    {
        float dj[4] = {0,0,0,0};
        const float4* qp = (const float4*)(sQ + t*QSTR);
        #pragma unroll 4
        for (int c4 = 0; c4 < 32; c4++) {
            float4 qv = qp[c4];
            #pragma unroll
            for (int j = 0; j < 4; j++) {
                int k = kg + 8*j;
                float4 kv = *(const float4*)(sT + k*QSTR + 4*c4);
                dj[j] += qv.x*kv.x + qv.y*kv.y + qv.z*kv.z + qv.w*kv.w;
            }
        }
        #pragma unroll
        for (int j = 0; j < 4; j++) sstat[j] = dj[j];
    }
    const float scale = 0.08838834764831845f;
    #pragma unroll
    for (int j = 0; j < 4; j++)
        sS[t][kg + 8*j] = (g*sdyn[j] + (1.f-g)*sstat[j]) * scale;
    __syncthreads();

    if (tid < TB) {
        float mx = -1e30f;
        #pragma unroll
        for (int k = 0; k < KB; k++) mx = fmaxf(mx, sS[tid][k]);
        float ssum = 0.f;
        #pragma unroll
        for (int k = 0; k < KB; k++) { float ev = __expf(sS[tid][k] - mx); sS[tid][k] = ev; ssum += ev; }
        float inv = 1.f / ssum;
        #pragma unroll
        for (int k = 0; k < KB; k++) sS[tid][k] *= inv;
    }

    float acc[16];
    #pragma unroll
    for (int i = 0; i < 16; i++) acc[i] = 0.f;

    for (int e = 0; e < NE; e++) {
        __syncthreads();
        for (int i = tid; i < KB*CH; i += 256) {
            int kk = i >> 7, cc = i & 127;
            sT[kk*QSTR + cc] = __ldg(&vexp[e*KB*CH + i]);
        }
        __syncthreads();
        float we = g * sRW[t*NE + e];
        #pragma unroll 4
        for (int k = 0; k < KB; k++) {
            float w = we * sS[t][k];
            #pragma unroll
            for (int j = 0; j < 4; j++) {
                float4 vv = *(const float4*)(sT + k*QSTR + 4*(kg + 8*j));
                acc[j*4+0] += w*vv.x; acc[j*4+1] += w*vv.y;
                acc[j*4+2] += w*vv.z; acc[j*4+3] += w*vv.w;
            }
        }
    }
    __syncthreads();
    for (int i = tid; i < KB*CH; i += 256) {
        int kk = i >> 7, cc = i & 127;
        sT[kk*QSTR + cc] = __ldg(&svv[i]);
    }
    __syncthreads();
    {
        float we = 1.f - g;
        #pragma unroll 4
        for (int k = 0; k < KB; k++) {
            float w = we * sS[t][k];
            #pragma unroll
            for (int j = 0; j < 4; j++) {
                float4 vv = *(const float4*)(sT + k*QSTR + 4*(kg + 8*j));
                acc[j*4+0] += w*vv.x; acc[j*4+1] += w*vv.y;
                acc[j*4+2] += w*vv.z; acc[j*4+3] += w*vv.w;
            }
        }
    }
    #pragma unroll
    for (int j = 0; j < 4; j++) {
        float4 o;
        o.x = acc[j*4+0]; o.y = acc[j*4+1]; o.z = acc[j*4+2]; o.w = acc[j*4+3];
        *(float4*)&g_ao[(t0+t)*CH + 4*(kg + 8*j)] = o;
    }
}

// ==================== K3: Wo+res+LN2+MLP+res (token-tiled GEMM) ====================
#define TB3 32
__global__ __launch_bounds__(256) void k3(const float* __restrict__ Wo,
        const float* __restrict__ Wm, const float* __restrict__ bm,
        const float* __restrict__ g2, const float* __restrict__ b2)
{
    __shared__ float sA[TB3*132];
    __shared__ float sW[32*132];

    int t0 = blockIdx.x * TB3;
    int tid = threadIdx.x;
    int td = tid & 31, tt = tid >> 5;

    // load ao tile
    for (int i = tid; i < TB3 * 32; i += 256) {
        int t = i >> 5, c4 = i & 31;
        *(float4*)&sA[t * 132 + c4 * 4] = *(const float4*)&g_ao[(size_t)(t0 + t) * CH + c4 * 4];
    }
    __syncthreads();

    // GEMM1: x2 = ao @ Wo^T + x ; x2 kept in registers (chunk dc, token i) for dim dc*32+td
    float x2r[4][4];
    #pragma unroll
    for (int dc = 0; dc < 4; dc++) {
        for (int i = tid; i < 32 * 32; i += 256) {
            int r = i >> 5, c4 = i & 31;
            *(float4*)&sW[r * 132 + c4 * 4] =
                __ldg((const float4*)&Wo[(size_t)(dc * 32 + r) * CH + c4 * 4]);
        }
        __syncthreads();
        float acc[4] = {0.f, 0.f, 0.f, 0.f};
        #pragma unroll 4
        for (int c4 = 0; c4 < 32; c4++) {
            float4 wv = *(float4*)&sW[td * 132 + c4 * 4];
            #pragma unroll
            for (int i = 0; i < 4; i++) {
                float4 xv = *(float4*)&sA[(tt * 4 + i) * 132 + c4 * 4];
                acc[i] += xv.x*wv.x + xv.y*wv.y + xv.z*wv.z + xv.w*wv.w;
            }
        }
        #pragma unroll
        for (int i = 0; i < 4; i++)
            x2r[dc][i] = acc[i] + g_x[(size_t)(t0 + tt * 4 + i) * CH + dc * 32 + td];
        __syncthreads();
    }

    // write x2 into sA (ao no longer needed)
    #pragma unroll
    for (int dc = 0; dc < 4; dc++)
        #pragma unroll
        for (int i = 0; i < 4; i++)
            sA[(tt * 4 + i) * 132 + dc * 32 + td] = x2r[dc][i];
    __syncthreads();

    // LN2 in place: warp tt handles tokens tt*4..+3 (lane td = 4 channels)
    #pragma unroll
    for (int i = 0; i < 4; i++) {
        int t = tt * 4 + i;
        float4 v = *(float4*)&sA[t * 132 + td * 4];
        float s = v.x + v.y + v.z + v.w;
        #pragma unroll
        for (int o = 16; o; o >>= 1) s += __shfl_xor_sync(0xffffffffu, s, o);
        float mu = s * (1.f/128.f);
        float4 d; d.x = v.x - mu; d.y = v.y - mu; d.z = v.z - mu; d.w = v.w - mu;
        float q2 = d.x*d.x + d.y*d.y + d.z*d.z + d.w*d.w;
        #pragma unroll
        for (int o = 16; o; o >>= 1) q2 += __shfl_xor_sync(0xffffffffu, q2, o);
        float inv = rsqrtf(q2 * (1.f/128.f) + 1e-5f);
        float4 g4 = __ldg((const float4*)&g2[td * 4]);
        float4 b4 = __ldg((const float4*)&b2[td * 4]);
        float4 o4;
        o4.x = d.x * inv * g4.x + b4.x;
        o4.y = d.y * inv * g4.y + b4.y;
        o4.z = d.z * inv * g4.z + b4.z;
        o4.w = d.w * inv * g4.w + b4.w;
        *(float4*)&sA[t * 132 + td * 4] = o4;
    }
    __syncthreads();

    // GEMM2: xf = x2 + bm + xln @ Wm^T
    #pragma unroll
    for (int dc = 0; dc < 4; dc++) {
        for (int i = tid; i < 32 * 32; i += 256) {
            int r = i >> 5, c4 = i & 31;
            *(float4*)&sW[r * 132 + c4 * 4] =
                __ldg((const float4*)&Wm[(size_t)(dc * 32 + r) * CH + c4 * 4]);
        }
        __syncthreads();
        float acc[4] = {0.f, 0.f, 0.f, 0.f};
        #pragma unroll 4
        for (int c4 = 0; c4 < 32; c4++) {
            float4 wv = *(float4*)&sW[td * 132 + c4 * 4];
            #pragma unroll
            for (int i = 0; i < 4; i++) {
                float4 xv = *(float4*)&sA[(tt * 4 + i) * 132 + c4 * 4];
                acc[i] += xv.x*wv.x + xv.y*wv.y + xv.z*wv.z + xv.w*wv.w;
            }
        }
        float bmv = __ldg(&bm[dc * 32 + td]);
        #pragma unroll
        for (int i = 0; i < 4; i++)
            g_xf[(size_t)(t0 + tt * 4 + i) * CH + dc * 32 + td] = x2r[dc][i] + bmv + acc[i];
        __syncthreads();
    }
}

// ==================== K4: LM head GEMM (cp.async B, TS-mode MMA) ====================
#if defined(__CUDA_ARCH__) && (__CUDA_ARCH__ == 1030) && defined(__CUDA_ARCH_FEAT_SM103_ALL)
#define HAS_TCGEN05 1
#else
#define HAS_TCGEN05 0
#endif

__device__ __forceinline__ uint32_t s2u(const void* p) {
    uint32_t a;
    asm("{ .reg .u64 t; cvta.to.shared.u64 t, %1; cvt.u32.u64 %0, t; }" : "=r"(a) : "l"(p));
    return a;
}

#define K4T 512
#define SMB0 0
#define SMB1 65536
#define SCR  131072
#define K4_SMEM 196608

#define TM_D0 0
#define TM_D1 128
#define TM_A  256

#if HAS_TCGEN05

__device__ __forceinline__ bool elect1() {
    uint32_t p;
    asm volatile("{ .reg .pred p; elect.sync _|p, 0xFFFFFFFF; selp.b32 %0, 1, 0, p; }" : "=r"(p));
    return p != 0;
}
__device__ __forceinline__ void mbar_init(uint32_t a, uint32_t cnt) {
    asm volatile("mbarrier.init.shared.b64 [%0], %1;" :: "r"(a), "r"(cnt) : "memory");
}
__device__ __forceinline__ void mbar_wait(uint32_t a, uint32_t ph) {
    asm volatile(
        "{\n\t.reg .pred P;\n"
        "W_%=:\n\t"
        "mbarrier.try_wait.parity.acquire.cta.shared::cta.b64 P, [%0], %1, 0x989680;\n\t"
        "@P bra D_%=;\n\t"
        "bra W_%=;\n"
        "D_%=:\n\t}"
        :: "r"(a), "r"(ph) : "memory");
}
__device__ __forceinline__ void sts128(uint32_t a, uint32_t r0, uint32_t r1, uint32_t r2, uint32_t r3) {
    asm volatile("st.shared.v4.b32 [%0], {%1, %2, %3, %4};" :: "r"(a), "r"(r0), "r"(r1), "r"(r2), "r"(r3) : "memory");
}
__device__ __forceinline__ void mma_tf32_ts(uint32_t d, uint32_t a, uint64_t bd, uint32_t idesc, bool accum) {
    uint32_t en = accum ? 1u : 0u;
    asm volatile(
        "{\n\t.reg .pred p;\n\t"
        "setp.ne.u32 p, %5, 0;\n\t"
        "tcgen05.mma.cta_group::1.kind::tf32 [%0], [%1], %2, %3, {%4, %4, %4, %4}, p;\n\t}"
        :: "r"(d), "r"(a), "l"(bd), "r"(idesc), "r"(0u), "r"(en) : "memory");
}
__device__ __forceinline__ void mma_commit(uint32_t mbar) {
    asm volatile("tcgen05.commit.cta_group::1.mbarrier::arrive::one.shared::cluster.b64 [%0];" :: "r"(mbar) : "memory");
}
__device__ __forceinline__ uint64_t mk_desc(uint32_t addr) {
    const uint64_t base = (uint64_t(2) << 61) | (uint64_t(1) << 46) | (uint64_t(64) << 32) | (uint64_t(1) << 16);
    return base | ((uint64_t)(addr >> 4) & 0x3FFF);
}

#define LDTM32(r, a) \
    asm volatile( \
        "tcgen05.ld.sync.aligned.32x32b.x32.b32 " \
        "{%0, %1, %2, %3, %4, %5, %6, %7, " \
        " %8, %9, %10, %11, %12, %13, %14, %15, " \
        " %16, %17, %18, %19, %20, %21, %22, %23, " \
        " %24, %25, %26, %27, %28, %29, %30, %31}, [%32];" \
        : "=r"((r)[0]),  "=r"((r)[1]),  "=r"((r)[2]),  "=r"((r)[3]), \
          "=r"((r)[4]),  "=r"((r)[5]),  "=r"((r)[6]),  "=r"((r)[7]), \
          "=r"((r)[8]),  "=r"((r)[9]),  "=r"((r)[10]), "=r"((r)[11]), \
          "=r"((r)[12]), "=r"((r)[13]), "=r"((r)[14]), "=r"((r)[15]), \
          "=r"((r)[16]), "=r"((r)[17]), "=r"((r)[18]), "=r"((r)[19]), \
          "=r"((r)[20]), "=r"((r)[21]), "=r"((r)[22]), "=r"((r)[23]), \
          "=r"((r)[24]), "=r"((r)[25]), "=r"((r)[26]), "=r"((r)[27]), \
          "=r"((r)[28]), "=r"((r)[29]), "=r"((r)[30]), "=r"((r)[31]) \
        : "r"(a))

#define STTM32(a, r) \
    asm volatile( \
        "tcgen05.st.sync.aligned.32x32b.x32.b32 [%0], " \
        "{%1, %2, %3, %4, %5, %6, %7, %8, " \
        " %9, %10, %11, %12, %13, %14, %15, %16, " \
        " %17, %18, %19, %20, %21, %22, %23, %24, " \
        " %25, %26, %27, %28, %29, %30, %31, %32};" \
        :: "r"(a), \
           "r"((r)[0]),  "r"((r)[1]),  "r"((r)[2]),  "r"((r)[3]), \
           "r"((r)[4]),  "r"((r)[5]),  "r"((r)[6]),  "r"((r)[7]), \
           "r"((r)[8]),  "r"((r)[9]),  "r"((r)[10]), "r"((r)[11]), \
           "r"((r)[12]), "r"((r)[13]), "r"((r)[14]), "r"((r)[15]), \
           "r"((r)[16]), "r"((r)[17]), "r"((r)[18]), "r"((r)[19]), \
           "r"((r)[20]), "r"((r)[21]), "r"((r)[22]), "r"((r)[23]), \
           "r"((r)[24]), "r"((r)[25]), "r"((r)[26]), "r"((r)[27]), \
           "r"((r)[28]), "r"((r)[29]), "r"((r)[30]), "r"((r)[31]) \
        : "memory")

#define K4_IDESC ((1u<<4) | (2u<<7) | (2u<<10) | (16u<<17) | (8u<<24))

__device__ __forceinline__ void k4_load_tile_ca(uint32_t sdst, int row0, int tid)
{
    #pragma unroll
    for (int it = 0; it < 8; it++) {
        int f = tid + it * K4T;
        int r = f >> 5, q = f & 31;
        int kc = q >> 3, c4 = q & 7;
        uint32_t off = (uint32_t)(kc * 16384 + r * 128 + c4 * 16);
        off = off ^ ((off >> 3) & 0x70);
        int row = row0 + r;
        int ok = (row < VSZ);
        const float* gsrc = &g_wtf[(size_t)(ok ? row : 0) * CH + q * 4];
        int sz = ok ? 16 : 0;
        asm volatile("cp.async.cg.shared.global [%0], [%1], 16, %2;"
                     :: "r"(sdst + off), "l"(gsrc), "r"(sz) : "memory");
    }
}

__device__ __forceinline__ void k4_epilogue(uint32_t dt, float* __restrict__ scr,
                                            int m0, int n0,
                                            float* __restrict__ out, int tid)
{
    int w = tid >> 5, lid = tid & 31;
    int row = (w & 3) * 32 + lid;
    int cb  = (w >> 2) * 32;
    uint32_t scr_u = s2u(scr);

    {
        uint32_t r[32];
        LDTM32(r, dt + cb);
        asm volatile("tcgen05.wait::ld.sync.aligned;" ::: "memory");
        #pragma unroll
        for (int gq = 0; gq < 8; gq++) {
            int cg = (cb >> 2) + gq;
            int sg = cg ^ (row & 31);
            sts128(scr_u + (uint32_t)(row * 128 + sg * 4) * 4,
                   r[4*gq], r[4*gq+1], r[4*gq+2], r[4*gq+3]);
        }
    }
    __syncthreads();

    if (n0 + 128 <= VSZ) {
        #pragma unroll
        for (int itr = 0; itr < 8; itr++) {
            int r2 = w * 8 + itr;
            int m  = m0 + r2;
            int c0 = (4 - (m & 3)) & 3;
            int sw = r2 & 31;
            float* orow = out + (size_t)m * VSZ + n0;
            int j = c0 + 4 * lid;
            if (j + 3 < 128) {
                float4 v;
                float* vp = &v.x;
                #pragma unroll
                for (int k = 0; k < 4; k++) {
                    int col = j + k;
                    int sg2 = (col >> 2) ^ sw;
                    vp[k] = scr[r2 * 128 + sg2 * 4 + (col & 3)];
                }
                *(float4*)(orow + j) = v;
            }
            if (c0 && lid < 4) {
                int col = (lid < c0) ? lid : (c0 + 124 + (lid - c0));
                int sg2 = (col >> 2) ^ sw;
                orow[col] = scr[r2 * 128 + sg2 * 4 + (col & 3)];
            }
        }
    } else {
        for (int itr = 0; itr < 8; itr++) {
            int r2 = w * 8 + itr;
            int sw = r2 & 31;
            float* orow = out + (size_t)(m0 + r2) * VSZ;
            #pragma unroll
            for (int k = 0; k < 4; k++) {
                int col = lid + 32 * k;
                if (n0 + col < VSZ) {
                    int sg2 = (col >> 2) ^ sw;
                    orow[n0 + col] = scr[r2 * 128 + sg2 * 4 + (col & 3)];
                }
            }
        }
    }
}
#endif  // HAS_TCGEN05

__global__ void __launch_bounds__(K4T, 1) k4mma(const float* __restrict__ Wlm,
                                                float* __restrict__ out)
{
    extern __shared__ __align__(1024) char smem[];
    int tid = threadIdx.x;
    int m0 = blockIdx.x * 128;
    int g  = blockIdx.y;
    int nt = (NTILES - 1 - g) / 4 + 1;

#if HAS_TCGEN05
    __shared__ __align__(16) unsigned long long s_mbar[2];
    __shared__ uint32_t s_tmem;

    int wid = tid >> 5;
    uint32_t sb = s2u(smem);
    float* scr = (float*)(smem + SCR);
    uint32_t mb[2] = { s2u(&s_mbar[0]), s2u(&s_mbar[1]) };

    if (wid == 0) {
        asm volatile("tcgen05.alloc.cta_group::1.sync.aligned.shared::cta.b32 [%0], %1;"
                     :: "r"(s2u(&s_tmem)), "r"(512u) : "memory");
        asm volatile("tcgen05.relinquish_alloc_permit.cta_group::1.sync.aligned;");
    }
    if (tid == 0) { mbar_init(mb[0], 1); mbar_init(mb[1], 1); }
    __syncthreads();
    uint32_t tmem;
    asm volatile("ld.shared.b32 %0, [%1];" : "=r"(tmem) : "r"(s2u(&s_tmem)));

    k4_load_tile_ca(sb + SMB0, g * 128, tid);
    asm volatile("cp.async.commit_group;" ::: "memory");

    if (tid < 128) {
        uint32_t warp_off = (uint32_t)(tid >> 5) << 21;
        const float* arow = &g_xf[(size_t)(m0 + tid) * CH];
        #pragma unroll
        for (int q = 0; q < 4; q++) {
            uint32_t ar[32];
            #pragma unroll
            for (int j = 0; j < 32; j++) ar[j] = f2tf(arow[q * 32 + j]);
            STTM32(tmem + TM_A + q * 32 + warp_off, ar);
        }
        asm volatile("tcgen05.wait::st.sync.aligned;" ::: "memory");
        asm volatile("tcgen05.fence::before_thread_sync;" ::: "memory");
    }

    uint64_t bdesc[2] = { mk_desc(sb + SMB0), mk_desc(sb + SMB1) };
    int ph[2] = {0, 0};

    for (int i = 0; i < nt; i++) {
        int b = i & 1, pb = b ^ 1;

        asm volatile("cp.async.wait_group 0;" ::: "memory");
        asm volatile("fence.proxy.async.shared::cta;" ::: "memory");
        __syncthreads();

        if (wid == 0 && elect1()) {
            asm volatile("tcgen05.fence::after_thread_sync;" ::: "memory");
            uint32_t dreg = tmem + (uint32_t)(b ? TM_D1 : TM_D0);
            #pragma unroll
            for (int s = 0; s < 16; s++) {
                uint64_t koff = (uint64_t)((s >> 2) * 1024 + (s & 3) * 2);
                mma_tf32_ts(dreg, tmem + TM_A + s * 8, bdesc[b] + koff, K4_IDESC, s > 0);
            }
            mma_commit(mb[b]);
        }

        if (i >= 1) {
            mbar_wait(mb[pb], ph[pb]); ph[pb] ^= 1;
            if (i + 1 < nt) {
                k4_load_tile_ca(sb + (pb ? SMB1 : SMB0), (g + 4 * (i + 1)) * 128, tid);
                asm volatile("cp.async.commit_group;" ::: "memory");
            }
            asm volatile("tcgen05.fence::after_thread_sync;" ::: "memory");
            k4_epilogue(tmem + (pb ? TM_D1 : TM_D0), scr, m0,
                        (g + 4 * (i - 1)) * 128, out, tid);
        } else if (nt > 1) {
            k4_load_tile_ca(sb + SMB1, (g + 4) * 128, tid);
            asm volatile("cp.async.commit_group;" ::: "memory");
        }
    }

    {
        int b = (nt - 1) & 1;
        mbar_wait(mb[b], ph[b]);
        asm volatile("tcgen05.fence::after_thread_sync;" ::: "memory");
        __syncthreads();
        k4_epilogue(tmem + (b ? TM_D1 : TM_D0), scr, m0,
                    (g + 4 * (nt - 1)) * 128, out, tid);
    }

    __syncthreads();
    if (wid == 0) {
        asm volatile("tcgen05.dealloc.cta_group::1.sync.aligned.b32 %0, %1;"
                     :: "r"(tmem), "r"(512u));
    }
#else
    // -------- fallback: plain fp32 smem GEMM (baseline sm_103 target) --------
    float* sA = (float*)(smem + SCR);
    float* sB = (float*)(smem + SMB0);

    for (int i = tid; i < 128 * 32; i += K4T) {
        int r = i >> 5, q = i & 31;
        *(float4*)&sA[r * 128 + q * 4] = *(const float4*)&g_xf[(size_t)(m0 + r) * CH + q * 4];
    }

    int tx = tid & 31, ty = tid >> 5;

    for (int t = 0; t < nt; t++) {
        int n0 = (g + 4 * t) * 128;
        __syncthreads();
        for (int i = tid; i < 128 * 32; i += K4T) {
            int r = i >> 5, q = i & 31;
            float4 v = make_float4(0.f, 0.f, 0.f, 0.f);
            if (n0 + r < VSZ)
                v = *(const float4*)&Wlm[(size_t)(n0 + r) * CH + q * 4];
            *(float4*)&sB[r * 128 + q * 4] = v;
        }
        __syncthreads();

        float acc[8][4];
        #pragma unroll
        for (int i = 0; i < 8; i++)
            #pragma unroll
            for (int j = 0; j < 4; j++) acc[i][j] = 0.f;

        for (int k = 0; k < 128; k++) {
            float a[8], b[4];
            #pragma unroll
            for (int i = 0; i < 8; i++) a[i] = sA[(ty * 8 + i) * 128 + k];
            #pragma unroll
            for (int j = 0; j < 4; j++) b[j] = sB[(tx * 4 + j) * 128 + k];
            #pragma unroll
            for (int i = 0; i < 8; i++)
                #pragma unroll
                for (int j = 0; j < 4; j++) acc[i][j] += a[i] * b[j];
        }

        #pragma unroll
        for (int i = 0; i < 8; i++) {
            float* row = out + (size_t)(m0 + ty * 8 + i) * VSZ;
            #pragma unroll
            for (int j = 0; j < 4; j++) {
                int n = n0 + tx * 4 + j;
                if (n < VSZ) row[n] = acc[i][j];
            }
        }
    }
#endif
}

// ==================== launch ====================
extern "C" void kernel_launch(void* const* d_in, const int* in_sizes, int n_in,
                              void* d_out, int out_size)
{
    const int*   ids    = (const int*)  d_in[0];
    const float* emb    = (const float*)d_in[1];
    const float* router = (const float*)d_in[2];
    const float* kexp   = (const float*)d_in[3];
    const float* vexp   = (const float*)d_in[4];
    const float* skv    = (const float*)d_in[5];
    const float* svv    = (const float*)d_in[6];
    const float* kvg    = (const float*)d_in[7];
    const float* Wq     = (const float*)d_in[8];
    const float* Wo     = (const float*)d_in[9];
    const float* Wm     = (const float*)d_in[10];
    const float* bm     = (const float*)d_in[11];
    const float* g1     = (const float*)d_in[12];
    const float* b1     = (const float*)d_in[13];
    const float* g2     = (const float*)d_in[14];
    const float* b2     = (const float*)d_in[15];
    const float* Wlm    = (const float*)d_in[16];

    float* out = (float*)d_out;
    float* gate_out = out + ((size_t)out_size - (size_t)TNUM * NE);

    cudaFuncSetAttribute(k4mma, cudaFuncAttributeMaxDynamicSharedMemorySize, K4_SMEM);

    k0<<<((VSZ*CH/4) + 511) / 512, 512>>>(Wlm);
    k1<<<TNUM/TB1, 256>>>(ids, emb, router, Wq, g1, b1, gate_out);
    k2<<<TNUM/TB, 256>>>(kexp, vexp, skv, svv, kvg);
    k3<<<TNUM/TB3, 256>>>(Wo, Wm, bm, g2, b2);
    dim3 g4(TNUM/128, 4);
    k4mma<<<g4, K4T, K4_SMEM>>>(Wlm, out);
}

// round 12
// speedup vs baseline: 1.7746x; 1.2012x over previous
#include <cuda_runtime.h>
#include <math.h>
#include <stdint.h>

#define TNUM 4096
#define CH 128
#define NE 16
#define KB 32
#define VSZ 50257
#define NTILES 393   // ceil(50257/128)

// scratch (static device arrays — no allocation)
__device__ float g_x [TNUM*CH];
__device__ float g_q [TNUM*CH];
__device__ float g_rw[TNUM*NE];
__device__ float g_ao[TNUM*CH];
__device__ float g_xf[TNUM*CH];
__device__ float g_wtf[VSZ*CH];   // Wlm pre-rounded to tf32 (RNA), 25.7MB

__device__ __forceinline__ uint32_t f2tf(float f) {
    uint32_t r; asm("cvt.rna.tf32.f32 %0, %1;" : "=r"(r) : "f"(f)); return r;
}
__device__ __forceinline__ uint32_t s2u(const void* p) {
    uint32_t a;
    asm("{ .reg .u64 t; cvta.to.shared.u64 t, %1; cvt.u32.u64 %0, t; }" : "=r"(a) : "l"(p));
    return a;
}

// ==================== K0: Wlm -> tf32-rounded copy ====================
__global__ __launch_bounds__(512) void k0(const float* __restrict__ Wlm)
{
    int i = blockIdx.x * 512 + threadIdx.x;          // float4 index
    const int n4 = (VSZ * CH) / 4;
    if (i < n4) {
        float4 v = *(const float4*)&Wlm[(size_t)i * 4];
        uint4 o;
        o.x = f2tf(v.x); o.y = f2tf(v.y); o.z = f2tf(v.z); o.w = f2tf(v.w);
        *(uint4*)&g_wtf[(size_t)i * 4] = o;
    }
}

// ==================== K1: embed + LN1 + routing + q (token-tiled) ====================
#define TB1 32
__global__ __launch_bounds__(256) void k1(const int* __restrict__ ids,
        const float* __restrict__ emb, const float* __restrict__ router,
        const float* __restrict__ Wq, const float* __restrict__ g1,
        const float* __restrict__ b1, float* __restrict__ gate_out)
{
    __shared__ float sXL[TB1*132];
    __shared__ float sW [32*132];
    __shared__ float sGL[TB1][17];

    int t0 = blockIdx.x * TB1;
    int tid = threadIdx.x;
    int wid = tid >> 5, lid = tid & 31;

    #pragma unroll
    for (int i = 0; i < 4; i++) {
        int t = wid * 4 + i;
        int id = ids[t0 + t];
        float4 v = __ldg((const float4*)&emb[(size_t)id * CH + lid * 4]);
        *(float4*)&g_x[(size_t)(t0 + t) * CH + lid * 4] = v;
        float s = v.x + v.y + v.z + v.w;
        #pragma unroll
        for (int o = 16; o; o >>= 1) s += __shfl_xor_sync(0xffffffffu, s, o);
        float mu = s * (1.f/128.f);
        float4 d; d.x = v.x - mu; d.y = v.y - mu; d.z = v.z - mu; d.w = v.w - mu;
        float q2 = d.x*d.x + d.y*d.y + d.z*d.z + d.w*d.w;
        #pragma unroll
        for (int o = 16; o; o >>= 1) q2 += __shfl_xor_sync(0xffffffffu, q2, o);
        float inv = rsqrtf(q2 * (1.f/128.f) + 1e-5f);
        float4 g4 = __ldg((const float4*)&g1[lid * 4]);
        float4 b4 = __ldg((const float4*)&b1[lid * 4]);
        float4 o4;
        o4.x = d.x * inv * g4.x + b4.x;
        o4.y = d.y * inv * g4.y + b4.y;
        o4.z = d.z * inv * g4.z + b4.z;
        o4.w = d.w * inv * g4.w + b4.w;
        *(float4*)&sXL[t * 132 + lid * 4] = o4;
    }
    for (int i = tid; i < 16 * 32; i += 256) {
        int e = i >> 5, c4 = i & 31;
        *(float4*)&sW[e * 132 + c4 * 4] = __ldg((const float4*)&router[(size_t)e * CH + c4 * 4]);
    }
    __syncthreads();

    {
        int t = tid >> 3, eg = tid & 7;
        float a0 = 0.f, a1 = 0.f;
        #pragma unroll 8
        for (int c4 = 0; c4 < 32; c4++) {
            float4 xv = *(float4*)&sXL[t * 132 + c4 * 4];
            float4 r0 = *(float4*)&sW[(2*eg)   * 132 + c4 * 4];
            float4 r1 = *(float4*)&sW[(2*eg+1) * 132 + c4 * 4];
            a0 += xv.x*r0.x + xv.y*r0.y + xv.z*r0.z + xv.w*r0.w;
            a1 += xv.x*r1.x + xv.y*r1.y + xv.z*r1.z + xv.w*r1.w;
        }
        sGL[t][2*eg] = a0; sGL[t][2*eg+1] = a1;
    }
    __syncthreads();

    for (int i = tid; i < TB1 * NE; i += 256)
        gate_out[(size_t)t0 * NE + i] = sGL[i >> 4][i & 15];
    if (tid < TB1) {
        float mx = -1e30f;
        #pragma unroll
        for (int e = 0; e < NE; e++) mx = fmaxf(mx, sGL[tid][e]);
        float ss = 0.f;
        #pragma unroll
        for (int e = 0; e < NE; e++) ss += __expf(sGL[tid][e] - mx);
        float inv = 1.f / ss;
        #pragma unroll
        for (int e = 0; e < NE; e++)
            g_rw[(size_t)(t0 + tid) * NE + e] = __expf(sGL[tid][e] - mx) * inv;
    }
    __syncthreads();

    int td = tid & 31, tt = tid >> 5;
    #pragma unroll
    for (int dc = 0; dc < 4; dc++) {
        for (int i = tid; i < 32 * 32; i += 256) {
            int r = i >> 5, c4 = i & 31;
            *(float4*)&sW[r * 132 + c4 * 4] =
                __ldg((const float4*)&Wq[(size_t)(dc * 32 + r) * CH + c4 * 4]);
        }
        __syncthreads();
        float acc[4] = {0.f, 0.f, 0.f, 0.f};
        #pragma unroll 4
        for (int c4 = 0; c4 < 32; c4++) {
            float4 wv = *(float4*)&sW[td * 132 + c4 * 4];
            #pragma unroll
            for (int i = 0; i < 4; i++) {
                float4 xv = *(float4*)&sXL[(tt * 4 + i) * 132 + c4 * 4];
                acc[i] += xv.x*wv.x + xv.y*wv.y + xv.z*wv.z + xv.w*wv.w;
            }
        }
        #pragma unroll
        for (int i = 0; i < 4; i++)
            g_q[(size_t)(t0 + tt * 4 + i) * CH + dc * 32 + td] = acc[i];
        __syncthreads();
    }
}

// ==================== K2: expert attention (cp.async 3-buffer pipeline) ====================
#define TB 32
#define QSTR 132
// dynamic smem layout (floats): sQ@0 (4224), buf0@4224, buf1@8448, buf2@12672,
// sS@16896 (32*33), sRW@17952 (512). total 18464 floats = 73856 B
#define K2_SMEM 73856

__device__ __forceinline__ void k2_issue(const float* __restrict__ src, float* dst, int tid) {
    #pragma unroll
    for (int it = 0; it < 4; it++) {
        int i = tid + it * 256;
        int r = i >> 5, c4 = i & 31;
        uint32_t d = s2u(&dst[r * QSTR + c4 * 4]);
        asm volatile("cp.async.cg.shared.global [%0], [%1], 16;"
                     :: "r"(d), "l"(src + r * CH + c4 * 4) : "memory");
    }
    asm volatile("cp.async.commit_group;" ::: "memory");
}

__global__ __launch_bounds__(256) void k2(const float* __restrict__ kexp,
        const float* __restrict__ vexp, const float* __restrict__ skv,
        const float* __restrict__ svv, const float* __restrict__ kvg)
{
    extern __shared__ float sm2[];
    float* sQ  = sm2;
    float* sS  = sm2 + 16896;   // [32][33]
    float* sRW = sm2 + 17952;

    int t0 = blockIdx.x * TB;
    int tid = threadIdx.x;
    float g = 1.f / (1.f + __expf(-kvg[0]));

    for (int i = tid; i < TB * 32; i += 256) {
        int t = i >> 5, c4 = i & 31;
        *(float4*)&sQ[t * QSTR + c4 * 4] = *(const float4*)&g_q[(size_t)(t0 + t) * CH + c4 * 4];
    }
    for (int i = tid; i < TB * NE; i += 256) sRW[i] = g_rw[(size_t)t0 * NE + i];

    int t = tid >> 3, kg = tid & 7;
    float sdyn[4] = {0,0,0,0}, sstat[4] = {0,0,0,0};

    // ---- K pass: tiles e=0..15 are experts, e=16 is static K ----
    k2_issue(kexp, sm2 + 4224, tid);
    for (int e = 0; e <= NE; e++) {
        if (e + 1 <= NE) {
            const float* s = (e + 1 < NE) ? kexp + (size_t)(e + 1) * KB * CH : skv;
            k2_issue(s, sm2 + 4224 + ((e + 1) % 3) * 4224, tid);
            asm volatile("cp.async.wait_group 1;" ::: "memory");
        } else {
            asm volatile("cp.async.wait_group 0;" ::: "memory");
        }
        __syncthreads();
        const float* bf = sm2 + 4224 + (e % 3) * 4224;
        float dj[4] = {0,0,0,0};
        const float4* qp = (const float4*)(sQ + t * QSTR);
        #pragma unroll 4
        for (int c4 = 0; c4 < 32; c4++) {
            float4 qv = qp[c4];
            #pragma unroll
            for (int j = 0; j < 4; j++) {
                float4 kv = *(const float4*)(bf + (kg + 8*j) * QSTR + 4 * c4);
                dj[j] += qv.x*kv.x + qv.y*kv.y + qv.z*kv.z + qv.w*kv.w;
            }
        }
        if (e < NE) {
            float rwv = sRW[t * NE + e];
            #pragma unroll
            for (int j = 0; j < 4; j++) sdyn[j] += rwv * dj[j];
        } else {
            #pragma unroll
            for (int j = 0; j < 4; j++) sstat[j] = dj[j];
        }
    }

    const float scale = 0.08838834764831845f; // 1/sqrt(128)
    #pragma unroll
    for (int j = 0; j < 4; j++)
        sS[t * 33 + kg + 8*j] = (g * sdyn[j] + (1.f - g) * sstat[j]) * scale;
    __syncthreads();

    // start V(0) load while softmax runs
    k2_issue(vexp, sm2 + 4224, tid);

    if (tid < TB) {
        float mx = -1e30f;
        #pragma unroll
        for (int k = 0; k < KB; k++) mx = fmaxf(mx, sS[tid * 33 + k]);
        float ssum = 0.f;
        #pragma unroll
        for (int k = 0; k < KB; k++) { float ev = __expf(sS[tid * 33 + k] - mx); sS[tid * 33 + k] = ev; ssum += ev; }
        float inv = 1.f / ssum;
        #pragma unroll
        for (int k = 0; k < KB; k++) sS[tid * 33 + k] *= inv;
    }
    __syncthreads();

    // ---- V pass ----
    float acc[16];
    #pragma unroll
    for (int i = 0; i < 16; i++) acc[i] = 0.f;

    for (int e = 0; e <= NE; e++) {
        if (e + 1 <= NE) {
            const float* s = (e + 1 < NE) ? vexp + (size_t)(e + 1) * KB * CH : svv;
            k2_issue(s, sm2 + 4224 + ((e + 1) % 3) * 4224, tid);
            asm volatile("cp.async.wait_group 1;" ::: "memory");
        } else {
            asm volatile("cp.async.wait_group 0;" ::: "memory");
        }
        __syncthreads();
        const float* bf = sm2 + 4224 + (e % 3) * 4224;
        float we = (e < NE) ? g * sRW[t * NE + e] : (1.f - g);
        #pragma unroll 4
        for (int k = 0; k < KB; k++) {
            float w = we * sS[t * 33 + k];
            #pragma unroll
            for (int j = 0; j < 4; j++) {
                float4 vv = *(const float4*)(bf + k * QSTR + 4 * (kg + 8*j));
                acc[j*4+0] += w*vv.x; acc[j*4+1] += w*vv.y;
                acc[j*4+2] += w*vv.z; acc[j*4+3] += w*vv.w;
            }
        }
    }
    #pragma unroll
    for (int j = 0; j < 4; j++) {
        float4 o;
        o.x = acc[j*4+0]; o.y = acc[j*4+1]; o.z = acc[j*4+2]; o.w = acc[j*4+3];
        *(float4*)&g_ao[(size_t)(t0 + t) * CH + 4 * (kg + 8*j)] = o;
    }
}

// ==================== K3: Wo+res+LN2+MLP+res (token-tiled GEMM) ====================
#define TB3 32
__global__ __launch_bounds__(256) void k3(const float* __restrict__ Wo,
        const float* __restrict__ Wm, const float* __restrict__ bm,
        const float* __restrict__ g2, const float* __restrict__ b2)
{
    __shared__ float sA[TB3*132];
    __shared__ float sW[32*132];

    int t0 = blockIdx.x * TB3;
    int tid = threadIdx.x;
    int td = tid & 31, tt = tid >> 5;

    for (int i = tid; i < TB3 * 32; i += 256) {
        int t = i >> 5, c4 = i & 31;
        *(float4*)&sA[t * 132 + c4 * 4] = *(const float4*)&g_ao[(size_t)(t0 + t) * CH + c4 * 4];
    }
    __syncthreads();

    float x2r[4][4];
    #pragma unroll
    for (int dc = 0; dc < 4; dc++) {
        for (int i = tid; i < 32 * 32; i += 256) {
            int r = i >> 5, c4 = i & 31;
            *(float4*)&sW[r * 132 + c4 * 4] =
                __ldg((const float4*)&Wo[(size_t)(dc * 32 + r) * CH + c4 * 4]);
        }
        __syncthreads();
        float acc[4] = {0.f, 0.f, 0.f, 0.f};
        #pragma unroll 4
        for (int c4 = 0; c4 < 32; c4++) {
            float4 wv = *(float4*)&sW[td * 132 + c4 * 4];
            #pragma unroll
            for (int i = 0; i < 4; i++) {
                float4 xv = *(float4*)&sA[(tt * 4 + i) * 132 + c4 * 4];
                acc[i] += xv.x*wv.x + xv.y*wv.y + xv.z*wv.z + xv.w*wv.w;
            }
        }
        #pragma unroll
        for (int i = 0; i < 4; i++)
            x2r[dc][i] = acc[i] + g_x[(size_t)(t0 + tt * 4 + i) * CH + dc * 32 + td];
        __syncthreads();
    }

    #pragma unroll
    for (int dc = 0; dc < 4; dc++)
        #pragma unroll
        for (int i = 0; i < 4; i++)
            sA[(tt * 4 + i) * 132 + dc * 32 + td] = x2r[dc][i];
    __syncthreads();

    #pragma unroll
    for (int i = 0; i < 4; i++) {
        int t = tt * 4 + i;
        float4 v = *(float4*)&sA[t * 132 + td * 4];
        float s = v.x + v.y + v.z + v.w;
        #pragma unroll
        for (int o = 16; o; o >>= 1) s += __shfl_xor_sync(0xffffffffu, s, o);
        float mu = s * (1.f/128.f);
        float4 d; d.x = v.x - mu; d.y = v.y - mu; d.z = v.z - mu; d.w = v.w - mu;
        float q2 = d.x*d.x + d.y*d.y + d.z*d.z + d.w*d.w;
        #pragma unroll
        for (int o = 16; o; o >>= 1) q2 += __shfl_xor_sync(0xffffffffu, q2, o);
        float inv = rsqrtf(q2 * (1.f/128.f) + 1e-5f);
        float4 g4 = __ldg((const float4*)&g2[td * 4]);
        float4 b4 = __ldg((const float4*)&b2[td * 4]);
        float4 o4;
        o4.x = d.x * inv * g4.x + b4.x;
        o4.y = d.y * inv * g4.y + b4.y;
        o4.z = d.z * inv * g4.z + b4.z;
        o4.w = d.w * inv * g4.w + b4.w;
        *(float4*)&sA[t * 132 + td * 4] = o4;
    }
    __syncthreads();

    #pragma unroll
    for (int dc = 0; dc < 4; dc++) {
        for (int i = tid; i < 32 * 32; i += 256) {
            int r = i >> 5, c4 = i & 31;
            *(float4*)&sW[r * 132 + c4 * 4] =
                __ldg((const float4*)&Wm[(size_t)(dc * 32 + r) * CH + c4 * 4]);
        }
        __syncthreads();
        float acc[4] = {0.f, 0.f, 0.f, 0.f};
        #pragma unroll 4
        for (int c4 = 0; c4 < 32; c4++) {
            float4 wv = *(float4*)&sW[td * 132 + c4 * 4];
            #pragma unroll
            for (int i = 0; i < 4; i++) {
                float4 xv = *(float4*)&sA[(tt * 4 + i) * 132 + c4 * 4];
                acc[i] += xv.x*wv.x + xv.y*wv.y + xv.z*wv.z + xv.w*wv.w;
            }
        }
        float bmv = __ldg(&bm[dc * 32 + td]);
        #pragma unroll
        for (int i = 0; i < 4; i++)
            g_xf[(size_t)(t0 + tt * 4 + i) * CH + dc * 32 + td] = x2r[dc][i] + bmv + acc[i];
        __syncthreads();
    }
}

// ==================== K4: LM head GEMM (persistent, cp.async B, TS-mode MMA) ====================
#if defined(__CUDA_ARCH__) && (__CUDA_ARCH__ == 1030) && defined(__CUDA_ARCH_FEAT_SM103_ALL)
#define HAS_TCGEN05 1
#else
#define HAS_TCGEN05 0
#endif

#define K4T 512
#define K4GRID 148
#define K4TT (32 * NTILES)          // 12576 total tiles
#define K4CHUNK 85                  // ceil(12576/148)
#define SMB0 0
#define SMB1 65536
#define SCR  131072
#define K4_SMEM 196608

#define TM_D0 0
#define TM_D1 128
#define TM_A  256

#if HAS_TCGEN05

__device__ __forceinline__ bool elect1() {
    uint32_t p;
    asm volatile("{ .reg .pred p; elect.sync _|p, 0xFFFFFFFF; selp.b32 %0, 1, 0, p; }" : "=r"(p));
    return p != 0;
}
__device__ __forceinline__ void mbar_init(uint32_t a, uint32_t cnt) {
    asm volatile("mbarrier.init.shared.b64 [%0], %1;" :: "r"(a), "r"(cnt) : "memory");
}
__device__ __forceinline__ void mbar_wait(uint32_t a, uint32_t ph) {
    asm volatile(
        "{\n\t.reg .pred P;\n"
        "W_%=:\n\t"
        "mbarrier.try_wait.parity.acquire.cta.shared::cta.b64 P, [%0], %1, 0x989680;\n\t"
        "@P bra D_%=;\n\t"
        "bra W_%=;\n"
        "D_%=:\n\t}"
        :: "r"(a), "r"(ph) : "memory");
}
__device__ __forceinline__ void sts128(uint32_t a, uint32_t r0, uint32_t r1, uint32_t r2, uint32_t r3) {
    asm volatile("st.shared.v4.b32 [%0], {%1, %2, %3, %4};" :: "r"(a), "r"(r0), "r"(r1), "r"(r2), "r"(r3) : "memory");
}
__device__ __forceinline__ void mma_tf32_ts(uint32_t d, uint32_t a, uint64_t bd, uint32_t idesc, bool accum) {
    uint32_t en = accum ? 1u : 0u;
    asm volatile(
        "{\n\t.reg .pred p;\n\t"
        "setp.ne.u32 p, %5, 0;\n\t"
        "tcgen05.mma.cta_group::1.kind::tf32 [%0], [%1], %2, %3, {%4, %4, %4, %4}, p;\n\t}"
        :: "r"(d), "r"(a), "l"(bd), "r"(idesc), "r"(0u), "r"(en) : "memory");
}
__device__ __forceinline__ void mma_commit(uint32_t mbar) {
    asm volatile("tcgen05.commit.cta_group::1.mbarrier::arrive::one.shared::cluster.b64 [%0];" :: "r"(mbar) : "memory");
}
__device__ __forceinline__ uint64_t mk_desc(uint32_t addr) {
    const uint64_t base = (uint64_t(2) << 61) | (uint64_t(1) << 46) | (uint64_t(64) << 32) | (uint64_t(1) << 16);
    return base | ((uint64_t)(addr >> 4) & 0x3FFF);
}

#define LDTM32(r, a) \
    asm volatile( \
        "tcgen05.ld.sync.aligned.32x32b.x32.b32 " \
        "{%0, %1, %2, %3, %4, %5, %6, %7, " \
        " %8, %9, %10, %11, %12, %13, %14, %15, " \
        " %16, %17, %18, %19, %20, %21, %22, %23, " \
        " %24, %25, %26, %27, %28, %29, %30, %31}, [%32];" \
        : "=r"((r)[0]),  "=r"((r)[1]),  "=r"((r)[2]),  "=r"((r)[3]), \
          "=r"((r)[4]),  "=r"((r)[5]),  "=r"((r)[6]),  "=r"((r)[7]), \
          "=r"((r)[8]),  "=r"((r)[9]),  "=r"((r)[10]), "=r"((r)[11]), \
          "=r"((r)[12]), "=r"((r)[13]), "=r"((r)[14]), "=r"((r)[15]), \
          "=r"((r)[16]), "=r"((r)[17]), "=r"((r)[18]), "=r"((r)[19]), \
          "=r"((r)[20]), "=r"((r)[21]), "=r"((r)[22]), "=r"((r)[23]), \
          "=r"((r)[24]), "=r"((r)[25]), "=r"((r)[26]), "=r"((r)[27]), \
          "=r"((r)[28]), "=r"((r)[29]), "=r"((r)[30]), "=r"((r)[31]) \
        : "r"(a))

#define STTM32(a, r) \
    asm volatile( \
        "tcgen05.st.sync.aligned.32x32b.x32.b32 [%0], " \
        "{%1, %2, %3, %4, %5, %6, %7, %8, " \
        " %9, %10, %11, %12, %13, %14, %15, %16, " \
        " %17, %18, %19, %20, %21, %22, %23, %24, " \
        " %25, %26, %27, %28, %29, %30, %31, %32};" \
        :: "r"(a), \
           "r"((r)[0]),  "r"((r)[1]),  "r"((r)[2]),  "r"((r)[3]), \
           "r"((r)[4]),  "r"((r)[5]),  "r"((r)[6]),  "r"((r)[7]), \
           "r"((r)[8]),  "r"((r)[9]),  "r"((r)[10]), "r"((r)[11]), \
           "r"((r)[12]), "r"((r)[13]), "r"((r)[14]), "r"((r)[15]), \
           "r"((r)[16]), "r"((r)[17]), "r"((r)[18]), "r"((r)[19]), \
           "r"((r)[20]), "r"((r)[21]), "r"((r)[22]), "r"((r)[23]), \
           "r"((r)[24]), "r"((r)[25]), "r"((r)[26]), "r"((r)[27]), \
           "r"((r)[28]), "r"((r)[29]), "r"((r)[30]), "r"((r)[31]) \
        : "memory")

#define K4_IDESC ((1u<<4) | (2u<<7) | (2u<<10) | (16u<<17) | (8u<<24))

__device__ __forceinline__ void k4_load_tile_ca(uint32_t sdst, int row0, int tid)
{
    #pragma unroll
    for (int it = 0; it < 8; it++) {
        int f = tid + it * K4T;
        int r = f >> 5, q = f & 31;
        int kc = q >> 3, c4 = q & 7;
        uint32_t off = (uint32_t)(kc * 16384 + r * 128 + c4 * 16);
        off = off ^ ((off >> 3) & 0x70);
        int row = row0 + r;
        int ok = (row < VSZ);
        const float* gsrc = &g_wtf[(size_t)(ok ? row : 0) * CH + q * 4];
        int sz = ok ? 16 : 0;
        asm volatile("cp.async.cg.shared.global [%0], [%1], 16, %2;"
                     :: "r"(sdst + off), "l"(gsrc), "r"(sz) : "memory");
    }
}

__device__ __forceinline__ void k4_epilogue(uint32_t dt, float* __restrict__ scr,
                                            int m0, int n0,
                                            float* __restrict__ out, int tid)
{
    int w = tid >> 5, lid = tid & 31;
    int row = (w & 3) * 32 + lid;
    int cb  = (w >> 2) * 32;
    uint32_t scr_u = s2u(scr);

    {
        uint32_t r[32];
        LDTM32(r, dt + cb);
        asm volatile("tcgen05.wait::ld.sync.aligned;" ::: "memory");
        #pragma unroll
        for (int gq = 0; gq < 8; gq++) {
            int cg = (cb >> 2) + gq;
            int sg = cg ^ (row & 31);
            sts128(scr_u + (uint32_t)(row * 128 + sg * 4) * 4,
                   r[4*gq], r[4*gq+1], r[4*gq+2], r[4*gq+3]);
        }
    }
    __syncthreads();

    if (n0 + 128 <= VSZ) {
        #pragma unroll
        for (int itr = 0; itr < 8; itr++) {
            int r2 = w * 8 + itr;
            int m  = m0 + r2;
            int c0 = (4 - (m & 3)) & 3;
            int sw = r2 & 31;
            float* orow = out + (size_t)m * VSZ + n0;
            int j = c0 + 4 * lid;
            if (j + 3 < 128) {
                float4 v;
                float* vp = &v.x;
                #pragma unroll
                for (int k = 0; k < 4; k++) {
                    int col = j + k;
                    int sg2 = (col >> 2) ^ sw;
                    vp[k] = scr[r2 * 128 + sg2 * 4 + (col & 3)];
                }
                *(float4*)(orow + j) = v;
            }
            if (c0 && lid < 4) {
                int col = (lid < c0) ? lid : (c0 + 124 + (lid - c0));
                int sg2 = (col >> 2) ^ sw;
                orow[col] = scr[r2 * 128 + sg2 * 4 + (col & 3)];
            }
        }
    } else {
        for (int itr = 0; itr < 8; itr++) {
            int r2 = w * 8 + itr;
            int sw = r2 & 31;
            float* orow = out + (size_t)(m0 + r2) * VSZ;
            #pragma unroll
            for (int k = 0; k < 4; k++) {
                int col = lid + 32 * k;
                if (n0 + col < VSZ) {
                    int sg2 = (col >> 2) ^ sw;
                    orow[n0 + col] = scr[r2 * 128 + sg2 * 4 + (col & 3)];
                }
            }
        }
    }
}
#endif  // HAS_TCGEN05

__global__ void __launch_bounds__(K4T, 1) k4mma(const float* __restrict__ Wlm,
                                                float* __restrict__ out)
{
    extern __shared__ __align__(1024) char smem[];
    int tid = threadIdx.x;
    int c = blockIdx.x;
    int T0 = c * K4CHUNK;
    int T1 = T0 + K4CHUNK; if (T1 > K4TT) T1 = K4TT;

#if HAS_TCGEN05
    __shared__ __align__(16) unsigned long long s_mbar[2];
    __shared__ uint32_t s_tmem;

    int wid = tid >> 5;
    uint32_t sb = s2u(smem);
    float* scr = (float*)(smem + SCR);
    uint32_t mb[2] = { s2u(&s_mbar[0]), s2u(&s_mbar[1]) };

    if (wid == 0) {
        asm volatile("tcgen05.alloc.cta_group::1.sync.aligned.shared::cta.b32 [%0], %1;"
                     :: "r"(s2u(&s_tmem)), "r"(512u) : "memory");
        asm volatile("tcgen05.relinquish_alloc_permit.cta_group::1.sync.aligned;");
    }
    if (tid == 0) { mbar_init(mb[0], 1); mbar_init(mb[1], 1); }
    __syncthreads();
    uint32_t tmem;
    asm volatile("ld.shared.b32 %0, [%1];" : "=r"(tmem) : "r"(s2u(&s_tmem)));

    uint64_t bdesc[2] = { mk_desc(sb + SMB0), mk_desc(sb + SMB1) };
    int ph[2] = {0, 0};
    int s = 0;   // global slot counter (B/D buffer parity)

    while (T0 < T1) {
        int m = T0 / NTILES;
        int n0idx = T0 - m * NTILES;
        int segend = (m + 1) * NTILES; if (segend > T1) segend = T1;
        int nt = segend - T0;
        int m0 = m * 128;

        // A(m) -> TMEM  (previous segment's MMAs fully drained by its final wait)
        if (tid < 128) {
            uint32_t warp_off = (uint32_t)(tid >> 5) << 21;
            const float* arow = &g_xf[(size_t)(m0 + tid) * CH];
            #pragma unroll
            for (int q = 0; q < 4; q++) {
                uint32_t ar[32];
                #pragma unroll
                for (int j = 0; j < 32; j++) ar[j] = f2tf(arow[q * 32 + j]);
                STTM32(tmem + TM_A + q * 32 + warp_off, ar);
            }
            asm volatile("tcgen05.wait::st.sync.aligned;" ::: "memory");
            asm volatile("tcgen05.fence::before_thread_sync;" ::: "memory");
        }
        // first B of segment into buffer (s&1)
        k4_load_tile_ca(sb + ((s & 1) ? SMB1 : SMB0), n0idx * 128, tid);
        asm volatile("cp.async.commit_group;" ::: "memory");

        for (int i = 0; i < nt; i++) {
            int b = s & 1, pb = b ^ 1;

            asm volatile("cp.async.wait_group 0;" ::: "memory");
            asm volatile("fence.proxy.async.shared::cta;" ::: "memory");
            __syncthreads();

            if (wid == 0 && elect1()) {
                asm volatile("tcgen05.fence::after_thread_sync;" ::: "memory");
                uint32_t dreg = tmem + (uint32_t)(b ? TM_D1 : TM_D0);
                #pragma unroll
                for (int st = 0; st < 16; st++) {
                    uint64_t koff = (uint64_t)((st >> 2) * 1024 + (st & 3) * 2);
                    mma_tf32_ts(dreg, tmem + TM_A + st * 8, bdesc[b] + koff, K4_IDESC, st > 0);
                }
                mma_commit(mb[b]);
            }

            if (i >= 1) {
                mbar_wait(mb[pb], ph[pb]); ph[pb] ^= 1;
                if (i + 1 < nt) {
                    k4_load_tile_ca(sb + (pb ? SMB1 : SMB0), (n0idx + i + 1) * 128, tid);
                    asm volatile("cp.async.commit_group;" ::: "memory");
                }
                asm volatile("tcgen05.fence::after_thread_sync;" ::: "memory");
                k4_epilogue(tmem + (pb ? TM_D1 : TM_D0), scr, m0,
                            (n0idx + i - 1) * 128, out, tid);
            } else if (nt > 1) {
                k4_load_tile_ca(sb + (pb ? SMB1 : SMB0), (n0idx + 1) * 128, tid);
                asm volatile("cp.async.commit_group;" ::: "memory");
            }
            s++;
        }

        // final tile epilogue of this segment
        {
            int bl = (s - 1) & 1;
            mbar_wait(mb[bl], ph[bl]); ph[bl] ^= 1;
            asm volatile("tcgen05.fence::after_thread_sync;" ::: "memory");
            __syncthreads();
            k4_epilogue(tmem + (bl ? TM_D1 : TM_D0), scr, m0,
                        (n0idx + nt - 1) * 128, out, tid);
        }
        T0 = segend;
    }

    __syncthreads();
    if (wid == 0) {
        asm volatile("tcgen05.dealloc.cta_group::1.sync.aligned.b32 %0, %1;"
                     :: "r"(tmem), "r"(512u));
    }
#else
    // -------- fallback: plain fp32 smem GEMM (baseline sm_103 target) --------
    float* sA = (float*)(smem + SCR);
    float* sB = (float*)(smem + SMB0);

    int tx = tid & 31, ty = tid >> 5;
    int mprev = -1;

    while (T0 < T1) {
        int m = T0 / NTILES;
        int n = T0 - m * NTILES;
        int m0 = m * 128, n0 = n * 128;

        __syncthreads();
        if (m != mprev) {
            for (int i = tid; i < 128 * 32; i += K4T) {
                int r = i >> 5, q = i & 31;
                *(float4*)&sA[r * 128 + q * 4] = *(const float4*)&g_xf[(size_t)(m0 + r) * CH + q * 4];
            }
            mprev = m;
        }
        for (int i = tid; i < 128 * 32; i += K4T) {
            int r = i >> 5, q = i & 31;
            float4 v = make_float4(0.f, 0.f, 0.f, 0.f);
            if (n0 + r < VSZ)
                v = *(const float4*)&Wlm[(size_t)(n0 + r) * CH + q * 4];
            *(float4*)&sB[r * 128 + q * 4] = v;
        }
        __syncthreads();

        float acc[8][4];
        #pragma unroll
        for (int i = 0; i < 8; i++)
            #pragma unroll
            for (int j = 0; j < 4; j++) acc[i][j] = 0.f;

        for (int k = 0; k < 128; k++) {
            float a[8], b[4];
            #pragma unroll
            for (int i = 0; i < 8; i++) a[i] = sA[(ty * 8 + i) * 128 + k];
            #pragma unroll
            for (int j = 0; j < 4; j++) b[j] = sB[(tx * 4 + j) * 128 + k];
            #pragma unroll
            for (int i = 0; i < 8; i++)
                #pragma unroll
                for (int j = 0; j < 4; j++) acc[i][j] += a[i] * b[j];
        }

        #pragma unroll
        for (int i = 0; i < 8; i++) {
            float* row = out + (size_t)(m0 + ty * 8 + i) * VSZ;
            #pragma unroll
            for (int j = 0; j < 4; j++) {
                int nn = n0 + tx * 4 + j;
                if (nn < VSZ) row[nn] = acc[i][j];
            }
        }
        T0++;
    }
#endif
}

// ==================== launch ====================
extern "C" void kernel_launch(void* const* d_in, const int* in_sizes, int n_in,
                              void* d_out, int out_size)
{
    const int*   ids    = (const int*)  d_in[0];
    const float* emb    = (const float*)d_in[1];
    const float* router = (const float*)d_in[2];
    const float* kexp   = (const float*)d_in[3];
    const float* vexp   = (const float*)d_in[4];
    const float* skv    = (const float*)d_in[5];
    const float* svv    = (const float*)d_in[6];
    const float* kvg    = (const float*)d_in[7];
    const float* Wq     = (const float*)d_in[8];
    const float* Wo     = (const float*)d_in[9];
    const float* Wm     = (const float*)d_in[10];
    const float* bm     = (const float*)d_in[11];
    const float* g1     = (const float*)d_in[12];
    const float* b1     = (const float*)d_in[13];
    const float* g2     = (const float*)d_in[14];
    const float* b2     = (const float*)d_in[15];
    const float* Wlm    = (const float*)d_in[16];

    float* out = (float*)d_out;
    float* gate_out = out + ((size_t)out_size - (size_t)TNUM * NE);

    cudaFuncSetAttribute(k4mma, cudaFuncAttributeMaxDynamicSharedMemorySize, K4_SMEM);
    cudaFuncSetAttribute(k2, cudaFuncAttributeMaxDynamicSharedMemorySize, K2_SMEM);

    k0<<<((VSZ*CH/4) + 511) / 512, 512>>>(Wlm);
    k1<<<TNUM/TB1, 256>>>(ids, emb, router, Wq, g1, b1, gate_out);
    k2<<<TNUM/TB, 256, K2_SMEM>>>(kexp, vexp, skv, svv, kvg);
    k3<<<TNUM/TB3, 256>>>(Wo, Wm, bm, g2, b2);
    k4mma<<<K4GRID, K4T, K4_SMEM>>>(Wlm, out);
}